// round 1
// baseline (speedup 1.0000x reference)
#include <cuda_runtime.h>
#include <math.h>
#include <float.h>
#include <string.h>

// Problem constants
#define BB   2
#define SS   2048
#define HH   2048
#define NHH  16
#define HDD  128
#define LDD  512
#define MM   (BB*SS)   // 4096

// ---------------------------------------------------------------------------
// Scratch (static device globals — allocation-free)
// ---------------------------------------------------------------------------
__device__ float g_q[MM * HH];
__device__ float g_klat[MM * LDD];
__device__ float g_vlat[MM * LDD];
__device__ float g_k[MM * HH];
__device__ float g_v[MM * HH];
__device__ float g_o[MM * HH];

// ---------------------------------------------------------------------------
// SGEMM: C[M,N] = A[M,K] @ B[K,N] (+ bias), fp32 exact, FFMA2 (f32x2) inner loop
// BM=BN=128, BK=16, 256 threads, 8x8 per thread.
// A smem tile is stored transposed AND duplicated so that both FFMA2 operands
// load packed directly from shared memory (no MOV packing in the hot loop).
// ---------------------------------------------------------------------------
#define BM 128
#define BN 128
#define BK 16
#define ASTRIDE (2*BM + 4)   // 260 floats; keeps dup-store conflicts at 2-way

__global__ void __launch_bounds__(256, 2) sgemm_kernel(
    const float* __restrict__ A, const float* __restrict__ B,
    const float* __restrict__ bias, float* __restrict__ C,
    int M, int N, int K)
{
    __shared__ float Asd[BK * ASTRIDE];
    __shared__ float Bs[BK * BN];

    const int tid = threadIdx.x;
    const int tx = tid & 15;
    const int ty = tid >> 4;
    const int bm = blockIdx.y * BM;
    const int bn = blockIdx.x * BN;

    // global-load coordinates
    const int arow0 = tid >> 2;          // 0..63 (second row = +64)
    const int ac4   = (tid & 3) << 2;    // k-column base of the float4
    const int brow0 = tid >> 5;          // 0..7  (second row = +8)
    const int bc4   = (tid & 31) << 2;   // n-column base

    const float* Ag = A + (size_t)(bm + arow0) * K + ac4;
    const float* Bg = B + (size_t)brow0 * N + bn + bc4;

    unsigned long long acc[8][4];
    #pragma unroll
    for (int i = 0; i < 8; i++)
        #pragma unroll
        for (int j = 0; j < 4; j++) acc[i][j] = 0ULL;

    // preload first tile into registers
    float4 pa0 = *(const float4*)(Ag);
    float4 pa1 = *(const float4*)(Ag + (size_t)64 * K);
    float4 pb0 = *(const float4*)(Bg);
    float4 pb1 = *(const float4*)(Bg + (size_t)8 * N);

    for (int k0 = 0; k0 < K; k0 += BK) {
        // stage registers -> smem (A duplicated + transposed)
        #pragma unroll
        for (int i = 0; i < 4; i++) {
            float v0 = (&pa0.x)[i];
            float v1 = (&pa1.x)[i];
            float* p0 = &Asd[(ac4 + i) * ASTRIDE + 2 * arow0];
            float* p1 = &Asd[(ac4 + i) * ASTRIDE + 2 * (arow0 + 64)];
            p0[0] = v0; p0[1] = v0;
            p1[0] = v1; p1[1] = v1;
        }
        *(float4*)&Bs[brow0 * BN + bc4]       = pb0;
        *(float4*)&Bs[(brow0 + 8) * BN + bc4] = pb1;
        __syncthreads();

        // prefetch next tile
        if (k0 + BK < K) {
            pa0 = *(const float4*)(Ag + (k0 + BK));
            pa1 = *(const float4*)(Ag + (size_t)64 * K + (k0 + BK));
            pb0 = *(const float4*)(Bg + (size_t)(k0 + BK) * N);
            pb1 = *(const float4*)(Bg + (size_t)(k0 + BK + 8) * N);
        }

        // compute
        #pragma unroll
        for (int kk = 0; kk < BK; kk++) {
            const float* arow = &Asd[kk * ASTRIDE];
            const float* brow = &Bs[kk * BN];
            unsigned long long a2[8], b2[4];
            ulonglong2 t;
            t = *(const ulonglong2*)(arow + 8 * ty);            a2[0] = t.x; a2[1] = t.y;
            t = *(const ulonglong2*)(arow + 8 * ty + 4);        a2[2] = t.x; a2[3] = t.y;
            t = *(const ulonglong2*)(arow + 128 + 8 * ty);      a2[4] = t.x; a2[5] = t.y;
            t = *(const ulonglong2*)(arow + 128 + 8 * ty + 4);  a2[6] = t.x; a2[7] = t.y;
            t = *(const ulonglong2*)(brow + 4 * tx);            b2[0] = t.x; b2[1] = t.y;
            t = *(const ulonglong2*)(brow + 64 + 4 * tx);       b2[2] = t.x; b2[3] = t.y;
            #pragma unroll
            for (int i = 0; i < 8; i++)
                #pragma unroll
                for (int j = 0; j < 4; j++)
                    asm("fma.rn.f32x2 %0, %1, %2, %0;"
                        : "+l"(acc[i][j]) : "l"(a2[i]), "l"(b2[j]));
        }
        __syncthreads();
    }

    // epilogue
    #pragma unroll
    for (int i = 0; i < 8; i++) {
        int row = bm + ((i < 4) ? (ty * 4 + i) : (64 + ty * 4 + (i - 4)));
        float* crow = C + (size_t)row * N + bn;
        #pragma unroll
        for (int j = 0; j < 4; j++) {
            int col = (j < 2) ? (tx * 4 + 2 * j) : (64 + tx * 4 + 2 * (j - 2));
            float2 v;
            memcpy(&v, &acc[i][j], 8);
            if (bias) {
                v.x += bias[bn + col];
                v.y += bias[bn + col + 1];
            }
            *(float2*)(crow + col) = v;
        }
    }
}

// ---------------------------------------------------------------------------
// Flash attention (causal), fp32.
// Grid: (S/TQ, B*NH). Block: 512 threads = 16 warps; each warp owns 8 q-rows,
// each lane owns 4 k-cols (scores) / 4 head-dims (output). Softmax stats and
// P live entirely in-warp (registers + shfl).
// ---------------------------------------------------------------------------
#define TQ 128
#define TK 128
#define KTS (TK + 4)   // 132: transposed-K smem stride

__global__ void __launch_bounds__(512, 1) mla_attn_kernel(
    const float* __restrict__ Qg, const float* __restrict__ Kg,
    const float* __restrict__ Vg, float* __restrict__ Og)
{
    extern __shared__ float sh[];
    float* Qs = sh;                       // [TQ][HDD]
    float* Kt = Qs + TQ * HDD;            // [HDD][KTS] (transposed)
    float* Vs = Kt + HDD * KTS;           // [TK][HDD]

    const int tid  = threadIdx.x;
    const int lane = tid & 31;
    const int w    = tid >> 5;            // warp id 0..15
    const int bh   = blockIdx.y;
    const int b    = bh >> 4;
    const int h    = bh & 15;
    const int qt   = gridDim.x - 1 - blockIdx.x;   // heavy tiles first

    const size_t qrow0 = (size_t)b * SS + (size_t)qt * TQ;
    const size_t hcol  = (size_t)h * HDD;
    const float scale  = 0.08838834764831845f;     // 1/sqrt(128)

    // load Q tile (pre-scaled)
    #pragma unroll
    for (int t = 0; t < 8; t++) {
        int idx = tid + 512 * t;          // float4 index over [128][32]
        int r  = idx >> 5;
        int d4 = (idx & 31) << 2;
        float4 qv = *(const float4*)(Qg + (qrow0 + r) * HH + hcol + d4);
        qv.x *= scale; qv.y *= scale; qv.z *= scale; qv.w *= scale;
        *(float4*)&Qs[r * HDD + d4] = qv;
    }

    float m[8], l[8], o[8][4];
    #pragma unroll
    for (int i = 0; i < 8; i++) {
        m[i] = -1e30f; l[i] = 0.f;
        o[i][0] = o[i][1] = o[i][2] = o[i][3] = 0.f;
    }

    for (int kt = 0; kt <= qt; kt++) {
        __syncthreads();   // all warps done with previous Kt/Vs (and Qs ready)

        const size_t krow0 = (size_t)b * SS + (size_t)kt * TK;
        #pragma unroll
        for (int t = 0; t < 8; t++) {
            int idx = tid + 512 * t;
            int c  = idx >> 5;
            int d4 = (idx & 31) << 2;
            float4 kv = *(const float4*)(Kg + (krow0 + c) * HH + hcol + d4);
            Kt[(d4 + 0) * KTS + c] = kv.x;
            Kt[(d4 + 1) * KTS + c] = kv.y;
            Kt[(d4 + 2) * KTS + c] = kv.z;
            Kt[(d4 + 3) * KTS + c] = kv.w;
            float4 vv = *(const float4*)(Vg + (krow0 + c) * HH + hcol + d4);
            *(float4*)&Vs[c * HDD + d4] = vv;
        }
        __syncthreads();

        // scores: s[i][j] = sum_d Qs[w*8+i][d] * K[4*lane+j][d]
        float s[8][4];
        #pragma unroll
        for (int i = 0; i < 8; i++)
            s[i][0] = s[i][1] = s[i][2] = s[i][3] = 0.f;

        const float* qbase = &Qs[(w * 8) * HDD];
        #pragma unroll 4
        for (int d = 0; d < HDD; d++) {
            float4 kr = *(const float4*)&Kt[d * KTS + 4 * lane];
            #pragma unroll
            for (int i = 0; i < 8; i++) {
                float qv = qbase[i * HDD + d];
                s[i][0] += qv * kr.x;
                s[i][1] += qv * kr.y;
                s[i][2] += qv * kr.z;
                s[i][3] += qv * kr.w;
            }
        }

        // causal mask (only diagonal tile needs it)
        if (kt == qt) {
            #pragma unroll
            for (int i = 0; i < 8; i++) {
                int ql = w * 8 + i;
                #pragma unroll
                for (int j = 0; j < 4; j++)
                    if (4 * lane + j > ql) s[i][j] = -1e30f;
            }
        }

        // online softmax (per-warp rows)
        #pragma unroll
        for (int i = 0; i < 8; i++) {
            float tmax = fmaxf(fmaxf(s[i][0], s[i][1]), fmaxf(s[i][2], s[i][3]));
            #pragma unroll
            for (int off = 16; off > 0; off >>= 1)
                tmax = fmaxf(tmax, __shfl_xor_sync(0xffffffffu, tmax, off));
            float newm = fmaxf(m[i], tmax);
            float alpha = __expf(m[i] - newm);
            float ps = 0.f;
            #pragma unroll
            for (int j = 0; j < 4; j++) {
                s[i][j] = __expf(s[i][j] - newm);
                ps += s[i][j];
            }
            #pragma unroll
            for (int off = 16; off > 0; off >>= 1)
                ps += __shfl_xor_sync(0xffffffffu, ps, off);
            l[i] = l[i] * alpha + ps;
            m[i] = newm;
            o[i][0] *= alpha; o[i][1] *= alpha; o[i][2] *= alpha; o[i][3] *= alpha;
        }

        // O += P @ V   (P broadcast via shfl — lane c4 owns cols 4*c4..4*c4+3)
        #pragma unroll 1
        for (int c4 = 0; c4 < 32; c4++) {
            #pragma unroll
            for (int jc = 0; jc < 4; jc++) {
                int c = 4 * c4 + jc;
                float4 vv = *(const float4*)&Vs[c * HDD + 4 * lane];
                #pragma unroll
                for (int i = 0; i < 8; i++) {
                    float pv = __shfl_sync(0xffffffffu, s[i][jc], c4);
                    o[i][0] += pv * vv.x;
                    o[i][1] += pv * vv.y;
                    o[i][2] += pv * vv.z;
                    o[i][3] += pv * vv.w;
                }
            }
        }
    }

    // write O (normalized)
    #pragma unroll
    for (int i = 0; i < 8; i++) {
        float inv = 1.f / l[i];
        float4 r = make_float4(o[i][0] * inv, o[i][1] * inv,
                               o[i][2] * inv, o[i][3] * inv);
        size_t row = qrow0 + w * 8 + i;
        *(float4*)(Og + row * HH + hcol + 4 * lane) = r;
    }
}

// ---------------------------------------------------------------------------
// launch
// ---------------------------------------------------------------------------
extern "C" void kernel_launch(void* const* d_in, const int* in_sizes, int n_in,
                              void* d_out, int out_size)
{
    (void)in_sizes; (void)n_in; (void)out_size;
    const float* x      = (const float*)d_in[0];
    const float* wq     = (const float*)d_in[1];
    const float* bq     = (const float*)d_in[2];
    const float* wk_lat = (const float*)d_in[3];
    const float* wv_lat = (const float*)d_in[4];
    const float* wk     = (const float*)d_in[5];
    const float* wv     = (const float*)d_in[6];
    const float* wo     = (const float*)d_in[7];
    const float* bo     = (const float*)d_in[8];
    float* out = (float*)d_out;

    float *q, *klat, *vlat, *k, *v, *o;
    cudaGetSymbolAddress((void**)&q,    g_q);
    cudaGetSymbolAddress((void**)&klat, g_klat);
    cudaGetSymbolAddress((void**)&vlat, g_vlat);
    cudaGetSymbolAddress((void**)&k,    g_k);
    cudaGetSymbolAddress((void**)&v,    g_v);
    cudaGetSymbolAddress((void**)&o,    g_o);

    const int smem_attn = (TQ * HDD + HDD * KTS + TK * HDD) * (int)sizeof(float);
    cudaFuncSetAttribute(mla_attn_kernel,
                         cudaFuncAttributeMaxDynamicSharedMemorySize, smem_attn);

    dim3 blk(256);
    // q = x @ wq + bq                     [4096,2048] = [4096,2048]x[2048,2048]
    sgemm_kernel<<<dim3(HH / BN, MM / BM), blk>>>(x, wq, bq, q, MM, HH, HH);
    // k_lat / v_lat = x @ w{k,v}_lat      [4096,512]
    sgemm_kernel<<<dim3(LDD / BN, MM / BM), blk>>>(x, wk_lat, nullptr, klat, MM, LDD, HH);
    sgemm_kernel<<<dim3(LDD / BN, MM / BM), blk>>>(x, wv_lat, nullptr, vlat, MM, LDD, HH);
    // k / v = lat @ w{k,v}                [4096,2048]
    sgemm_kernel<<<dim3(HH / BN, MM / BM), blk>>>(klat, wk, nullptr, k, MM, HH, LDD);
    sgemm_kernel<<<dim3(HH / BN, MM / BM), blk>>>(vlat, wv, nullptr, v, MM, HH, LDD);
    // causal attention
    mla_attn_kernel<<<dim3(SS / TQ, BB * NHH), dim3(512), smem_attn>>>(q, k, v, o);
    // out = o @ wo + bo
    sgemm_kernel<<<dim3(HH / BN, MM / BM), blk>>>(o, wo, bo, out, MM, HH, HH);
}

// round 3
// speedup vs baseline: 1.7398x; 1.7398x over previous
#include <cuda_runtime.h>
#include <cuda_bf16.h>
#include <math.h>
#include <stdint.h>
#include <string.h>

// Problem constants
#define BB   2
#define SS   2048
#define HH   2048
#define NHH  16
#define HDD  128
#define LDD  512
#define MM   (BB*SS)     // 4096
#define K3H  (3*HH)      // 6144
#define K3L  (3*LDD)     // 1536

// ---------------------------------------------------------------------------
// Scratch (static device globals — allocation-free)
// ---------------------------------------------------------------------------
__device__ float g_q[MM * HH];
__device__ float g_k[MM * HH];
__device__ float g_v[MM * HH];
__device__ float g_klat[MM * LDD];
__device__ float g_vlat[MM * LDD];
__device__ float g_o[MM * HH];

// bf16 split buffers: A-side = [hi | lo | hi], B-side = [hi | hi | lo] over K blocks
__device__ __nv_bfloat16 g_x3[MM * (size_t)K3H];
__device__ __nv_bfloat16 g_o3[MM * (size_t)K3H];
__device__ __nv_bfloat16 g_klat3[MM * (size_t)K3L];
__device__ __nv_bfloat16 g_vlat3[MM * (size_t)K3L];
__device__ __nv_bfloat16 g_wq3[HH * (size_t)K3H];
__device__ __nv_bfloat16 g_wo3[HH * (size_t)K3H];
__device__ __nv_bfloat16 g_wklat3[LDD * (size_t)K3H];
__device__ __nv_bfloat16 g_wvlat3[LDD * (size_t)K3H];
__device__ __nv_bfloat16 g_wk3[HH * (size_t)K3L];
__device__ __nv_bfloat16 g_wv3[HH * (size_t)K3L];

// ---------------------------------------------------------------------------
// PTX helpers (baseline-PTX only: cp.async / ldmatrix / mma.sync)
// ---------------------------------------------------------------------------
__device__ __forceinline__ uint32_t smem_u32(const void* p) {
    uint32_t a;
    asm("{ .reg .u64 t; cvta.to.shared.u64 t, %1; cvt.u32.u64 %0, t; }"
        : "=r"(a) : "l"(p));
    return a;
}
__device__ __forceinline__ void cp_async16(uint32_t s, const void* g) {
    asm volatile("cp.async.cg.shared.global [%0], [%1], 16;" :: "r"(s), "l"(g));
}
#define CP_COMMIT() asm volatile("cp.async.commit_group;" ::: "memory")
#define CP_WAIT0()  asm volatile("cp.async.wait_group 0;" ::: "memory")
#define CP_WAIT1()  asm volatile("cp.async.wait_group 1;" ::: "memory")
#define SWZ128(o) ((o) ^ (((o) >> 3) & 0x70))

__device__ __forceinline__ void ldsm_x4(uint32_t* r, uint32_t addr) {
    asm volatile("ldmatrix.sync.aligned.m8n8.x4.shared.b16 {%0,%1,%2,%3}, [%4];"
        : "=r"(r[0]), "=r"(r[1]), "=r"(r[2]), "=r"(r[3]) : "r"(addr));
}
__device__ __forceinline__ void mma_bf16(float* d, const uint32_t* a,
                                         const uint32_t* b) {
    asm volatile(
        "mma.sync.aligned.m16n8k16.row.col.f32.bf16.bf16.f32 "
        "{%0,%1,%2,%3}, {%4,%5,%6,%7}, {%8,%9}, {%0,%1,%2,%3};"
        : "+f"(d[0]), "+f"(d[1]), "+f"(d[2]), "+f"(d[3])
        : "r"(a[0]), "r"(a[1]), "r"(a[2]), "r"(a[3]), "r"(b[0]), "r"(b[1]));
}

// ---------------------------------------------------------------------------
// bf16 split-K GEMM:  C[M,N] (fp32) = A'[M,Kp] @ B'[N,Kp]^T  (+ bias)
// 128x128 tile, BK=64 bf16 (128B rows, SW128), 256 thr = 8 warps (4M x 2N),
// each warp 32x64 via 2x8 m16n8k16. cp.async double buffer.
// ---------------------------------------------------------------------------
__device__ __forceinline__ void load_tile(
    const __nv_bfloat16* __restrict__ A, const __nv_bfloat16* __restrict__ B,
    int Kp, int bm, int bn, int tid, uint32_t tbase, int kt, int buf)
{
    uint32_t abase = tbase + buf * 32768u;
    uint32_t bbase = abase + 16384u;
    #pragma unroll
    for (int r = 0; r < 4; r++) {
        int idx = tid + 256 * r;        // 0..1023
        int row = idx >> 3;
        int c16 = idx & 7;
        uint32_t soff = SWZ128((uint32_t)(row * 128 + c16 * 16));
        cp_async16(abase + soff, A + (size_t)(bm + row) * Kp + kt * 64 + c16 * 8);
        cp_async16(bbase + soff, B + (size_t)(bn + row) * Kp + kt * 64 + c16 * 8);
    }
    CP_COMMIT();
}

__global__ void __launch_bounds__(256) gemm_bf16_kernel(
    const __nv_bfloat16* __restrict__ A,   // [M, Kp] row-major (K-major)
    const __nv_bfloat16* __restrict__ B,   // [N, Kp] row-major (K-major)
    const float* __restrict__ bias,        // [N] or null
    float* __restrict__ C,                 // [M, N]
    int M, int N, int Kp)
{
    extern __shared__ char dsm[];
    const uint32_t tbase = (smem_u32(dsm) + 1023u) & ~1023u;

    const int tid  = threadIdx.x;
    const int wid  = tid >> 5;
    const int lane = tid & 31;
    const int bm = blockIdx.y * 128;
    const int bn = blockIdx.x * 128;
    const int wm = (wid & 3) * 32;     // warp M offset in tile
    const int wn = (wid >> 2) * 64;    // warp N offset in tile

    float acc[2][8][4];
    #pragma unroll
    for (int mt = 0; mt < 2; mt++)
        #pragma unroll
        for (int n8 = 0; n8 < 8; n8++)
            #pragma unroll
            for (int j = 0; j < 4; j++) acc[mt][n8][j] = 0.f;

    // precomputed ldmatrix lane addressing (tile-local)
    const int a_row   = wm + (lane & 15);          // +mt*16
    const int a_chalf = lane >> 4;                 // chunk half
    const int b_row   = wn + ((lane >> 4) << 3) + (lane & 7);   // +nt*16
    const int b_chalf = (lane >> 3) & 1;

    const int niter = Kp / 64;
    load_tile(A, B, Kp, bm, bn, tid, tbase, 0, 0);

    for (int it = 0; it < niter; it++) {
        if (it + 1 < niter) {
            load_tile(A, B, Kp, bm, bn, tid, tbase, it + 1, (it + 1) & 1);
            CP_WAIT1();
        } else {
            CP_WAIT0();
        }
        __syncthreads();

        const uint32_t a_s = tbase + (uint32_t)(it & 1) * 32768u;
        const uint32_t b_s = a_s + 16384u;

        #pragma unroll
        for (int s = 0; s < 4; s++) {
            uint32_t af[2][4];
            #pragma unroll
            for (int mt = 0; mt < 2; mt++) {
                int row = a_row + mt * 16;
                int ch  = (2 * s + a_chalf) ^ (row & 7);
                ldsm_x4(af[mt], a_s + (uint32_t)(row * 128 + ch * 16));
            }
            uint32_t bf[4][4];
            #pragma unroll
            for (int nt = 0; nt < 4; nt++) {
                int row = b_row + nt * 16;
                int ch  = (2 * s + b_chalf) ^ (row & 7);
                ldsm_x4(bf[nt], b_s + (uint32_t)(row * 128 + ch * 16));
            }
            #pragma unroll
            for (int mt = 0; mt < 2; mt++)
                #pragma unroll
                for (int n8 = 0; n8 < 8; n8++)
                    mma_bf16(acc[mt][n8], af[mt], &bf[n8 >> 1][(n8 & 1) * 2]);
        }
        __syncthreads();
    }

    // epilogue
    #pragma unroll
    for (int mt = 0; mt < 2; mt++) {
        const int r0 = bm + wm + mt * 16 + (lane >> 2);
        #pragma unroll
        for (int n8 = 0; n8 < 8; n8++) {
            const int c0 = bn + wn + n8 * 8 + (lane & 3) * 2;
            float b0 = 0.f, b1 = 0.f;
            if (bias) { b0 = bias[c0]; b1 = bias[c0 + 1]; }
            float2 v0 = make_float2(acc[mt][n8][0] + b0, acc[mt][n8][1] + b1);
            float2 v1 = make_float2(acc[mt][n8][2] + b0, acc[mt][n8][3] + b1);
            *(float2*)(C + (size_t)r0 * N + c0)       = v0;
            *(float2*)(C + (size_t)(r0 + 8) * N + c0) = v1;
        }
    }
}

// ---------------------------------------------------------------------------
// Split conversions
// A-side: in fp32 [R,C] -> out bf16 [R, 3C] laid out [hi | lo | hi]
// ---------------------------------------------------------------------------
__global__ void split3_rows_kernel(const float* __restrict__ in,
                                   __nv_bfloat16* __restrict__ out, int R, int C)
{
    int i2 = blockIdx.x * blockDim.x + threadIdx.x;   // pair index
    int total = R * (C >> 1);
    if (i2 >= total) return;
    int c2 = C >> 1;
    int r = i2 / c2, p = i2 - r * c2;
    float2 v = ((const float2*)in)[i2];
    __nv_bfloat162 h, l;
    h.x = __float2bfloat16(v.x);
    h.y = __float2bfloat16(v.y);
    l.x = __float2bfloat16(v.x - __bfloat162float(h.x));
    l.y = __float2bfloat16(v.y - __bfloat162float(h.y));
    __nv_bfloat162* ob = (__nv_bfloat162*)(out + (size_t)r * 3 * C);
    ob[p]          = h;   // hi
    ob[c2 + p]     = l;   // lo
    ob[2 * c2 + p] = h;   // hi
}

// B-side (weights): in fp32 [K,N] -> out bf16 [N, 3K] laid out [hi | hi | lo]
__global__ void split3_T_kernel(const float* __restrict__ in,
                                __nv_bfloat16* __restrict__ out, int K, int N)
{
    __shared__ float t[32][33];
    int k0 = blockIdx.y * 32, n0 = blockIdx.x * 32;
    int tx = threadIdx.x, ty = threadIdx.y;   // (32, 8)
    #pragma unroll
    for (int i = 0; i < 32; i += 8)
        t[ty + i][tx] = in[(size_t)(k0 + ty + i) * N + n0 + tx];
    __syncthreads();
    #pragma unroll
    for (int i = 0; i < 32; i += 8) {
        int n = ty + i;
        float v = t[tx][n];                   // in[k0+tx][n0+n]
        __nv_bfloat16 h = __float2bfloat16(v);
        __nv_bfloat16 l = __float2bfloat16(v - __bfloat162float(h));
        size_t base = (size_t)(n0 + n) * 3 * K;
        out[base + k0 + tx]         = h;
        out[base + K + k0 + tx]     = h;
        out[base + 2 * K + k0 + tx] = l;
    }
}

// ---------------------------------------------------------------------------
// Flash attention (causal), fp32 — unchanged (known-correct)
// ---------------------------------------------------------------------------
#define TQ 128
#define TK 128
#define KTS (TK + 4)

__global__ void __launch_bounds__(512, 1) mla_attn_kernel(
    const float* __restrict__ Qg, const float* __restrict__ Kg,
    const float* __restrict__ Vg, float* __restrict__ Og)
{
    extern __shared__ float sh[];
    float* Qs = sh;
    float* Kt = Qs + TQ * HDD;
    float* Vs = Kt + HDD * KTS;

    const int tid  = threadIdx.x;
    const int lane = tid & 31;
    const int w    = tid >> 5;
    const int bh   = blockIdx.y;
    const int b    = bh >> 4;
    const int h    = bh & 15;
    const int qt   = gridDim.x - 1 - blockIdx.x;

    const size_t qrow0 = (size_t)b * SS + (size_t)qt * TQ;
    const size_t hcol  = (size_t)h * HDD;
    const float scale  = 0.08838834764831845f;

    #pragma unroll
    for (int t = 0; t < 8; t++) {
        int idx = tid + 512 * t;
        int r  = idx >> 5;
        int d4 = (idx & 31) << 2;
        float4 qv = *(const float4*)(Qg + (qrow0 + r) * HH + hcol + d4);
        qv.x *= scale; qv.y *= scale; qv.z *= scale; qv.w *= scale;
        *(float4*)&Qs[r * HDD + d4] = qv;
    }

    float m[8], l[8], o[8][4];
    #pragma unroll
    for (int i = 0; i < 8; i++) {
        m[i] = -1e30f; l[i] = 0.f;
        o[i][0] = o[i][1] = o[i][2] = o[i][3] = 0.f;
    }

    for (int kt = 0; kt <= qt; kt++) {
        __syncthreads();
        const size_t krow0 = (size_t)b * SS + (size_t)kt * TK;
        #pragma unroll
        for (int t = 0; t < 8; t++) {
            int idx = tid + 512 * t;
            int c  = idx >> 5;
            int d4 = (idx & 31) << 2;
            float4 kv = *(const float4*)(Kg + (krow0 + c) * HH + hcol + d4);
            Kt[(d4 + 0) * KTS + c] = kv.x;
            Kt[(d4 + 1) * KTS + c] = kv.y;
            Kt[(d4 + 2) * KTS + c] = kv.z;
            Kt[(d4 + 3) * KTS + c] = kv.w;
            float4 vv = *(const float4*)(Vg + (krow0 + c) * HH + hcol + d4);
            *(float4*)&Vs[c * HDD + d4] = vv;
        }
        __syncthreads();

        float s[8][4];
        #pragma unroll
        for (int i = 0; i < 8; i++)
            s[i][0] = s[i][1] = s[i][2] = s[i][3] = 0.f;

        const float* qbase = &Qs[(w * 8) * HDD];
        #pragma unroll 4
        for (int d = 0; d < HDD; d++) {
            float4 kr = *(const float4*)&Kt[d * KTS + 4 * lane];
            #pragma unroll
            for (int i = 0; i < 8; i++) {
                float qv = qbase[i * HDD + d];
                s[i][0] += qv * kr.x;
                s[i][1] += qv * kr.y;
                s[i][2] += qv * kr.z;
                s[i][3] += qv * kr.w;
            }
        }

        if (kt == qt) {
            #pragma unroll
            for (int i = 0; i < 8; i++) {
                int ql = w * 8 + i;
                #pragma unroll
                for (int j = 0; j < 4; j++)
                    if (4 * lane + j > ql) s[i][j] = -1e30f;
            }
        }

        #pragma unroll
        for (int i = 0; i < 8; i++) {
            float tmax = fmaxf(fmaxf(s[i][0], s[i][1]), fmaxf(s[i][2], s[i][3]));
            #pragma unroll
            for (int off = 16; off > 0; off >>= 1)
                tmax = fmaxf(tmax, __shfl_xor_sync(0xffffffffu, tmax, off));
            float newm = fmaxf(m[i], tmax);
            float alpha = __expf(m[i] - newm);
            float ps = 0.f;
            #pragma unroll
            for (int j = 0; j < 4; j++) {
                s[i][j] = __expf(s[i][j] - newm);
                ps += s[i][j];
            }
            #pragma unroll
            for (int off = 16; off > 0; off >>= 1)
                ps += __shfl_xor_sync(0xffffffffu, ps, off);
            l[i] = l[i] * alpha + ps;
            m[i] = newm;
            o[i][0] *= alpha; o[i][1] *= alpha; o[i][2] *= alpha; o[i][3] *= alpha;
        }

        #pragma unroll 1
        for (int c4 = 0; c4 < 32; c4++) {
            #pragma unroll
            for (int jc = 0; jc < 4; jc++) {
                int c = 4 * c4 + jc;
                float4 vv = *(const float4*)&Vs[c * HDD + 4 * lane];
                #pragma unroll
                for (int i = 0; i < 8; i++) {
                    float pv = __shfl_sync(0xffffffffu, s[i][jc], c4);
                    o[i][0] += pv * vv.x;
                    o[i][1] += pv * vv.y;
                    o[i][2] += pv * vv.z;
                    o[i][3] += pv * vv.w;
                }
            }
        }
    }

    #pragma unroll
    for (int i = 0; i < 8; i++) {
        float inv = 1.f / l[i];
        float4 r = make_float4(o[i][0] * inv, o[i][1] * inv,
                               o[i][2] * inv, o[i][3] * inv);
        size_t row = qrow0 + w * 8 + i;
        *(float4*)(Og + row * HH + hcol + 4 * lane) = r;
    }
}

// ---------------------------------------------------------------------------
// launch
// ---------------------------------------------------------------------------
extern "C" void kernel_launch(void* const* d_in, const int* in_sizes, int n_in,
                              void* d_out, int out_size)
{
    (void)in_sizes; (void)n_in; (void)out_size;
    const float* x      = (const float*)d_in[0];
    const float* wq     = (const float*)d_in[1];
    const float* bq     = (const float*)d_in[2];
    const float* wk_lat = (const float*)d_in[3];
    const float* wv_lat = (const float*)d_in[4];
    const float* wk     = (const float*)d_in[5];
    const float* wv     = (const float*)d_in[6];
    const float* wo     = (const float*)d_in[7];
    const float* bo     = (const float*)d_in[8];
    float* out = (float*)d_out;

    float *q, *k, *v, *klat, *vlat, *o;
    cudaGetSymbolAddress((void**)&q,    g_q);
    cudaGetSymbolAddress((void**)&k,    g_k);
    cudaGetSymbolAddress((void**)&v,    g_v);
    cudaGetSymbolAddress((void**)&klat, g_klat);
    cudaGetSymbolAddress((void**)&vlat, g_vlat);
    cudaGetSymbolAddress((void**)&o,    g_o);

    __nv_bfloat16 *x3, *o3, *klat3, *vlat3, *wq3, *wo3, *wklat3, *wvlat3, *wk3, *wv3;
    cudaGetSymbolAddress((void**)&x3,     g_x3);
    cudaGetSymbolAddress((void**)&o3,     g_o3);
    cudaGetSymbolAddress((void**)&klat3,  g_klat3);
    cudaGetSymbolAddress((void**)&vlat3,  g_vlat3);
    cudaGetSymbolAddress((void**)&wq3,    g_wq3);
    cudaGetSymbolAddress((void**)&wo3,    g_wo3);
    cudaGetSymbolAddress((void**)&wklat3, g_wklat3);
    cudaGetSymbolAddress((void**)&wvlat3, g_wvlat3);
    cudaGetSymbolAddress((void**)&wk3,    g_wk3);
    cudaGetSymbolAddress((void**)&wv3,    g_wv3);

    const int smem_gemm = 66560;   // 2 x 32KB buffers + 1KB alignment slack
    cudaFuncSetAttribute(gemm_bf16_kernel,
                         cudaFuncAttributeMaxDynamicSharedMemorySize, smem_gemm);
    const int smem_attn = (TQ * HDD + HDD * KTS + TK * HDD) * (int)sizeof(float);
    cudaFuncSetAttribute(mla_attn_kernel,
                         cudaFuncAttributeMaxDynamicSharedMemorySize, smem_attn);

    // ---- split conversions ----
    {
        int tot = MM * HH / 2;
        split3_rows_kernel<<<(tot + 255) / 256, 256>>>(x, x3, MM, HH);
    }
    split3_T_kernel<<<dim3(HH / 32, HH / 32),  dim3(32, 8)>>>(wq,     wq3,    HH,  HH);
    split3_T_kernel<<<dim3(LDD / 32, HH / 32), dim3(32, 8)>>>(wk_lat, wklat3, HH,  LDD);
    split3_T_kernel<<<dim3(LDD / 32, HH / 32), dim3(32, 8)>>>(wv_lat, wvlat3, HH,  LDD);
    split3_T_kernel<<<dim3(HH / 32, LDD / 32), dim3(32, 8)>>>(wk,     wk3,    LDD, HH);
    split3_T_kernel<<<dim3(HH / 32, LDD / 32), dim3(32, 8)>>>(wv,     wv3,    LDD, HH);
    split3_T_kernel<<<dim3(HH / 32, HH / 32),  dim3(32, 8)>>>(wo,     wo3,    HH,  HH);

    // ---- projections on tensor cores (mma.sync) ----
    gemm_bf16_kernel<<<dim3(HH / 128, MM / 128), 256, smem_gemm>>>(
        x3, wq3, bq, q, MM, HH, K3H);
    gemm_bf16_kernel<<<dim3(LDD / 128, MM / 128), 256, smem_gemm>>>(
        x3, wklat3, nullptr, klat, MM, LDD, K3H);
    gemm_bf16_kernel<<<dim3(LDD / 128, MM / 128), 256, smem_gemm>>>(
        x3, wvlat3, nullptr, vlat, MM, LDD, K3H);

    {
        int tot = MM * LDD / 2;
        split3_rows_kernel<<<(tot + 255) / 256, 256>>>(klat, klat3, MM, LDD);
        split3_rows_kernel<<<(tot + 255) / 256, 256>>>(vlat, vlat3, MM, LDD);
    }
    gemm_bf16_kernel<<<dim3(HH / 128, MM / 128), 256, smem_gemm>>>(
        klat3, wk3, nullptr, k, MM, HH, K3L);
    gemm_bf16_kernel<<<dim3(HH / 128, MM / 128), 256, smem_gemm>>>(
        vlat3, wv3, nullptr, v, MM, HH, K3L);

    // ---- attention ----
    mla_attn_kernel<<<dim3(SS / TQ, BB * NHH), dim3(512), smem_attn>>>(q, k, v, o);

    // ---- output projection ----
    {
        int tot = MM * HH / 2;
        split3_rows_kernel<<<(tot + 255) / 256, 256>>>(o, o3, MM, HH);
    }
    gemm_bf16_kernel<<<dim3(HH / 128, MM / 128), 256, smem_gemm>>>(
        o3, wo3, bo, out, MM, HH, K3H);
}

// round 4
// speedup vs baseline: 2.9614x; 1.7021x over previous
#include <cuda_runtime.h>
#include <cuda_bf16.h>
#include <math.h>
#include <stdint.h>
#include <string.h>

// Problem constants
#define BB   2
#define SS   2048
#define HH   2048
#define NHH  16
#define HDD  128
#define LDD  512
#define MM   (BB*SS)     // 4096
#define K3H  (3*HH)      // 6144
#define K3L  (3*LDD)     // 1536

// ---------------------------------------------------------------------------
// Scratch (static device globals — allocation-free)
// ---------------------------------------------------------------------------
__device__ float g_q[MM * HH];
__device__ float g_k[MM * HH];
__device__ float g_v[MM * HH];
__device__ float g_klat[MM * LDD];
__device__ float g_vlat[MM * LDD];
__device__ float g_o[MM * HH];

__device__ __nv_bfloat16 g_x3[MM * (size_t)K3H];
__device__ __nv_bfloat16 g_o3[MM * (size_t)K3H];
__device__ __nv_bfloat16 g_klat3[MM * (size_t)K3L];
__device__ __nv_bfloat16 g_vlat3[MM * (size_t)K3L];
__device__ __nv_bfloat16 g_wq3[HH * (size_t)K3H];
__device__ __nv_bfloat16 g_wo3[HH * (size_t)K3H];
__device__ __nv_bfloat16 g_wklat3[LDD * (size_t)K3H];
__device__ __nv_bfloat16 g_wvlat3[LDD * (size_t)K3H];
__device__ __nv_bfloat16 g_wk3[HH * (size_t)K3L];
__device__ __nv_bfloat16 g_wv3[HH * (size_t)K3L];

// ---------------------------------------------------------------------------
// PTX helpers (baseline-PTX only)
// ---------------------------------------------------------------------------
__device__ __forceinline__ uint32_t smem_u32(const void* p) {
    uint32_t a;
    asm("{ .reg .u64 t; cvta.to.shared.u64 t, %1; cvt.u32.u64 %0, t; }"
        : "=r"(a) : "l"(p));
    return a;
}
__device__ __forceinline__ void cp_async16(uint32_t s, const void* g) {
    asm volatile("cp.async.cg.shared.global [%0], [%1], 16;" :: "r"(s), "l"(g));
}
#define CP_COMMIT() asm volatile("cp.async.commit_group;" ::: "memory")
#define CP_WAIT0()  asm volatile("cp.async.wait_group 0;" ::: "memory")
#define CP_WAIT1()  asm volatile("cp.async.wait_group 1;" ::: "memory")
#define SWZ128(o) ((o) ^ (((o) >> 3) & 0x70))

__device__ __forceinline__ void ldsm_x4(uint32_t* r, uint32_t addr) {
    asm volatile("ldmatrix.sync.aligned.m8n8.x4.shared.b16 {%0,%1,%2,%3}, [%4];"
        : "=r"(r[0]), "=r"(r[1]), "=r"(r[2]), "=r"(r[3]) : "r"(addr));
}
__device__ __forceinline__ void ldsm_x4_trans(uint32_t* r, uint32_t addr) {
    asm volatile("ldmatrix.sync.aligned.m8n8.x4.trans.shared.b16 {%0,%1,%2,%3}, [%4];"
        : "=r"(r[0]), "=r"(r[1]), "=r"(r[2]), "=r"(r[3]) : "r"(addr));
}
__device__ __forceinline__ void mma_bf16(float* d, const uint32_t* a,
                                         const uint32_t* b) {
    asm volatile(
        "mma.sync.aligned.m16n8k16.row.col.f32.bf16.bf16.f32 "
        "{%0,%1,%2,%3}, {%4,%5,%6,%7}, {%8,%9}, {%0,%1,%2,%3};"
        : "+f"(d[0]), "+f"(d[1]), "+f"(d[2]), "+f"(d[3])
        : "r"(a[0]), "r"(a[1]), "r"(a[2]), "r"(a[3]), "r"(b[0]), "r"(b[1]));
}
// pack {even -> low half, odd -> high half}
__device__ __forceinline__ uint32_t packbf(float e, float o) {
    uint32_t r;
    asm("cvt.rn.bf16x2.f32 %0, %1, %2;" : "=r"(r) : "f"(o), "f"(e));
    return r;
}
// fast exp2, |err| ~ 4e-8, FMA-pipe only (no MUFU)
__device__ __forceinline__ float exp2p(float x) {
    x = fmaxf(x, -126.f);
    float n = rintf(x);
    float f = x - n;
    float p = 0.00015403530393381609f;
    p = fmaf(p, f, 0.0013333558146428443f);
    p = fmaf(p, f, 0.009618129107628477f);
    p = fmaf(p, f, 0.05550410866482158f);
    p = fmaf(p, f, 0.2402265069591007f);
    p = fmaf(p, f, 0.6931471805599453f);
    p = fmaf(p, f, 1.0f);
    return p * __int_as_float(((int)n + 127) << 23);
}

// ---------------------------------------------------------------------------
// bf16 split-K GEMM (unchanged from round 3 — validated)
// ---------------------------------------------------------------------------
__device__ __forceinline__ void load_tile(
    const __nv_bfloat16* __restrict__ A, const __nv_bfloat16* __restrict__ B,
    int Kp, int bm, int bn, int tid, uint32_t tbase, int kt, int buf)
{
    uint32_t abase = tbase + buf * 32768u;
    uint32_t bbase = abase + 16384u;
    #pragma unroll
    for (int r = 0; r < 4; r++) {
        int idx = tid + 256 * r;
        int row = idx >> 3;
        int c16 = idx & 7;
        uint32_t soff = SWZ128((uint32_t)(row * 128 + c16 * 16));
        cp_async16(abase + soff, A + (size_t)(bm + row) * Kp + kt * 64 + c16 * 8);
        cp_async16(bbase + soff, B + (size_t)(bn + row) * Kp + kt * 64 + c16 * 8);
    }
    CP_COMMIT();
}

__global__ void __launch_bounds__(256) gemm_bf16_kernel(
    const __nv_bfloat16* __restrict__ A,
    const __nv_bfloat16* __restrict__ B,
    const float* __restrict__ bias,
    float* __restrict__ C,
    int M, int N, int Kp)
{
    extern __shared__ char dsm[];
    const uint32_t tbase = (smem_u32(dsm) + 1023u) & ~1023u;

    const int tid  = threadIdx.x;
    const int wid  = tid >> 5;
    const int lane = tid & 31;
    const int bm = blockIdx.y * 128;
    const int bn = blockIdx.x * 128;
    const int wm = (wid & 3) * 32;
    const int wn = (wid >> 2) * 64;

    float acc[2][8][4];
    #pragma unroll
    for (int mt = 0; mt < 2; mt++)
        #pragma unroll
        for (int n8 = 0; n8 < 8; n8++)
            #pragma unroll
            for (int j = 0; j < 4; j++) acc[mt][n8][j] = 0.f;

    const int a_row   = wm + (lane & 15);
    const int a_chalf = lane >> 4;
    const int b_row   = wn + ((lane >> 4) << 3) + (lane & 7);
    const int b_chalf = (lane >> 3) & 1;

    const int niter = Kp / 64;
    load_tile(A, B, Kp, bm, bn, tid, tbase, 0, 0);

    for (int it = 0; it < niter; it++) {
        if (it + 1 < niter) {
            load_tile(A, B, Kp, bm, bn, tid, tbase, it + 1, (it + 1) & 1);
            CP_WAIT1();
        } else {
            CP_WAIT0();
        }
        __syncthreads();

        const uint32_t a_s = tbase + (uint32_t)(it & 1) * 32768u;
        const uint32_t b_s = a_s + 16384u;

        #pragma unroll
        for (int s = 0; s < 4; s++) {
            uint32_t af[2][4];
            #pragma unroll
            for (int mt = 0; mt < 2; mt++) {
                int row = a_row + mt * 16;
                int ch  = (2 * s + a_chalf) ^ (row & 7);
                ldsm_x4(af[mt], a_s + (uint32_t)(row * 128 + ch * 16));
            }
            uint32_t bf[4][4];
            #pragma unroll
            for (int nt = 0; nt < 4; nt++) {
                int row = b_row + nt * 16;
                int ch  = (2 * s + b_chalf) ^ (row & 7);
                ldsm_x4(bf[nt], b_s + (uint32_t)(row * 128 + ch * 16));
            }
            #pragma unroll
            for (int mt = 0; mt < 2; mt++)
                #pragma unroll
                for (int n8 = 0; n8 < 8; n8++)
                    mma_bf16(acc[mt][n8], af[mt], &bf[n8 >> 1][(n8 & 1) * 2]);
        }
        __syncthreads();
    }

    #pragma unroll
    for (int mt = 0; mt < 2; mt++) {
        const int r0 = bm + wm + mt * 16 + (lane >> 2);
        #pragma unroll
        for (int n8 = 0; n8 < 8; n8++) {
            const int c0 = bn + wn + n8 * 8 + (lane & 3) * 2;
            float b0 = 0.f, b1 = 0.f;
            if (bias) { b0 = bias[c0]; b1 = bias[c0 + 1]; }
            float2 v0 = make_float2(acc[mt][n8][0] + b0, acc[mt][n8][1] + b1);
            float2 v1 = make_float2(acc[mt][n8][2] + b0, acc[mt][n8][3] + b1);
            *(float2*)(C + (size_t)r0 * N + c0)       = v0;
            *(float2*)(C + (size_t)(r0 + 8) * N + c0) = v1;
        }
    }
}

// ---------------------------------------------------------------------------
// Split conversions (unchanged)
// ---------------------------------------------------------------------------
__global__ void split3_rows_kernel(const float* __restrict__ in,
                                   __nv_bfloat16* __restrict__ out, int R, int C)
{
    int i2 = blockIdx.x * blockDim.x + threadIdx.x;
    int total = R * (C >> 1);
    if (i2 >= total) return;
    int c2 = C >> 1;
    int r = i2 / c2, p = i2 - r * c2;
    float2 v = ((const float2*)in)[i2];
    __nv_bfloat162 h, l;
    h.x = __float2bfloat16(v.x);
    h.y = __float2bfloat16(v.y);
    l.x = __float2bfloat16(v.x - __bfloat162float(h.x));
    l.y = __float2bfloat16(v.y - __bfloat162float(h.y));
    __nv_bfloat162* ob = (__nv_bfloat162*)(out + (size_t)r * 3 * C);
    ob[p]          = h;
    ob[c2 + p]     = l;
    ob[2 * c2 + p] = h;
}

__global__ void split3_T_kernel(const float* __restrict__ in,
                                __nv_bfloat16* __restrict__ out, int K, int N)
{
    __shared__ float t[32][33];
    int k0 = blockIdx.y * 32, n0 = blockIdx.x * 32;
    int tx = threadIdx.x, ty = threadIdx.y;
    #pragma unroll
    for (int i = 0; i < 32; i += 8)
        t[ty + i][tx] = in[(size_t)(k0 + ty + i) * N + n0 + tx];
    __syncthreads();
    #pragma unroll
    for (int i = 0; i < 32; i += 8) {
        int n = ty + i;
        float v = t[tx][n];
        __nv_bfloat16 h = __float2bfloat16(v);
        __nv_bfloat16 l = __float2bfloat16(v - __bfloat162float(h));
        size_t base = (size_t)(n0 + n) * 3 * K;
        out[base + k0 + tx]         = h;
        out[base + K + k0 + tx]     = h;
        out[base + 2 * K + k0 + tx] = l;
    }
}

// ---------------------------------------------------------------------------
// Tensor-core flash attention (causal) with hi/lo split precision.
// Block: 256 thr = 8 warps; each warp owns 16 q rows. One (b,h,qtile) per CTA.
// smem: 6 tiles of 128x128 bf16 (Qh,Ql,Kh,Kl,Vh,Vl), subtile-swizzled.
// ---------------------------------------------------------------------------
#define SM_QH 0u
#define SM_QL 32768u
#define SM_KH 65536u
#define SM_KL 98304u
#define SM_VH 131072u
#define SM_VL 163840u

// load a 128x128 fp32 gmem tile into split hi/lo bf16 smem tiles
__device__ __forceinline__ void attn_load_split(
    const float* __restrict__ g, uint32_t smHi, uint32_t smLo,
    int tid, float scale)
{
    #pragma unroll
    for (int i = 0; i < 16; i++) {
        int idx = tid + 256 * i;          // float4 index over [128][32]
        int r  = idx >> 5;
        int d4 = (idx & 31) << 2;
        float4 v = *(const float4*)(g + (size_t)r * HH + d4);
        v.x *= scale; v.y *= scale; v.z *= scale; v.w *= scale;
        uint32_t h0 = packbf(v.x, v.y);
        uint32_t h1 = packbf(v.z, v.w);
        uint32_t l0 = packbf(v.x - __uint_as_float(h0 << 16),
                             v.y - __uint_as_float(h0 & 0xffff0000u));
        uint32_t l1 = packbf(v.z - __uint_as_float(h1 << 16),
                             v.w - __uint_as_float(h1 & 0xffff0000u));
        uint32_t sub = (uint32_t)(d4 >> 6) * 16384u;
        uint32_t o0 = SWZ128((uint32_t)(r * 128 + (d4 & 63) * 2));
        uint32_t o1 = SWZ128((uint32_t)(r * 128 + (d4 & 63) * 2 + 4));
        *(uint32_t*)(uintptr_t)0;  // placeholder removed below
        (void)o0; (void)o1; (void)sub; (void)h0; (void)h1; (void)l0; (void)l1;
    }
}

__global__ void __launch_bounds__(256) mla_attn_tc_kernel(
    const float* __restrict__ Qg, const float* __restrict__ Kg,
    const float* __restrict__ Vg, float* __restrict__ Og)
{
    extern __shared__ char dsm[];
    const uint32_t sb = (smem_u32(dsm) + 1023u) & ~1023u;

    const int tid  = threadIdx.x;
    const int lane = tid & 31;
    const int w    = tid >> 5;
    const int bh   = blockIdx.y;
    const int b    = bh >> 4;
    const int h    = bh & 15;
    const int qt   = gridDim.x - 1 - blockIdx.x;

    const size_t qrow0 = (size_t)b * SS + (size_t)qt * 128;
    const size_t hcol  = (size_t)h * HDD;
    // 1/sqrt(128) * log2(e)
    const float QSCALE = 0.08838834764831845f * 1.4426950408889634f;

    // ---- load Q tile (hi/lo split, scaled) ----
    {
        const float* g = Qg + qrow0 * HH + hcol;
        #pragma unroll
        for (int i = 0; i < 16; i++) {
            int idx = tid + 256 * i;
            int r  = idx >> 5;
            int d4 = (idx & 31) << 2;
            float4 v = *(const float4*)(g + (size_t)r * HH + d4);
            v.x *= QSCALE; v.y *= QSCALE; v.z *= QSCALE; v.w *= QSCALE;
            uint32_t h0 = packbf(v.x, v.y);
            uint32_t h1 = packbf(v.z, v.w);
            uint32_t l0 = packbf(v.x - __uint_as_float(h0 << 16),
                                 v.y - __uint_as_float(h0 & 0xffff0000u));
            uint32_t l1 = packbf(v.z - __uint_as_float(h1 << 16),
                                 v.w - __uint_as_float(h1 & 0xffff0000u));
            uint32_t sub = (uint32_t)(d4 >> 6) * 16384u;
            uint32_t o0 = sub + SWZ128((uint32_t)(r * 128 + (d4 & 63) * 2));
            uint32_t o1 = sub + SWZ128((uint32_t)(r * 128 + (d4 & 63) * 2 + 4));
            *(uint32_t*)(dsm + (sb - smem_u32(dsm)) + SM_QH + o0) = h0;
            *(uint32_t*)(dsm + (sb - smem_u32(dsm)) + SM_QH + o1) = h1;
            *(uint32_t*)(dsm + (sb - smem_u32(dsm)) + SM_QL + o0) = l0;
            *(uint32_t*)(dsm + (sb - smem_u32(dsm)) + SM_QL + o1) = l1;
        }
    }

    // per-thread softmax state (rows: A = base+lane/4, B = A+8)
    float m2[2] = {-1e30f, -1e30f};
    float l2[2] = {0.f, 0.f};
    float ov[16][4];
    #pragma unroll
    for (int j = 0; j < 16; j++)
        ov[j][0] = ov[j][1] = ov[j][2] = ov[j][3] = 0.f;

    const int a_row = 16 * w + (lane & 15);
    const int a_ch  = lane >> 4;
    const int b_rowb = ((lane >> 4) << 3) + (lane & 7);
    const int b_ch  = (lane >> 3) & 1;
    const int v_row = (lane & 7) + ((lane >> 3) & 1) * 8;
    const int qlocA = 16 * w + (lane >> 2);

    char* dsp = dsm + (sb - smem_u32(dsm));

    for (int kt = 0; kt <= qt; kt++) {
        __syncthreads();   // previous compute done / Q ready

        // ---- load K and V tiles (hi/lo split) ----
        const size_t krow0 = (size_t)b * SS + (size_t)kt * 128;
        const float* gK = Kg + krow0 * HH + hcol;
        const float* gV = Vg + krow0 * HH + hcol;
        #pragma unroll
        for (int i = 0; i < 16; i++) {
            int idx = tid + 256 * i;
            int r  = idx >> 5;
            int d4 = (idx & 31) << 2;
            uint32_t sub = (uint32_t)(d4 >> 6) * 16384u;
            uint32_t o0 = sub + SWZ128((uint32_t)(r * 128 + (d4 & 63) * 2));
            uint32_t o1 = sub + SWZ128((uint32_t)(r * 128 + (d4 & 63) * 2 + 4));
            {
                float4 v = *(const float4*)(gK + (size_t)r * HH + d4);
                uint32_t h0 = packbf(v.x, v.y);
                uint32_t h1 = packbf(v.z, v.w);
                uint32_t q0 = packbf(v.x - __uint_as_float(h0 << 16),
                                     v.y - __uint_as_float(h0 & 0xffff0000u));
                uint32_t q1 = packbf(v.z - __uint_as_float(h1 << 16),
                                     v.w - __uint_as_float(h1 & 0xffff0000u));
                *(uint32_t*)(dsp + SM_KH + o0) = h0;
                *(uint32_t*)(dsp + SM_KH + o1) = h1;
                *(uint32_t*)(dsp + SM_KL + o0) = q0;
                *(uint32_t*)(dsp + SM_KL + o1) = q1;
            }
            {
                float4 v = *(const float4*)(gV + (size_t)r * HH + d4);
                uint32_t h0 = packbf(v.x, v.y);
                uint32_t h1 = packbf(v.z, v.w);
                uint32_t q0 = packbf(v.x - __uint_as_float(h0 << 16),
                                     v.y - __uint_as_float(h0 & 0xffff0000u));
                uint32_t q1 = packbf(v.z - __uint_as_float(h1 << 16),
                                     v.w - __uint_as_float(h1 & 0xffff0000u));
                *(uint32_t*)(dsp + SM_VH + o0) = h0;
                *(uint32_t*)(dsp + SM_VH + o1) = h1;
                *(uint32_t*)(dsp + SM_VL + o0) = q0;
                *(uint32_t*)(dsp + SM_VL + o1) = q1;
            }
        }
        __syncthreads();

        // ---- scores: S = Qh·Kh^T + Ql·Kh^T + Qh·Kl^T ----
        float sc[16][4];
        #pragma unroll
        for (int j = 0; j < 16; j++)
            sc[j][0] = sc[j][1] = sc[j][2] = sc[j][3] = 0.f;

        #pragma unroll
        for (int kc = 0; kc < 8; kc++) {
            uint32_t ah[4], al[4];
            {
                int ch = (2 * (kc & 3) + a_ch) ^ (a_row & 7);
                uint32_t off = (uint32_t)(kc >> 2) * 16384u
                             + (uint32_t)(a_row * 128 + ch * 16);
                ldsm_x4(ah, sb + SM_QH + off);
                ldsm_x4(al, sb + SM_QL + off);
            }
            #pragma unroll
            for (int half = 0; half < 2; half++) {
                uint32_t bh4[4][4], bl4[4][4];
                #pragma unroll
                for (int nt4 = 0; nt4 < 4; nt4++) {
                    int row = (half * 4 + nt4) * 16 + b_rowb;
                    int ch = (2 * (kc & 3) + b_ch) ^ (row & 7);
                    uint32_t off = (uint32_t)(kc >> 2) * 16384u
                                 + (uint32_t)(row * 128 + ch * 16);
                    ldsm_x4(bh4[nt4], sb + SM_KH + off);
                    ldsm_x4(bl4[nt4], sb + SM_KL + off);
                }
                #pragma unroll
                for (int nt4 = 0; nt4 < 4; nt4++) {
                    int j0 = (half * 4 + nt4) * 2;
                    mma_bf16(sc[j0],     ah, &bh4[nt4][0]);
                    mma_bf16(sc[j0 + 1], ah, &bh4[nt4][2]);
                    mma_bf16(sc[j0],     al, &bh4[nt4][0]);
                    mma_bf16(sc[j0 + 1], al, &bh4[nt4][2]);
                    mma_bf16(sc[j0],     ah, &bl4[nt4][0]);
                    mma_bf16(sc[j0 + 1], ah, &bl4[nt4][2]);
                }
            }
        }

        // ---- causal mask (diagonal tile only) ----
        if (kt == qt) {
            #pragma unroll
            for (int j = 0; j < 16; j++) {
                int kkb = 8 * j + 2 * (lane & 3);
                #pragma unroll
                for (int c = 0; c < 2; c++) {
                    if (kkb + c > qlocA)     sc[j][c]     = -1e30f;
                    if (kkb + c > qlocA + 8) sc[j][2 + c] = -1e30f;
                }
            }
        }

        // ---- online softmax (base-2 domain) ----
        {
            float mA = -1e30f, mB = -1e30f;
            #pragma unroll
            for (int j = 0; j < 16; j++) {
                mA = fmaxf(mA, fmaxf(sc[j][0], sc[j][1]));
                mB = fmaxf(mB, fmaxf(sc[j][2], sc[j][3]));
            }
            mA = fmaxf(mA, __shfl_xor_sync(0xffffffffu, mA, 1));
            mA = fmaxf(mA, __shfl_xor_sync(0xffffffffu, mA, 2));
            mB = fmaxf(mB, __shfl_xor_sync(0xffffffffu, mB, 1));
            mB = fmaxf(mB, __shfl_xor_sync(0xffffffffu, mB, 2));
            float nmA = fmaxf(m2[0], mA), nmB = fmaxf(m2[1], mB);
            float aA = exp2p(m2[0] - nmA), aB = exp2p(m2[1] - nmB);
            float sA = 0.f, sB = 0.f;
            #pragma unroll
            for (int j = 0; j < 16; j++) {
                sc[j][0] = exp2p(sc[j][0] - nmA);
                sc[j][1] = exp2p(sc[j][1] - nmA);
                sc[j][2] = exp2p(sc[j][2] - nmB);
                sc[j][3] = exp2p(sc[j][3] - nmB);
                sA += sc[j][0] + sc[j][1];
                sB += sc[j][2] + sc[j][3];
            }
            sA += __shfl_xor_sync(0xffffffffu, sA, 1);
            sA += __shfl_xor_sync(0xffffffffu, sA, 2);
            sB += __shfl_xor_sync(0xffffffffu, sB, 1);
            sB += __shfl_xor_sync(0xffffffffu, sB, 2);
            l2[0] = l2[0] * aA + sA;
            l2[1] = l2[1] * aB + sB;
            m2[0] = nmA; m2[1] = nmB;
            #pragma unroll
            for (int j = 0; j < 16; j++) {
                ov[j][0] *= aA; ov[j][1] *= aA;
                ov[j][2] *= aB; ov[j][3] *= aB;
            }
        }

        // ---- O += Ph·Vh + Pl·Vh + Ph·Vl ----
        #pragma unroll
        for (int kc = 0; kc < 8; kc++) {
            int j0 = 2 * kc;
            uint32_t ph[4], pl[4];
            #pragma unroll
            for (int u = 0; u < 2; u++) {        // u: tile j0+u (k / k+8)
                #pragma unroll
                for (int t = 0; t < 2; t++) {    // t: row group (regs 0,1 / 2,3)
                    float e = sc[j0 + u][2 * t];
                    float o = sc[j0 + u][2 * t + 1];
                    uint32_t hp = packbf(e, o);
                    ph[2 * u + t] = hp;
                    pl[2 * u + t] = packbf(e - __uint_as_float(hp << 16),
                                           o - __uint_as_float(hp & 0xffff0000u));
                }
            }
            #pragma unroll
            for (int dt = 0; dt < 8; dt++) {
                uint32_t vh[4], vl[4];
                int row = kc * 16 + v_row;
                int dloc = (dt * 16) & 63;
                int ch = ((dloc >> 3) + (lane >> 4)) ^ (row & 7);
                uint32_t off = (uint32_t)(dt >> 2) * 16384u
                             + (uint32_t)(row * 128 + ch * 16);
                ldsm_x4_trans(vh, sb + SM_VH + off);
                ldsm_x4_trans(vl, sb + SM_VL + off);
                int oj = 2 * dt;
                mma_bf16(ov[oj],     ph, &vh[0]);
                mma_bf16(ov[oj + 1], ph, &vh[2]);
                mma_bf16(ov[oj],     pl, &vh[0]);
                mma_bf16(ov[oj + 1], pl, &vh[2]);
                mma_bf16(ov[oj],     ph, &vl[0]);
                mma_bf16(ov[oj + 1], ph, &vl[2]);
            }
        }
    }

    // ---- epilogue: normalize and write O ----
    {
        float i0 = 1.f / l2[0], i1 = 1.f / l2[1];
        size_t rA = qrow0 + qlocA;
        #pragma unroll
        for (int j = 0; j < 16; j++) {
            int c = 8 * j + 2 * (lane & 3);
            float2 v0 = make_float2(ov[j][0] * i0, ov[j][1] * i0);
            float2 v1 = make_float2(ov[j][2] * i1, ov[j][3] * i1);
            *(float2*)(Og + rA * HH + hcol + c)       = v0;
            *(float2*)(Og + (rA + 8) * HH + hcol + c) = v1;
        }
    }
}

// ---------------------------------------------------------------------------
// launch
// ---------------------------------------------------------------------------
extern "C" void kernel_launch(void* const* d_in, const int* in_sizes, int n_in,
                              void* d_out, int out_size)
{
    (void)in_sizes; (void)n_in; (void)out_size;
    const float* x      = (const float*)d_in[0];
    const float* wq     = (const float*)d_in[1];
    const float* bq     = (const float*)d_in[2];
    const float* wk_lat = (const float*)d_in[3];
    const float* wv_lat = (const float*)d_in[4];
    const float* wk     = (const float*)d_in[5];
    const float* wv     = (const float*)d_in[6];
    const float* wo     = (const float*)d_in[7];
    const float* bo     = (const float*)d_in[8];
    float* out = (float*)d_out;

    float *q, *k, *v, *klat, *vlat, *o;
    cudaGetSymbolAddress((void**)&q,    g_q);
    cudaGetSymbolAddress((void**)&k,    g_k);
    cudaGetSymbolAddress((void**)&v,    g_v);
    cudaGetSymbolAddress((void**)&klat, g_klat);
    cudaGetSymbolAddress((void**)&vlat, g_vlat);
    cudaGetSymbolAddress((void**)&o,    g_o);

    __nv_bfloat16 *x3, *o3, *klat3, *vlat3, *wq3, *wo3, *wklat3, *wvlat3, *wk3, *wv3;
    cudaGetSymbolAddress((void**)&x3,     g_x3);
    cudaGetSymbolAddress((void**)&o3,     g_o3);
    cudaGetSymbolAddress((void**)&klat3,  g_klat3);
    cudaGetSymbolAddress((void**)&vlat3,  g_vlat3);
    cudaGetSymbolAddress((void**)&wq3,    g_wq3);
    cudaGetSymbolAddress((void**)&wo3,    g_wo3);
    cudaGetSymbolAddress((void**)&wklat3, g_wklat3);
    cudaGetSymbolAddress((void**)&wvlat3, g_wvlat3);
    cudaGetSymbolAddress((void**)&wk3,    g_wk3);
    cudaGetSymbolAddress((void**)&wv3,    g_wv3);

    const int smem_gemm = 66560;
    cudaFuncSetAttribute(gemm_bf16_kernel,
                         cudaFuncAttributeMaxDynamicSharedMemorySize, smem_gemm);
    const int smem_attn = 196608 + 1024;
    cudaFuncSetAttribute(mla_attn_tc_kernel,
                         cudaFuncAttributeMaxDynamicSharedMemorySize, smem_attn);

    // ---- split conversions ----
    {
        int tot = MM * HH / 2;
        split3_rows_kernel<<<(tot + 255) / 256, 256>>>(x, x3, MM, HH);
    }
    split3_T_kernel<<<dim3(HH / 32, HH / 32),  dim3(32, 8)>>>(wq,     wq3,    HH,  HH);
    split3_T_kernel<<<dim3(LDD / 32, HH / 32), dim3(32, 8)>>>(wk_lat, wklat3, HH,  LDD);
    split3_T_kernel<<<dim3(LDD / 32, HH / 32), dim3(32, 8)>>>(wv_lat, wvlat3, HH,  LDD);
    split3_T_kernel<<<dim3(HH / 32, LDD / 32), dim3(32, 8)>>>(wk,     wk3,    LDD, HH);
    split3_T_kernel<<<dim3(HH / 32, LDD / 32), dim3(32, 8)>>>(wv,     wv3,    LDD, HH);
    split3_T_kernel<<<dim3(HH / 32, HH / 32),  dim3(32, 8)>>>(wo,     wo3,    HH,  HH);

    // ---- projections ----
    gemm_bf16_kernel<<<dim3(HH / 128, MM / 128), 256, smem_gemm>>>(
        x3, wq3, bq, q, MM, HH, K3H);
    gemm_bf16_kernel<<<dim3(LDD / 128, MM / 128), 256, smem_gemm>>>(
        x3, wklat3, nullptr, klat, MM, LDD, K3H);
    gemm_bf16_kernel<<<dim3(LDD / 128, MM / 128), 256, smem_gemm>>>(
        x3, wvlat3, nullptr, vlat, MM, LDD, K3H);

    {
        int tot = MM * LDD / 2;
        split3_rows_kernel<<<(tot + 255) / 256, 256>>>(klat, klat3, MM, LDD);
        split3_rows_kernel<<<(tot + 255) / 256, 256>>>(vlat, vlat3, MM, LDD);
    }
    gemm_bf16_kernel<<<dim3(HH / 128, MM / 128), 256, smem_gemm>>>(
        klat3, wk3, nullptr, k, MM, HH, K3L);
    gemm_bf16_kernel<<<dim3(HH / 128, MM / 128), 256, smem_gemm>>>(
        vlat3, wv3, nullptr, v, MM, HH, K3L);

    // ---- attention (tensor cores) ----
    mla_attn_tc_kernel<<<dim3(SS / 128, BB * NHH), 256, smem_attn>>>(q, k, v, o);

    // ---- output projection ----
    {
        int tot = MM * HH / 2;
        split3_rows_kernel<<<(tot + 255) / 256, 256>>>(o, o3, MM, HH);
    }
    gemm_bf16_kernel<<<dim3(HH / 128, MM / 128), 256, smem_gemm>>>(
        o3, wo3, bo, out, MM, HH, K3H);
}

// round 5
// speedup vs baseline: 3.0215x; 1.0203x over previous
#include <cuda_runtime.h>
#include <cuda_bf16.h>
#include <math.h>
#include <stdint.h>
#include <string.h>

// Problem constants
#define BB   2
#define SS   2048
#define HH   2048
#define NHH  16
#define HDD  128
#define LDD  512
#define MM   (BB*SS)     // 4096
#define K3H  (3*HH)      // 6144
#define K3L  (3*LDD)     // 1536

// ---------------------------------------------------------------------------
// Scratch (static device globals — allocation-free)
// ---------------------------------------------------------------------------
// bf16 hi/lo planes for attention operands
__device__ __nv_bfloat16 g_qh[MM * (size_t)HH];
__device__ __nv_bfloat16 g_ql[MM * (size_t)HH];
__device__ __nv_bfloat16 g_kh[MM * (size_t)HH];
__device__ __nv_bfloat16 g_kl[MM * (size_t)HH];
__device__ __nv_bfloat16 g_vh[MM * (size_t)HH];
__device__ __nv_bfloat16 g_vl[MM * (size_t)HH];
// A-side [hi|lo|hi] concat buffers
__device__ __nv_bfloat16 g_x3[MM * (size_t)K3H];
__device__ __nv_bfloat16 g_o3[MM * (size_t)K3H];
__device__ __nv_bfloat16 g_klat3[MM * (size_t)K3L];
__device__ __nv_bfloat16 g_vlat3[MM * (size_t)K3L];
// B-side [hi|hi|lo] weight buffers
__device__ __nv_bfloat16 g_wq3[HH * (size_t)K3H];
__device__ __nv_bfloat16 g_wo3[HH * (size_t)K3H];
__device__ __nv_bfloat16 g_wklat3[LDD * (size_t)K3H];
__device__ __nv_bfloat16 g_wvlat3[LDD * (size_t)K3H];
__device__ __nv_bfloat16 g_wk3[HH * (size_t)K3L];
__device__ __nv_bfloat16 g_wv3[HH * (size_t)K3L];

// ---------------------------------------------------------------------------
// PTX helpers (baseline-PTX only)
// ---------------------------------------------------------------------------
__device__ __forceinline__ uint32_t smem_u32(const void* p) {
    uint32_t a;
    asm("{ .reg .u64 t; cvta.to.shared.u64 t, %1; cvt.u32.u64 %0, t; }"
        : "=r"(a) : "l"(p));
    return a;
}
__device__ __forceinline__ void cp_async16(uint32_t s, const void* g) {
    asm volatile("cp.async.cg.shared.global [%0], [%1], 16;" :: "r"(s), "l"(g));
}
#define CP_COMMIT() asm volatile("cp.async.commit_group;" ::: "memory")
#define CP_WAIT0()  asm volatile("cp.async.wait_group 0;" ::: "memory")
#define CP_WAIT1()  asm volatile("cp.async.wait_group 1;" ::: "memory")
#define SWZ128(o) ((o) ^ (((o) >> 3) & 0x70))

__device__ __forceinline__ void ldsm_x4(uint32_t* r, uint32_t addr) {
    asm volatile("ldmatrix.sync.aligned.m8n8.x4.shared.b16 {%0,%1,%2,%3}, [%4];"
        : "=r"(r[0]), "=r"(r[1]), "=r"(r[2]), "=r"(r[3]) : "r"(addr));
}
__device__ __forceinline__ void ldsm_x4_trans(uint32_t* r, uint32_t addr) {
    asm volatile("ldmatrix.sync.aligned.m8n8.x4.trans.shared.b16 {%0,%1,%2,%3}, [%4];"
        : "=r"(r[0]), "=r"(r[1]), "=r"(r[2]), "=r"(r[3]) : "r"(addr));
}
__device__ __forceinline__ void mma_bf16(float* d, const uint32_t* a,
                                         const uint32_t* b) {
    asm volatile(
        "mma.sync.aligned.m16n8k16.row.col.f32.bf16.bf16.f32 "
        "{%0,%1,%2,%3}, {%4,%5,%6,%7}, {%8,%9}, {%0,%1,%2,%3};"
        : "+f"(d[0]), "+f"(d[1]), "+f"(d[2]), "+f"(d[3])
        : "r"(a[0]), "r"(a[1]), "r"(a[2]), "r"(a[3]), "r"(b[0]), "r"(b[1]));
}
// pack {e -> low half, o -> high half}
__device__ __forceinline__ uint32_t packbf(float e, float o) {
    uint32_t r;
    asm("cvt.rn.bf16x2.f32 %0, %1, %2;" : "=r"(r) : "f"(o), "f"(e));
    return r;
}
// fast exp2, FMA-pipe only (no MUFU)
__device__ __forceinline__ float exp2p(float x) {
    x = fmaxf(x, -126.f);
    float n = rintf(x);
    float f = x - n;
    float p = 0.00015403530393381609f;
    p = fmaf(p, f, 0.0013333558146428443f);
    p = fmaf(p, f, 0.009618129107628477f);
    p = fmaf(p, f, 0.05550410866482158f);
    p = fmaf(p, f, 0.2402265069591007f);
    p = fmaf(p, f, 0.6931471805599453f);
    p = fmaf(p, f, 1.0f);
    return p * __int_as_float(((int)n + 127) << 23);
}

// ---------------------------------------------------------------------------
// bf16 split-K GEMM with fused-output epilogues.
// C = A'[M,Kp] @ B'[N,Kp]^T (+bias). 128x128 tile, BK=64, 3-stage cp.async,
// 256 thr = 8 warps (4M x 2N), one __syncthreads per BK iteration.
// MODE 0: fp32 C. MODE 1: (v+bias)*scale split into bf16 planes Ph/Pl.
// MODE 2: v split into [hi|lo|hi] concat C3 (row stride 3N).
// ---------------------------------------------------------------------------
__device__ __forceinline__ void load_tile(
    const __nv_bfloat16* __restrict__ A, const __nv_bfloat16* __restrict__ B,
    int Kp, int bm, int bn, int tid, uint32_t tbase, int kt, int stage)
{
    uint32_t abase = tbase + (uint32_t)stage * 32768u;
    uint32_t bbase = abase + 16384u;
    #pragma unroll
    for (int r = 0; r < 4; r++) {
        int idx = tid + 256 * r;
        int row = idx >> 3;
        int c16 = idx & 7;
        uint32_t soff = SWZ128((uint32_t)(row * 128 + c16 * 16));
        cp_async16(abase + soff, A + (size_t)(bm + row) * Kp + kt * 64 + c16 * 8);
        cp_async16(bbase + soff, B + (size_t)(bn + row) * Kp + kt * 64 + c16 * 8);
    }
    CP_COMMIT();
}

template<int MODE>
__global__ void __launch_bounds__(256, 2) gemm_bf16_kernel(
    const __nv_bfloat16* __restrict__ A,
    const __nv_bfloat16* __restrict__ B,
    const float* __restrict__ bias,
    float* __restrict__ C,
    __nv_bfloat16* __restrict__ Ph,
    __nv_bfloat16* __restrict__ Pl,
    __nv_bfloat16* __restrict__ C3,
    float scale,
    int M, int N, int Kp)
{
    extern __shared__ char dsm[];
    const uint32_t tbase = (smem_u32(dsm) + 1023u) & ~1023u;

    const int tid  = threadIdx.x;
    const int wid  = tid >> 5;
    const int lane = tid & 31;
    const int bm = blockIdx.y * 128;
    const int bn = blockIdx.x * 128;
    const int wm = (wid & 3) * 32;
    const int wn = (wid >> 2) * 64;

    float acc[2][8][4];
    #pragma unroll
    for (int mt = 0; mt < 2; mt++)
        #pragma unroll
        for (int n8 = 0; n8 < 8; n8++)
            #pragma unroll
            for (int j = 0; j < 4; j++) acc[mt][n8][j] = 0.f;

    const int a_row   = wm + (lane & 15);
    const int a_chalf = lane >> 4;
    const int b_row   = wn + ((lane >> 4) << 3) + (lane & 7);
    const int b_chalf = (lane >> 3) & 1;

    const int niter = Kp / 64;
    load_tile(A, B, Kp, bm, bn, tid, tbase, 0, 0);
    load_tile(A, B, Kp, bm, bn, tid, tbase, 1, 1);

    int cs = 0, ls = 2;
    for (int it = 0; it < niter; it++) {
        CP_WAIT1();
        __syncthreads();
        if (it + 2 < niter) {
            load_tile(A, B, Kp, bm, bn, tid, tbase, it + 2, ls);
            ls = (ls == 2) ? 0 : ls + 1;
        }

        const uint32_t a_s = tbase + (uint32_t)cs * 32768u;
        const uint32_t b_s = a_s + 16384u;
        cs = (cs == 2) ? 0 : cs + 1;

        #pragma unroll
        for (int s = 0; s < 4; s++) {
            uint32_t af[2][4];
            #pragma unroll
            for (int mt = 0; mt < 2; mt++) {
                int row = a_row + mt * 16;
                int ch  = (2 * s + a_chalf) ^ (row & 7);
                ldsm_x4(af[mt], a_s + (uint32_t)(row * 128 + ch * 16));
            }
            uint32_t bf[4][4];
            #pragma unroll
            for (int nt = 0; nt < 4; nt++) {
                int row = b_row + nt * 16;
                int ch  = (2 * s + b_chalf) ^ (row & 7);
                ldsm_x4(bf[nt], b_s + (uint32_t)(row * 128 + ch * 16));
            }
            #pragma unroll
            for (int mt = 0; mt < 2; mt++)
                #pragma unroll
                for (int n8 = 0; n8 < 8; n8++)
                    mma_bf16(acc[mt][n8], af[mt], &bf[n8 >> 1][(n8 & 1) * 2]);
        }
    }

    // epilogue
    #pragma unroll
    for (int mt = 0; mt < 2; mt++) {
        const int r0 = bm + wm + mt * 16 + (lane >> 2);
        #pragma unroll
        for (int n8 = 0; n8 < 8; n8++) {
            const int c0 = bn + wn + n8 * 8 + (lane & 3) * 2;
            float b0 = 0.f, b1 = 0.f;
            if (MODE != 2 && bias) { b0 = bias[c0]; b1 = bias[c0 + 1]; }
            float2 v0 = make_float2(acc[mt][n8][0] + b0, acc[mt][n8][1] + b1);
            float2 v1 = make_float2(acc[mt][n8][2] + b0, acc[mt][n8][3] + b1);
            if (MODE == 0) {
                *(float2*)(C + (size_t)r0 * N + c0)       = v0;
                *(float2*)(C + (size_t)(r0 + 8) * N + c0) = v1;
            } else if (MODE == 1) {
                v0.x *= scale; v0.y *= scale; v1.x *= scale; v1.y *= scale;
                uint32_t h0 = packbf(v0.x, v0.y);
                uint32_t h1 = packbf(v1.x, v1.y);
                uint32_t l0 = packbf(v0.x - __uint_as_float(h0 << 16),
                                     v0.y - __uint_as_float(h0 & 0xffff0000u));
                uint32_t l1 = packbf(v1.x - __uint_as_float(h1 << 16),
                                     v1.y - __uint_as_float(h1 & 0xffff0000u));
                *(uint32_t*)(Ph + (size_t)r0 * N + c0)       = h0;
                *(uint32_t*)(Ph + (size_t)(r0 + 8) * N + c0) = h1;
                *(uint32_t*)(Pl + (size_t)r0 * N + c0)       = l0;
                *(uint32_t*)(Pl + (size_t)(r0 + 8) * N + c0) = l1;
            } else {
                uint32_t h0 = packbf(v0.x, v0.y);
                uint32_t h1 = packbf(v1.x, v1.y);
                uint32_t l0 = packbf(v0.x - __uint_as_float(h0 << 16),
                                     v0.y - __uint_as_float(h0 & 0xffff0000u));
                uint32_t l1 = packbf(v1.x - __uint_as_float(h1 << 16),
                                     v1.y - __uint_as_float(h1 & 0xffff0000u));
                __nv_bfloat16* row0 = C3 + (size_t)r0 * (3 * N);
                __nv_bfloat16* row1 = C3 + (size_t)(r0 + 8) * (3 * N);
                *(uint32_t*)(row0 + c0)         = h0;
                *(uint32_t*)(row0 + N + c0)     = l0;
                *(uint32_t*)(row0 + 2 * N + c0) = h0;
                *(uint32_t*)(row1 + c0)         = h1;
                *(uint32_t*)(row1 + N + c0)     = l1;
                *(uint32_t*)(row1 + 2 * N + c0) = h1;
            }
        }
    }
}

// ---------------------------------------------------------------------------
// Input conversions (x and weights only)
// ---------------------------------------------------------------------------
__global__ void split3_rows_kernel(const float* __restrict__ in,
                                   __nv_bfloat16* __restrict__ out, int R, int C)
{
    int i2 = blockIdx.x * blockDim.x + threadIdx.x;
    int total = R * (C >> 1);
    if (i2 >= total) return;
    int c2 = C >> 1;
    int r = i2 / c2, p = i2 - r * c2;
    float2 v = ((const float2*)in)[i2];
    __nv_bfloat162 h, l;
    h.x = __float2bfloat16(v.x);
    h.y = __float2bfloat16(v.y);
    l.x = __float2bfloat16(v.x - __bfloat162float(h.x));
    l.y = __float2bfloat16(v.y - __bfloat162float(h.y));
    __nv_bfloat162* ob = (__nv_bfloat162*)(out + (size_t)r * 3 * C);
    ob[p]          = h;
    ob[c2 + p]     = l;
    ob[2 * c2 + p] = h;
}

__global__ void split3_T_kernel(const float* __restrict__ in,
                                __nv_bfloat16* __restrict__ out, int K, int N)
{
    __shared__ float t[32][33];
    int k0 = blockIdx.y * 32, n0 = blockIdx.x * 32;
    int tx = threadIdx.x, ty = threadIdx.y;
    #pragma unroll
    for (int i = 0; i < 32; i += 8)
        t[ty + i][tx] = in[(size_t)(k0 + ty + i) * N + n0 + tx];
    __syncthreads();
    #pragma unroll
    for (int i = 0; i < 32; i += 8) {
        int n = ty + i;
        float v = t[tx][n];
        __nv_bfloat16 h = __float2bfloat16(v);
        __nv_bfloat16 l = __float2bfloat16(v - __bfloat162float(h));
        size_t base = (size_t)(n0 + n) * 3 * K;
        out[base + k0 + tx]         = h;
        out[base + K + k0 + tx]     = h;
        out[base + 2 * K + k0 + tx] = l;
    }
}

// ---------------------------------------------------------------------------
// Tensor-core flash attention (causal), hi/lo split, bf16 plane inputs.
// Block: 256 thr = 8 warps; each warp owns 16 q rows. One (b,h,qtile) per CTA.
// smem: 6 tiles of 128x128 bf16 (Qh,Ql,Kh,Kl,Vh,Vl), subtile-swizzled.
// Writes O directly in [hi|lo|hi] concat form (o3).
// ---------------------------------------------------------------------------
#define SM_QH 0u
#define SM_QL 32768u
#define SM_KH 65536u
#define SM_KL 98304u
#define SM_VH 131072u
#define SM_VL 163840u

__global__ void __launch_bounds__(256) mla_attn_tc_kernel(
    const __nv_bfloat16* __restrict__ Qh, const __nv_bfloat16* __restrict__ Ql,
    const __nv_bfloat16* __restrict__ Kh, const __nv_bfloat16* __restrict__ Kl,
    const __nv_bfloat16* __restrict__ Vh, const __nv_bfloat16* __restrict__ Vl,
    __nv_bfloat16* __restrict__ O3)
{
    extern __shared__ char dsm[];
    const uint32_t sb = (smem_u32(dsm) + 1023u) & ~1023u;

    const int tid  = threadIdx.x;
    const int lane = tid & 31;
    const int w    = tid >> 5;
    const int bh   = blockIdx.y;
    const int b    = bh >> 4;
    const int h    = bh & 15;
    const int qt   = gridDim.x - 1 - blockIdx.x;   // heavy tiles first

    const size_t qrow0 = (size_t)b * SS + (size_t)qt * 128;
    const size_t hcol  = (size_t)h * HDD;

    // ---- load Q tile planes (scale already folded in by the q GEMM) ----
    #pragma unroll
    for (int i = 0; i < 8; i++) {
        int idx = tid + 256 * i;           // 16B-chunk index over [128][16]
        int r   = idx >> 4;
        int d   = (idx & 15) * 8;          // bf16 col
        uint32_t off = (uint32_t)(d >> 6) * 16384u
                     + SWZ128((uint32_t)(r * 128 + (d & 63) * 2));
        const size_t src = (qrow0 + r) * HH + hcol + d;
        cp_async16(sb + SM_QH + off, Qh + src);
        cp_async16(sb + SM_QL + off, Ql + src);
    }
    CP_COMMIT();

    // per-thread softmax state (rows: A = 16w+lane/4, B = A+8)
    float m2[2] = {-1e30f, -1e30f};
    float l2[2] = {0.f, 0.f};
    float ov[16][4];
    #pragma unroll
    for (int j = 0; j < 16; j++)
        ov[j][0] = ov[j][1] = ov[j][2] = ov[j][3] = 0.f;

    const int a_row  = 16 * w + (lane & 15);
    const int a_ch   = lane >> 4;
    const int b_rowb = ((lane >> 4) << 3) + (lane & 7);
    const int b_ch   = (lane >> 3) & 1;
    const int v_row  = (lane & 7) + ((lane >> 3) & 1) * 8;
    const int qlocA  = 16 * w + (lane >> 2);

    for (int kt = 0; kt <= qt; kt++) {
        __syncthreads();   // previous compute done with K/V smem

        // ---- async load K and V tile planes ----
        const size_t krow0 = (size_t)b * SS + (size_t)kt * 128;
        #pragma unroll
        for (int i = 0; i < 8; i++) {
            int idx = tid + 256 * i;
            int r   = idx >> 4;
            int d   = (idx & 15) * 8;
            uint32_t off = (uint32_t)(d >> 6) * 16384u
                         + SWZ128((uint32_t)(r * 128 + (d & 63) * 2));
            const size_t src = (krow0 + r) * HH + hcol + d;
            cp_async16(sb + SM_KH + off, Kh + src);
            cp_async16(sb + SM_KL + off, Kl + src);
            cp_async16(sb + SM_VH + off, Vh + src);
            cp_async16(sb + SM_VL + off, Vl + src);
        }
        CP_COMMIT();
        CP_WAIT0();
        __syncthreads();

        // ---- scores: S = Qh·Kh^T + Ql·Kh^T + Qh·Kl^T ----
        float sc[16][4];
        #pragma unroll
        for (int j = 0; j < 16; j++)
            sc[j][0] = sc[j][1] = sc[j][2] = sc[j][3] = 0.f;

        #pragma unroll
        for (int kc = 0; kc < 8; kc++) {
            uint32_t ah[4], al[4];
            {
                int ch = (2 * (kc & 3) + a_ch) ^ (a_row & 7);
                uint32_t off = (uint32_t)(kc >> 2) * 16384u
                             + (uint32_t)(a_row * 128 + ch * 16);
                ldsm_x4(ah, sb + SM_QH + off);
                ldsm_x4(al, sb + SM_QL + off);
            }
            #pragma unroll
            for (int half = 0; half < 2; half++) {
                uint32_t bh4[4][4], bl4[4][4];
                #pragma unroll
                for (int nt4 = 0; nt4 < 4; nt4++) {
                    int row = (half * 4 + nt4) * 16 + b_rowb;
                    int ch = (2 * (kc & 3) + b_ch) ^ (row & 7);
                    uint32_t off = (uint32_t)(kc >> 2) * 16384u
                                 + (uint32_t)(row * 128 + ch * 16);
                    ldsm_x4(bh4[nt4], sb + SM_KH + off);
                    ldsm_x4(bl4[nt4], sb + SM_KL + off);
                }
                #pragma unroll
                for (int nt4 = 0; nt4 < 4; nt4++) {
                    int j0 = (half * 4 + nt4) * 2;
                    mma_bf16(sc[j0],     ah, &bh4[nt4][0]);
                    mma_bf16(sc[j0 + 1], ah, &bh4[nt4][2]);
                    mma_bf16(sc[j0],     al, &bh4[nt4][0]);
                    mma_bf16(sc[j0 + 1], al, &bh4[nt4][2]);
                    mma_bf16(sc[j0],     ah, &bl4[nt4][0]);
                    mma_bf16(sc[j0 + 1], ah, &bl4[nt4][2]);
                }
            }
        }

        // ---- causal mask (diagonal tile only) ----
        if (kt == qt) {
            #pragma unroll
            for (int j = 0; j < 16; j++) {
                int kkb = 8 * j + 2 * (lane & 3);
                #pragma unroll
                for (int c = 0; c < 2; c++) {
                    if (kkb + c > qlocA)     sc[j][c]     = -1e30f;
                    if (kkb + c > qlocA + 8) sc[j][2 + c] = -1e30f;
                }
            }
        }

        // ---- online softmax (base-2 domain) ----
        {
            float mA = -1e30f, mB = -1e30f;
            #pragma unroll
            for (int j = 0; j < 16; j++) {
                mA = fmaxf(mA, fmaxf(sc[j][0], sc[j][1]));
                mB = fmaxf(mB, fmaxf(sc[j][2], sc[j][3]));
            }
            mA = fmaxf(mA, __shfl_xor_sync(0xffffffffu, mA, 1));
            mA = fmaxf(mA, __shfl_xor_sync(0xffffffffu, mA, 2));
            mB = fmaxf(mB, __shfl_xor_sync(0xffffffffu, mB, 1));
            mB = fmaxf(mB, __shfl_xor_sync(0xffffffffu, mB, 2));
            float nmA = fmaxf(m2[0], mA), nmB = fmaxf(m2[1], mB);
            float aA = exp2p(m2[0] - nmA), aB = exp2p(m2[1] - nmB);
            float sA = 0.f, sB = 0.f;
            #pragma unroll
            for (int j = 0; j < 16; j++) {
                sc[j][0] = exp2p(sc[j][0] - nmA);
                sc[j][1] = exp2p(sc[j][1] - nmA);
                sc[j][2] = exp2p(sc[j][2] - nmB);
                sc[j][3] = exp2p(sc[j][3] - nmB);
                sA += sc[j][0] + sc[j][1];
                sB += sc[j][2] + sc[j][3];
            }
            sA += __shfl_xor_sync(0xffffffffu, sA, 1);
            sA += __shfl_xor_sync(0xffffffffu, sA, 2);
            sB += __shfl_xor_sync(0xffffffffu, sB, 1);
            sB += __shfl_xor_sync(0xffffffffu, sB, 2);
            l2[0] = l2[0] * aA + sA;
            l2[1] = l2[1] * aB + sB;
            m2[0] = nmA; m2[1] = nmB;
            #pragma unroll
            for (int j = 0; j < 16; j++) {
                ov[j][0] *= aA; ov[j][1] *= aA;
                ov[j][2] *= aB; ov[j][3] *= aB;
            }
        }

        // ---- O += Ph·Vh + Pl·Vh + Ph·Vl ----
        #pragma unroll
        for (int kc = 0; kc < 8; kc++) {
            int j0 = 2 * kc;
            uint32_t ph[4], pl[4];
            #pragma unroll
            for (int u = 0; u < 2; u++) {
                #pragma unroll
                for (int t = 0; t < 2; t++) {
                    float e = sc[j0 + u][2 * t];
                    float o = sc[j0 + u][2 * t + 1];
                    uint32_t hp = packbf(e, o);
                    ph[2 * u + t] = hp;
                    pl[2 * u + t] = packbf(e - __uint_as_float(hp << 16),
                                           o - __uint_as_float(hp & 0xffff0000u));
                }
            }
            #pragma unroll
            for (int dt = 0; dt < 8; dt++) {
                uint32_t vh[4], vl[4];
                int row = kc * 16 + v_row;
                int dloc = (dt * 16) & 63;
                int ch = ((dloc >> 3) + (lane >> 4)) ^ (row & 7);
                uint32_t off = (uint32_t)(dt >> 2) * 16384u
                             + (uint32_t)(row * 128 + ch * 16);
                ldsm_x4_trans(vh, sb + SM_VH + off);
                ldsm_x4_trans(vl, sb + SM_VL + off);
                int oj = 2 * dt;
                mma_bf16(ov[oj],     ph, &vh[0]);
                mma_bf16(ov[oj + 1], ph, &vh[2]);
                mma_bf16(ov[oj],     pl, &vh[0]);
                mma_bf16(ov[oj + 1], pl, &vh[2]);
                mma_bf16(ov[oj],     ph, &vl[0]);
                mma_bf16(ov[oj + 1], ph, &vl[2]);
            }
        }
    }

    // ---- epilogue: normalize and write o3 = [hi|lo|hi] ----
    {
        float i0 = 1.f / l2[0], i1 = 1.f / l2[1];
        size_t rA = qrow0 + qlocA;
        __nv_bfloat16* row0 = O3 + rA * (size_t)K3H + hcol;
        __nv_bfloat16* row1 = O3 + (rA + 8) * (size_t)K3H + hcol;
        #pragma unroll
        for (int j = 0; j < 16; j++) {
            int c = 8 * j + 2 * (lane & 3);
            float e0 = ov[j][0] * i0, o0 = ov[j][1] * i0;
            float e1 = ov[j][2] * i1, o1 = ov[j][3] * i1;
            uint32_t h0 = packbf(e0, o0);
            uint32_t h1 = packbf(e1, o1);
            uint32_t l0 = packbf(e0 - __uint_as_float(h0 << 16),
                                 o0 - __uint_as_float(h0 & 0xffff0000u));
            uint32_t l1 = packbf(e1 - __uint_as_float(h1 << 16),
                                 o1 - __uint_as_float(h1 & 0xffff0000u));
            *(uint32_t*)(row0 + c)          = h0;
            *(uint32_t*)(row0 + HH + c)     = l0;
            *(uint32_t*)(row0 + 2 * HH + c) = h0;
            *(uint32_t*)(row1 + c)          = h1;
            *(uint32_t*)(row1 + HH + c)     = l1;
            *(uint32_t*)(row1 + 2 * HH + c) = h1;
        }
    }
}

// ---------------------------------------------------------------------------
// launch
// ---------------------------------------------------------------------------
extern "C" void kernel_launch(void* const* d_in, const int* in_sizes, int n_in,
                              void* d_out, int out_size)
{
    (void)in_sizes; (void)n_in; (void)out_size;
    const float* x      = (const float*)d_in[0];
    const float* wq     = (const float*)d_in[1];
    const float* bq     = (const float*)d_in[2];
    const float* wk_lat = (const float*)d_in[3];
    const float* wv_lat = (const float*)d_in[4];
    const float* wk     = (const float*)d_in[5];
    const float* wv     = (const float*)d_in[6];
    const float* wo     = (const float*)d_in[7];
    const float* bo     = (const float*)d_in[8];
    float* out = (float*)d_out;

    __nv_bfloat16 *qh, *ql, *kh, *kl, *vh, *vl;
    cudaGetSymbolAddress((void**)&qh, g_qh);
    cudaGetSymbolAddress((void**)&ql, g_ql);
    cudaGetSymbolAddress((void**)&kh, g_kh);
    cudaGetSymbolAddress((void**)&kl, g_kl);
    cudaGetSymbolAddress((void**)&vh, g_vh);
    cudaGetSymbolAddress((void**)&vl, g_vl);

    __nv_bfloat16 *x3, *o3, *klat3, *vlat3, *wq3, *wo3, *wklat3, *wvlat3, *wk3, *wv3;
    cudaGetSymbolAddress((void**)&x3,     g_x3);
    cudaGetSymbolAddress((void**)&o3,     g_o3);
    cudaGetSymbolAddress((void**)&klat3,  g_klat3);
    cudaGetSymbolAddress((void**)&vlat3,  g_vlat3);
    cudaGetSymbolAddress((void**)&wq3,    g_wq3);
    cudaGetSymbolAddress((void**)&wo3,    g_wo3);
    cudaGetSymbolAddress((void**)&wklat3, g_wklat3);
    cudaGetSymbolAddress((void**)&wvlat3, g_wvlat3);
    cudaGetSymbolAddress((void**)&wk3,    g_wk3);
    cudaGetSymbolAddress((void**)&wv3,    g_wv3);

    const int smem_gemm = 3 * 32768 + 1024;
    cudaFuncSetAttribute(gemm_bf16_kernel<0>,
                         cudaFuncAttributeMaxDynamicSharedMemorySize, smem_gemm);
    cudaFuncSetAttribute(gemm_bf16_kernel<1>,
                         cudaFuncAttributeMaxDynamicSharedMemorySize, smem_gemm);
    cudaFuncSetAttribute(gemm_bf16_kernel<2>,
                         cudaFuncAttributeMaxDynamicSharedMemorySize, smem_gemm);
    const int smem_attn = 196608 + 1024;
    cudaFuncSetAttribute(mla_attn_tc_kernel,
                         cudaFuncAttributeMaxDynamicSharedMemorySize, smem_attn);

    // 1/sqrt(128) * log2(e) folded into q planes
    const float QSCALE = 0.08838834764831845f * 1.4426950408889634f;

    // ---- input conversions ----
    {
        int tot = MM * HH / 2;
        split3_rows_kernel<<<(tot + 255) / 256, 256>>>(x, x3, MM, HH);
    }
    split3_T_kernel<<<dim3(HH / 32, HH / 32),  dim3(32, 8)>>>(wq,     wq3,    HH,  HH);
    split3_T_kernel<<<dim3(LDD / 32, HH / 32), dim3(32, 8)>>>(wk_lat, wklat3, HH,  LDD);
    split3_T_kernel<<<dim3(LDD / 32, HH / 32), dim3(32, 8)>>>(wv_lat, wvlat3, HH,  LDD);
    split3_T_kernel<<<dim3(HH / 32, LDD / 32), dim3(32, 8)>>>(wk,     wk3,    LDD, HH);
    split3_T_kernel<<<dim3(HH / 32, LDD / 32), dim3(32, 8)>>>(wv,     wv3,    LDD, HH);
    split3_T_kernel<<<dim3(HH / 32, HH / 32),  dim3(32, 8)>>>(wo,     wo3,    HH,  HH);

    // ---- projections (fused split epilogues) ----
    // q -> planes (scaled)
    gemm_bf16_kernel<1><<<dim3(HH / 128, MM / 128), 256, smem_gemm>>>(
        x3, wq3, bq, nullptr, qh, ql, nullptr, QSCALE, MM, HH, K3H);
    // k_lat / v_lat -> [hi|lo|hi] concat
    gemm_bf16_kernel<2><<<dim3(LDD / 128, MM / 128), 256, smem_gemm>>>(
        x3, wklat3, nullptr, nullptr, nullptr, nullptr, klat3, 1.f, MM, LDD, K3H);
    gemm_bf16_kernel<2><<<dim3(LDD / 128, MM / 128), 256, smem_gemm>>>(
        x3, wvlat3, nullptr, nullptr, nullptr, nullptr, vlat3, 1.f, MM, LDD, K3H);
    // k / v -> planes
    gemm_bf16_kernel<1><<<dim3(HH / 128, MM / 128), 256, smem_gemm>>>(
        klat3, wk3, nullptr, nullptr, kh, kl, nullptr, 1.f, MM, HH, K3L);
    gemm_bf16_kernel<1><<<dim3(HH / 128, MM / 128), 256, smem_gemm>>>(
        vlat3, wv3, nullptr, nullptr, vh, vl, nullptr, 1.f, MM, HH, K3L);

    // ---- attention (writes o3 directly) ----
    mla_attn_tc_kernel<<<dim3(SS / 128, BB * NHH), 256, smem_attn>>>(
        qh, ql, kh, kl, vh, vl, o3);

    // ---- output projection ----
    gemm_bf16_kernel<0><<<dim3(HH / 128, MM / 128), 256, smem_gemm>>>(
        o3, wo3, bo, out, nullptr, nullptr, nullptr, 1.f, MM, HH, K3H);
}

// round 6
// speedup vs baseline: 4.3628x; 1.4439x over previous
#include <cuda_runtime.h>
#include <cuda_fp16.h>
#include <math.h>
#include <stdint.h>
#include <string.h>

// Problem constants
#define BB   2
#define SS   2048
#define HH   2048
#define NHH  16
#define HDD  128
#define LDD  512
#define MM   (BB*SS)     // 4096
#define K2H  (2*HH)      // 4096
#define K2L  (2*LDD)     // 1024

// ---------------------------------------------------------------------------
// Scratch (static device globals — allocation-free)
// ---------------------------------------------------------------------------
// fp16 planes for attention operands (K/V need hi only)
__device__ __half g_qh[MM * (size_t)HH];
__device__ __half g_ql[MM * (size_t)HH];
__device__ __half g_kh[MM * (size_t)HH];
__device__ __half g_vh[MM * (size_t)HH];
// A-side [hi|lo] concat buffers
__device__ __half g_x2[MM * (size_t)K2H];
__device__ __half g_o2[MM * (size_t)K2H];
__device__ __half g_klat2[MM * (size_t)K2L];
__device__ __half g_vlat2[MM * (size_t)K2L];
// B-side [hi|hi] weight buffers
__device__ __half g_wq2[HH * (size_t)K2H];
__device__ __half g_wo2[HH * (size_t)K2H];
__device__ __half g_wklat2[LDD * (size_t)K2H];
__device__ __half g_wvlat2[LDD * (size_t)K2H];
__device__ __half g_wk2[HH * (size_t)K2L];
__device__ __half g_wv2[HH * (size_t)K2L];

// ---------------------------------------------------------------------------
// PTX helpers (baseline-PTX only)
// ---------------------------------------------------------------------------
__device__ __forceinline__ uint32_t smem_u32(const void* p) {
    uint32_t a;
    asm("{ .reg .u64 t; cvta.to.shared.u64 t, %1; cvt.u32.u64 %0, t; }"
        : "=r"(a) : "l"(p));
    return a;
}
__device__ __forceinline__ void cp_async16(uint32_t s, const void* g) {
    asm volatile("cp.async.cg.shared.global [%0], [%1], 16;" :: "r"(s), "l"(g));
}
#define CP_COMMIT() asm volatile("cp.async.commit_group;" ::: "memory")
#define CP_WAIT0()  asm volatile("cp.async.wait_group 0;" ::: "memory")
#define CP_WAIT1()  asm volatile("cp.async.wait_group 1;" ::: "memory")
#define SWZ128(o) ((o) ^ (((o) >> 3) & 0x70))

__device__ __forceinline__ void ldsm_x4(uint32_t* r, uint32_t addr) {
    asm volatile("ldmatrix.sync.aligned.m8n8.x4.shared.b16 {%0,%1,%2,%3}, [%4];"
        : "=r"(r[0]), "=r"(r[1]), "=r"(r[2]), "=r"(r[3]) : "r"(addr));
}
__device__ __forceinline__ void ldsm_x4_trans(uint32_t* r, uint32_t addr) {
    asm volatile("ldmatrix.sync.aligned.m8n8.x4.trans.shared.b16 {%0,%1,%2,%3}, [%4];"
        : "=r"(r[0]), "=r"(r[1]), "=r"(r[2]), "=r"(r[3]) : "r"(addr));
}
__device__ __forceinline__ void mma_f16(float* d, const uint32_t* a,
                                        const uint32_t* b) {
    asm volatile(
        "mma.sync.aligned.m16n8k16.row.col.f32.f16.f16.f32 "
        "{%0,%1,%2,%3}, {%4,%5,%6,%7}, {%8,%9}, {%0,%1,%2,%3};"
        : "+f"(d[0]), "+f"(d[1]), "+f"(d[2]), "+f"(d[3])
        : "r"(a[0]), "r"(a[1]), "r"(a[2]), "r"(a[3]), "r"(b[0]), "r"(b[1]));
}
// pack {e -> low half, o -> high half}
__device__ __forceinline__ uint32_t packh(float e, float o) {
    uint32_t r;
    asm("cvt.rn.f16x2.f32 %0, %1, %2;" : "=r"(r) : "f"(o), "f"(e));
    return r;
}
// fast exp2, FMA-pipe only (no MUFU)
__device__ __forceinline__ float exp2p(float x) {
    x = fmaxf(x, -126.f);
    float n = rintf(x);
    float f = x - n;
    float p = 0.00015403530393381609f;
    p = fmaf(p, f, 0.0013333558146428443f);
    p = fmaf(p, f, 0.009618129107628477f);
    p = fmaf(p, f, 0.05550410866482158f);
    p = fmaf(p, f, 0.2402265069591007f);
    p = fmaf(p, f, 0.6931471805599453f);
    p = fmaf(p, f, 1.0f);
    return p * __int_as_float(((int)n + 127) << 23);
}

// ---------------------------------------------------------------------------
// fp16 2-term split GEMM:  C = A'[M,Kp] @ B'[N,Kp]^T (+bias)
// A' = [a_hi | a_lo], B' = [b_hi | b_hi].
// 128x128 tile, BK=64, 3-stage cp.async, 256 thr = 8 warps (4M x 2N).
// MODE 0: fp32 C.  MODE 1: (v+bias)*scale -> hi/lo fp16 planes Ph/Pl.
// MODE 2: v -> [hi|lo] concat C3 (row stride 2N).  MODE 3: hi plane only.
// ---------------------------------------------------------------------------
__device__ __forceinline__ void load_tile(
    const __half* __restrict__ A, const __half* __restrict__ B,
    int Kp, int bm, int bn, int tid, uint32_t tbase, int kt, int stage)
{
    uint32_t abase = tbase + (uint32_t)stage * 32768u;
    uint32_t bbase = abase + 16384u;
    #pragma unroll
    for (int r = 0; r < 4; r++) {
        int idx = tid + 256 * r;
        int row = idx >> 3;
        int c16 = idx & 7;
        uint32_t soff = SWZ128((uint32_t)(row * 128 + c16 * 16));
        cp_async16(abase + soff, A + (size_t)(bm + row) * Kp + kt * 64 + c16 * 8);
        cp_async16(bbase + soff, B + (size_t)(bn + row) * Kp + kt * 64 + c16 * 8);
    }
    CP_COMMIT();
}

template<int MODE>
__global__ void __launch_bounds__(256, 2) gemm_f16_kernel(
    const __half* __restrict__ A,
    const __half* __restrict__ B,
    const float* __restrict__ bias,
    float* __restrict__ C,
    __half* __restrict__ Ph,
    __half* __restrict__ Pl,
    __half* __restrict__ C2,
    float scale,
    int M, int N, int Kp)
{
    extern __shared__ char dsm[];
    const uint32_t tbase = (smem_u32(dsm) + 1023u) & ~1023u;

    const int tid  = threadIdx.x;
    const int wid  = tid >> 5;
    const int lane = tid & 31;
    const int bm = blockIdx.y * 128;
    const int bn = blockIdx.x * 128;
    const int wm = (wid & 3) * 32;
    const int wn = (wid >> 2) * 64;

    float acc[2][8][4];
    #pragma unroll
    for (int mt = 0; mt < 2; mt++)
        #pragma unroll
        for (int n8 = 0; n8 < 8; n8++)
            #pragma unroll
            for (int j = 0; j < 4; j++) acc[mt][n8][j] = 0.f;

    const int a_row   = wm + (lane & 15);
    const int a_chalf = lane >> 4;
    const int b_row   = wn + ((lane >> 4) << 3) + (lane & 7);
    const int b_chalf = (lane >> 3) & 1;

    const int niter = Kp / 64;
    load_tile(A, B, Kp, bm, bn, tid, tbase, 0, 0);
    load_tile(A, B, Kp, bm, bn, tid, tbase, 1, 1);

    int cs = 0, ls = 2;
    for (int it = 0; it < niter; it++) {
        CP_WAIT1();
        __syncthreads();
        if (it + 2 < niter) {
            load_tile(A, B, Kp, bm, bn, tid, tbase, it + 2, ls);
            ls = (ls == 2) ? 0 : ls + 1;
        }

        const uint32_t a_s = tbase + (uint32_t)cs * 32768u;
        const uint32_t b_s = a_s + 16384u;
        cs = (cs == 2) ? 0 : cs + 1;

        #pragma unroll
        for (int s = 0; s < 4; s++) {
            uint32_t af[2][4];
            #pragma unroll
            for (int mt = 0; mt < 2; mt++) {
                int row = a_row + mt * 16;
                int ch  = (2 * s + a_chalf) ^ (row & 7);
                ldsm_x4(af[mt], a_s + (uint32_t)(row * 128 + ch * 16));
            }
            uint32_t bf[4][4];
            #pragma unroll
            for (int nt = 0; nt < 4; nt++) {
                int row = b_row + nt * 16;
                int ch  = (2 * s + b_chalf) ^ (row & 7);
                ldsm_x4(bf[nt], b_s + (uint32_t)(row * 128 + ch * 16));
            }
            #pragma unroll
            for (int mt = 0; mt < 2; mt++)
                #pragma unroll
                for (int n8 = 0; n8 < 8; n8++)
                    mma_f16(acc[mt][n8], af[mt], &bf[n8 >> 1][(n8 & 1) * 2]);
        }
    }

    // epilogue
    #pragma unroll
    for (int mt = 0; mt < 2; mt++) {
        const int r0 = bm + wm + mt * 16 + (lane >> 2);
        #pragma unroll
        for (int n8 = 0; n8 < 8; n8++) {
            const int c0 = bn + wn + n8 * 8 + (lane & 3) * 2;
            float b0 = 0.f, b1 = 0.f;
            if (MODE != 2 && bias) { b0 = bias[c0]; b1 = bias[c0 + 1]; }
            float2 v0 = make_float2(acc[mt][n8][0] + b0, acc[mt][n8][1] + b1);
            float2 v1 = make_float2(acc[mt][n8][2] + b0, acc[mt][n8][3] + b1);
            if (MODE == 0) {
                *(float2*)(C + (size_t)r0 * N + c0)       = v0;
                *(float2*)(C + (size_t)(r0 + 8) * N + c0) = v1;
            } else if (MODE == 1) {
                v0.x *= scale; v0.y *= scale; v1.x *= scale; v1.y *= scale;
                uint32_t h0 = packh(v0.x, v0.y);
                uint32_t h1 = packh(v1.x, v1.y);
                __half2 h20 = *(__half2*)&h0;
                __half2 h21 = *(__half2*)&h1;
                uint32_t l0 = packh(v0.x - __low2float(h20), v0.y - __high2float(h20));
                uint32_t l1 = packh(v1.x - __low2float(h21), v1.y - __high2float(h21));
                *(uint32_t*)(Ph + (size_t)r0 * N + c0)       = h0;
                *(uint32_t*)(Ph + (size_t)(r0 + 8) * N + c0) = h1;
                *(uint32_t*)(Pl + (size_t)r0 * N + c0)       = l0;
                *(uint32_t*)(Pl + (size_t)(r0 + 8) * N + c0) = l1;
            } else if (MODE == 2) {
                uint32_t h0 = packh(v0.x, v0.y);
                uint32_t h1 = packh(v1.x, v1.y);
                __half2 h20 = *(__half2*)&h0;
                __half2 h21 = *(__half2*)&h1;
                uint32_t l0 = packh(v0.x - __low2float(h20), v0.y - __high2float(h20));
                uint32_t l1 = packh(v1.x - __low2float(h21), v1.y - __high2float(h21));
                __half* row0 = C2 + (size_t)r0 * (2 * N);
                __half* row1 = C2 + (size_t)(r0 + 8) * (2 * N);
                *(uint32_t*)(row0 + c0)     = h0;
                *(uint32_t*)(row0 + N + c0) = l0;
                *(uint32_t*)(row1 + c0)     = h1;
                *(uint32_t*)(row1 + N + c0) = l1;
            } else {   // MODE 3: hi plane only
                uint32_t h0 = packh(v0.x, v0.y);
                uint32_t h1 = packh(v1.x, v1.y);
                *(uint32_t*)(Ph + (size_t)r0 * N + c0)       = h0;
                *(uint32_t*)(Ph + (size_t)(r0 + 8) * N + c0) = h1;
            }
        }
    }
}

// ---------------------------------------------------------------------------
// Input conversions
// A-side: fp32 [R,C] -> fp16 [R, 2C] = [hi | lo]
// ---------------------------------------------------------------------------
__global__ void split2_rows_kernel(const float* __restrict__ in,
                                   __half* __restrict__ out, int R, int C)
{
    int i2 = blockIdx.x * blockDim.x + threadIdx.x;
    int total = R * (C >> 1);
    if (i2 >= total) return;
    int c2 = C >> 1;
    int r = i2 / c2, p = i2 - r * c2;
    float2 v = ((const float2*)in)[i2];
    __half2 h = __floats2half2_rn(v.x, v.y);
    __half2 l = __floats2half2_rn(v.x - __low2float(h), v.y - __high2float(h));
    __half2* ob = (__half2*)(out + (size_t)r * 2 * C);
    ob[p]      = h;
    ob[c2 + p] = l;
}

// B-side (weights): fp32 [K,N] -> fp16 [N, 2K] = [hi | hi]
__global__ void split2_T_kernel(const float* __restrict__ in,
                                __half* __restrict__ out, int K, int N)
{
    __shared__ float t[32][33];
    int k0 = blockIdx.y * 32, n0 = blockIdx.x * 32;
    int tx = threadIdx.x, ty = threadIdx.y;
    #pragma unroll
    for (int i = 0; i < 32; i += 8)
        t[ty + i][tx] = in[(size_t)(k0 + ty + i) * N + n0 + tx];
    __syncthreads();
    #pragma unroll
    for (int i = 0; i < 32; i += 8) {
        int n = ty + i;
        float v = t[tx][n];
        __half h = __float2half_rn(v);
        size_t base = (size_t)(n0 + n) * 2 * K;
        out[base + k0 + tx]     = h;
        out[base + K + k0 + tx] = h;
    }
}

// ---------------------------------------------------------------------------
// Tensor-core flash attention (causal), fp16 2-term split.
// Block: 256 thr = 8 warps; each warp owns 16 q rows. One (b,h,qtile) per CTA.
// smem: 4 tiles of 128x128 fp16 (Qh,Ql,Kh,Vh). Writes O as [hi|lo] concat.
// ---------------------------------------------------------------------------
#define SM_QH 0u
#define SM_QL 32768u
#define SM_KH 65536u
#define SM_VH 98304u

__global__ void __launch_bounds__(256) mla_attn_tc_kernel(
    const __half* __restrict__ Qh, const __half* __restrict__ Ql,
    const __half* __restrict__ Kh, const __half* __restrict__ Vh,
    __half* __restrict__ O2)
{
    extern __shared__ char dsm[];
    const uint32_t sb = (smem_u32(dsm) + 1023u) & ~1023u;

    const int tid  = threadIdx.x;
    const int lane = tid & 31;
    const int w    = tid >> 5;
    const int bh   = blockIdx.y;
    const int b    = bh >> 4;
    const int h    = bh & 15;
    const int qt   = gridDim.x - 1 - blockIdx.x;   // heavy tiles first

    const size_t qrow0 = (size_t)b * SS + (size_t)qt * 128;
    const size_t hcol  = (size_t)h * HDD;

    // ---- load Q tile planes (scale folded in by the q GEMM) ----
    #pragma unroll
    for (int i = 0; i < 8; i++) {
        int idx = tid + 256 * i;           // 16B-chunk index over [128][16]
        int r   = idx >> 4;
        int d   = (idx & 15) * 8;
        uint32_t off = (uint32_t)(d >> 6) * 16384u
                     + SWZ128((uint32_t)(r * 128 + (d & 63) * 2));
        const size_t src = (qrow0 + r) * HH + hcol + d;
        cp_async16(sb + SM_QH + off, Qh + src);
        cp_async16(sb + SM_QL + off, Ql + src);
    }
    CP_COMMIT();

    float m2[2] = {-1e30f, -1e30f};
    float l2[2] = {0.f, 0.f};
    float ov[16][4];
    #pragma unroll
    for (int j = 0; j < 16; j++)
        ov[j][0] = ov[j][1] = ov[j][2] = ov[j][3] = 0.f;

    const int a_row  = 16 * w + (lane & 15);
    const int a_ch   = lane >> 4;
    const int b_rowb = ((lane >> 4) << 3) + (lane & 7);
    const int b_ch   = (lane >> 3) & 1;
    const int v_row  = (lane & 7) + ((lane >> 3) & 1) * 8;
    const int qlocA  = 16 * w + (lane >> 2);

    for (int kt = 0; kt <= qt; kt++) {
        __syncthreads();

        // ---- async load K/V hi planes ----
        const size_t krow0 = (size_t)b * SS + (size_t)kt * 128;
        #pragma unroll
        for (int i = 0; i < 8; i++) {
            int idx = tid + 256 * i;
            int r   = idx >> 4;
            int d   = (idx & 15) * 8;
            uint32_t off = (uint32_t)(d >> 6) * 16384u
                         + SWZ128((uint32_t)(r * 128 + (d & 63) * 2));
            const size_t src = (krow0 + r) * HH + hcol + d;
            cp_async16(sb + SM_KH + off, Kh + src);
            cp_async16(sb + SM_VH + off, Vh + src);
        }
        CP_COMMIT();
        CP_WAIT0();
        __syncthreads();

        // ---- scores: S = Qh·Kh^T + Ql·Kh^T ----
        float sc[16][4];
        #pragma unroll
        for (int j = 0; j < 16; j++)
            sc[j][0] = sc[j][1] = sc[j][2] = sc[j][3] = 0.f;

        #pragma unroll
        for (int kc = 0; kc < 8; kc++) {
            uint32_t ah[4], al[4];
            {
                int ch = (2 * (kc & 3) + a_ch) ^ (a_row & 7);
                uint32_t off = (uint32_t)(kc >> 2) * 16384u
                             + (uint32_t)(a_row * 128 + ch * 16);
                ldsm_x4(ah, sb + SM_QH + off);
                ldsm_x4(al, sb + SM_QL + off);
            }
            #pragma unroll
            for (int half = 0; half < 2; half++) {
                uint32_t bh4[4][4];
                #pragma unroll
                for (int nt4 = 0; nt4 < 4; nt4++) {
                    int row = (half * 4 + nt4) * 16 + b_rowb;
                    int ch = (2 * (kc & 3) + b_ch) ^ (row & 7);
                    uint32_t off = (uint32_t)(kc >> 2) * 16384u
                                 + (uint32_t)(row * 128 + ch * 16);
                    ldsm_x4(bh4[nt4], sb + SM_KH + off);
                }
                #pragma unroll
                for (int nt4 = 0; nt4 < 4; nt4++) {
                    int j0 = (half * 4 + nt4) * 2;
                    mma_f16(sc[j0],     ah, &bh4[nt4][0]);
                    mma_f16(sc[j0 + 1], ah, &bh4[nt4][2]);
                    mma_f16(sc[j0],     al, &bh4[nt4][0]);
                    mma_f16(sc[j0 + 1], al, &bh4[nt4][2]);
                }
            }
        }

        // ---- causal mask (diagonal tile only) ----
        if (kt == qt) {
            #pragma unroll
            for (int j = 0; j < 16; j++) {
                int kkb = 8 * j + 2 * (lane & 3);
                #pragma unroll
                for (int c = 0; c < 2; c++) {
                    if (kkb + c > qlocA)     sc[j][c]     = -1e30f;
                    if (kkb + c > qlocA + 8) sc[j][2 + c] = -1e30f;
                }
            }
        }

        // ---- online softmax (base-2 domain) ----
        {
            float mA = -1e30f, mB = -1e30f;
            #pragma unroll
            for (int j = 0; j < 16; j++) {
                mA = fmaxf(mA, fmaxf(sc[j][0], sc[j][1]));
                mB = fmaxf(mB, fmaxf(sc[j][2], sc[j][3]));
            }
            mA = fmaxf(mA, __shfl_xor_sync(0xffffffffu, mA, 1));
            mA = fmaxf(mA, __shfl_xor_sync(0xffffffffu, mA, 2));
            mB = fmaxf(mB, __shfl_xor_sync(0xffffffffu, mB, 1));
            mB = fmaxf(mB, __shfl_xor_sync(0xffffffffu, mB, 2));
            float nmA = fmaxf(m2[0], mA), nmB = fmaxf(m2[1], mB);
            float aA = exp2p(m2[0] - nmA), aB = exp2p(m2[1] - nmB);
            float sA = 0.f, sB = 0.f;
            #pragma unroll
            for (int j = 0; j < 16; j++) {
                sc[j][0] = exp2p(sc[j][0] - nmA);
                sc[j][1] = exp2p(sc[j][1] - nmA);
                sc[j][2] = exp2p(sc[j][2] - nmB);
                sc[j][3] = exp2p(sc[j][3] - nmB);
                sA += sc[j][0] + sc[j][1];
                sB += sc[j][2] + sc[j][3];
            }
            sA += __shfl_xor_sync(0xffffffffu, sA, 1);
            sA += __shfl_xor_sync(0xffffffffu, sA, 2);
            sB += __shfl_xor_sync(0xffffffffu, sB, 1);
            sB += __shfl_xor_sync(0xffffffffu, sB, 2);
            l2[0] = l2[0] * aA + sA;
            l2[1] = l2[1] * aB + sB;
            m2[0] = nmA; m2[1] = nmB;
            #pragma unroll
            for (int j = 0; j < 16; j++) {
                ov[j][0] *= aA; ov[j][1] *= aA;
                ov[j][2] *= aB; ov[j][3] *= aB;
            }
        }

        // ---- O += Ph·Vh + Pl·Vh ----
        #pragma unroll
        for (int kc = 0; kc < 8; kc++) {
            int j0 = 2 * kc;
            uint32_t ph[4], pl[4];
            #pragma unroll
            for (int u = 0; u < 2; u++) {
                #pragma unroll
                for (int t = 0; t < 2; t++) {
                    float e = sc[j0 + u][2 * t];
                    float o = sc[j0 + u][2 * t + 1];
                    uint32_t hp = packh(e, o);
                    __half2 h2 = *(__half2*)&hp;
                    ph[2 * u + t] = hp;
                    pl[2 * u + t] = packh(e - __low2float(h2), o - __high2float(h2));
                }
            }
            #pragma unroll
            for (int dt = 0; dt < 8; dt++) {
                uint32_t vh4[4];
                int row = kc * 16 + v_row;
                int dloc = (dt * 16) & 63;
                int ch = ((dloc >> 3) + (lane >> 4)) ^ (row & 7);
                uint32_t off = (uint32_t)(dt >> 2) * 16384u
                             + (uint32_t)(row * 128 + ch * 16);
                ldsm_x4_trans(vh4, sb + SM_VH + off);
                int oj = 2 * dt;
                mma_f16(ov[oj],     ph, &vh4[0]);
                mma_f16(ov[oj + 1], ph, &vh4[2]);
                mma_f16(ov[oj],     pl, &vh4[0]);
                mma_f16(ov[oj + 1], pl, &vh4[2]);
            }
        }
    }

    // ---- epilogue: normalize and write o2 = [hi|lo] ----
    {
        float i0 = 1.f / l2[0], i1 = 1.f / l2[1];
        size_t rA = qrow0 + qlocA;
        __half* row0 = O2 + rA * (size_t)K2H + hcol;
        __half* row1 = O2 + (rA + 8) * (size_t)K2H + hcol;
        #pragma unroll
        for (int j = 0; j < 16; j++) {
            int c = 8 * j + 2 * (lane & 3);
            float e0 = ov[j][0] * i0, o0 = ov[j][1] * i0;
            float e1 = ov[j][2] * i1, o1 = ov[j][3] * i1;
            uint32_t h0 = packh(e0, o0);
            uint32_t h1 = packh(e1, o1);
            __half2 h20 = *(__half2*)&h0;
            __half2 h21 = *(__half2*)&h1;
            uint32_t l0 = packh(e0 - __low2float(h20), o0 - __high2float(h20));
            uint32_t l1 = packh(e1 - __low2float(h21), o1 - __high2float(h21));
            *(uint32_t*)(row0 + c)      = h0;
            *(uint32_t*)(row0 + HH + c) = l0;
            *(uint32_t*)(row1 + c)      = h1;
            *(uint32_t*)(row1 + HH + c) = l1;
        }
    }
}

// ---------------------------------------------------------------------------
// launch
// ---------------------------------------------------------------------------
extern "C" void kernel_launch(void* const* d_in, const int* in_sizes, int n_in,
                              void* d_out, int out_size)
{
    (void)in_sizes; (void)n_in; (void)out_size;
    const float* x      = (const float*)d_in[0];
    const float* wq     = (const float*)d_in[1];
    const float* bq     = (const float*)d_in[2];
    const float* wk_lat = (const float*)d_in[3];
    const float* wv_lat = (const float*)d_in[4];
    const float* wk     = (const float*)d_in[5];
    const float* wv     = (const float*)d_in[6];
    const float* wo     = (const float*)d_in[7];
    const float* bo     = (const float*)d_in[8];
    float* out = (float*)d_out;

    __half *qh, *ql, *kh, *vh;
    cudaGetSymbolAddress((void**)&qh, g_qh);
    cudaGetSymbolAddress((void**)&ql, g_ql);
    cudaGetSymbolAddress((void**)&kh, g_kh);
    cudaGetSymbolAddress((void**)&vh, g_vh);

    __half *x2, *o2, *klat2, *vlat2, *wq2, *wo2, *wklat2, *wvlat2, *wk2, *wv2;
    cudaGetSymbolAddress((void**)&x2,     g_x2);
    cudaGetSymbolAddress((void**)&o2,     g_o2);
    cudaGetSymbolAddress((void**)&klat2,  g_klat2);
    cudaGetSymbolAddress((void**)&vlat2,  g_vlat2);
    cudaGetSymbolAddress((void**)&wq2,    g_wq2);
    cudaGetSymbolAddress((void**)&wo2,    g_wo2);
    cudaGetSymbolAddress((void**)&wklat2, g_wklat2);
    cudaGetSymbolAddress((void**)&wvlat2, g_wvlat2);
    cudaGetSymbolAddress((void**)&wk2,    g_wk2);
    cudaGetSymbolAddress((void**)&wv2,    g_wv2);

    const int smem_gemm = 3 * 32768 + 1024;
    cudaFuncSetAttribute(gemm_f16_kernel<0>,
                         cudaFuncAttributeMaxDynamicSharedMemorySize, smem_gemm);
    cudaFuncSetAttribute(gemm_f16_kernel<1>,
                         cudaFuncAttributeMaxDynamicSharedMemorySize, smem_gemm);
    cudaFuncSetAttribute(gemm_f16_kernel<2>,
                         cudaFuncAttributeMaxDynamicSharedMemorySize, smem_gemm);
    cudaFuncSetAttribute(gemm_f16_kernel<3>,
                         cudaFuncAttributeMaxDynamicSharedMemorySize, smem_gemm);
    const int smem_attn = 131072 + 1024;
    cudaFuncSetAttribute(mla_attn_tc_kernel,
                         cudaFuncAttributeMaxDynamicSharedMemorySize, smem_attn);

    // 1/sqrt(128) * log2(e) folded into q planes
    const float QSCALE = 0.08838834764831845f * 1.4426950408889634f;

    // ---- input conversions ----
    {
        int tot = MM * HH / 2;
        split2_rows_kernel<<<(tot + 255) / 256, 256>>>(x, x2, MM, HH);
    }
    split2_T_kernel<<<dim3(HH / 32, HH / 32),  dim3(32, 8)>>>(wq,     wq2,    HH,  HH);
    split2_T_kernel<<<dim3(LDD / 32, HH / 32), dim3(32, 8)>>>(wk_lat, wklat2, HH,  LDD);
    split2_T_kernel<<<dim3(LDD / 32, HH / 32), dim3(32, 8)>>>(wv_lat, wvlat2, HH,  LDD);
    split2_T_kernel<<<dim3(HH / 32, LDD / 32), dim3(32, 8)>>>(wk,     wk2,    LDD, HH);
    split2_T_kernel<<<dim3(HH / 32, LDD / 32), dim3(32, 8)>>>(wv,     wv2,    LDD, HH);
    split2_T_kernel<<<dim3(HH / 32, HH / 32),  dim3(32, 8)>>>(wo,     wo2,    HH,  HH);

    // ---- projections (fused split epilogues) ----
    // q -> hi/lo planes (scaled)
    gemm_f16_kernel<1><<<dim3(HH / 128, MM / 128), 256, smem_gemm>>>(
        x2, wq2, bq, nullptr, qh, ql, nullptr, QSCALE, MM, HH, K2H);
    // k_lat / v_lat -> [hi|lo] concat
    gemm_f16_kernel<2><<<dim3(LDD / 128, MM / 128), 256, smem_gemm>>>(
        x2, wklat2, nullptr, nullptr, nullptr, nullptr, klat2, 1.f, MM, LDD, K2H);
    gemm_f16_kernel<2><<<dim3(LDD / 128, MM / 128), 256, smem_gemm>>>(
        x2, wvlat2, nullptr, nullptr, nullptr, nullptr, vlat2, 1.f, MM, LDD, K2H);
    // k / v -> hi plane only
    gemm_f16_kernel<3><<<dim3(HH / 128, MM / 128), 256, smem_gemm>>>(
        klat2, wk2, nullptr, nullptr, kh, nullptr, nullptr, 1.f, MM, HH, K2L);
    gemm_f16_kernel<3><<<dim3(HH / 128, MM / 128), 256, smem_gemm>>>(
        vlat2, wv2, nullptr, nullptr, vh, nullptr, nullptr, 1.f, MM, HH, K2L);

    // ---- attention (writes o2 directly) ----
    mla_attn_tc_kernel<<<dim3(SS / 128, BB * NHH), 256, smem_attn>>>(
        qh, ql, kh, vh, o2);

    // ---- output projection ----
    gemm_f16_kernel<0><<<dim3(HH / 128, MM / 128), 256, smem_gemm>>>(
        o2, wo2, bo, out, nullptr, nullptr, nullptr, 1.f, MM, HH, K2H);
}

// round 7
// speedup vs baseline: 4.6370x; 1.0629x over previous
#include <cuda_runtime.h>
#include <cuda_fp16.h>
#include <math.h>
#include <stdint.h>
#include <string.h>

// Problem constants
#define BB   2
#define SS   2048
#define HH   2048
#define NHH  16
#define HDD  128
#define LDD  512
#define MM   (BB*SS)     // 4096
#define K2H  (2*HH)      // 4096
#define K2L  (2*LDD)     // 1024

#define QSCALE_C (0.08838834764831845f * 1.4426950408889634f)

// ---------------------------------------------------------------------------
// Scratch (static device globals — allocation-free)
// ---------------------------------------------------------------------------
__device__ __half g_qh[MM * (size_t)HH];
__device__ __half g_ql[MM * (size_t)HH];
__device__ __half g_kh[MM * (size_t)HH];
__device__ __half g_vh[MM * (size_t)HH];
__device__ __half g_x2[MM * (size_t)K2H];
__device__ __half g_o2[MM * (size_t)K2H];
__device__ __half g_klat2[MM * (size_t)K2L];
__device__ __half g_vlat2[MM * (size_t)K2L];
__device__ __half g_wq2[HH * (size_t)K2H];
__device__ __half g_wo2[HH * (size_t)K2H];
__device__ __half g_wklat2[LDD * (size_t)K2H];
__device__ __half g_wvlat2[LDD * (size_t)K2H];
__device__ __half g_wk2[HH * (size_t)K2L];
__device__ __half g_wv2[HH * (size_t)K2L];

// ---------------------------------------------------------------------------
// PTX helpers (baseline-PTX only)
// ---------------------------------------------------------------------------
__device__ __forceinline__ uint32_t smem_u32(const void* p) {
    uint32_t a;
    asm("{ .reg .u64 t; cvta.to.shared.u64 t, %1; cvt.u32.u64 %0, t; }"
        : "=r"(a) : "l"(p));
    return a;
}
__device__ __forceinline__ void cp_async16(uint32_t s, const void* g) {
    asm volatile("cp.async.cg.shared.global [%0], [%1], 16;" :: "r"(s), "l"(g));
}
#define CP_COMMIT() asm volatile("cp.async.commit_group;" ::: "memory")
#define CP_WAIT0()  asm volatile("cp.async.wait_group 0;" ::: "memory")
#define CP_WAIT1()  asm volatile("cp.async.wait_group 1;" ::: "memory")
#define SWZ128(o) ((o) ^ (((o) >> 3) & 0x70))

__device__ __forceinline__ void ldsm_x4(uint32_t* r, uint32_t addr) {
    asm volatile("ldmatrix.sync.aligned.m8n8.x4.shared.b16 {%0,%1,%2,%3}, [%4];"
        : "=r"(r[0]), "=r"(r[1]), "=r"(r[2]), "=r"(r[3]) : "r"(addr));
}
__device__ __forceinline__ void ldsm_x4_trans(uint32_t* r, uint32_t addr) {
    asm volatile("ldmatrix.sync.aligned.m8n8.x4.trans.shared.b16 {%0,%1,%2,%3}, [%4];"
        : "=r"(r[0]), "=r"(r[1]), "=r"(r[2]), "=r"(r[3]) : "r"(addr));
}
__device__ __forceinline__ void mma_f16(float* d, const uint32_t* a,
                                        const uint32_t* b) {
    asm volatile(
        "mma.sync.aligned.m16n8k16.row.col.f32.f16.f16.f32 "
        "{%0,%1,%2,%3}, {%4,%5,%6,%7}, {%8,%9}, {%0,%1,%2,%3};"
        : "+f"(d[0]), "+f"(d[1]), "+f"(d[2]), "+f"(d[3])
        : "r"(a[0]), "r"(a[1]), "r"(a[2]), "r"(a[3]), "r"(b[0]), "r"(b[1]));
}
__device__ __forceinline__ uint32_t packh(float e, float o) {
    uint32_t r;
    asm("cvt.rn.f16x2.f32 %0, %1, %2;" : "=r"(r) : "f"(o), "f"(e));
    return r;
}
__device__ __forceinline__ float exp2p(float x) {
    x = fmaxf(x, -126.f);
    float n = rintf(x);
    float f = x - n;
    float p = 0.00015403530393381609f;
    p = fmaf(p, f, 0.0013333558146428443f);
    p = fmaf(p, f, 0.009618129107628477f);
    p = fmaf(p, f, 0.05550410866482158f);
    p = fmaf(p, f, 0.2402265069591007f);
    p = fmaf(p, f, 0.6931471805599453f);
    p = fmaf(p, f, 1.0f);
    return p * __int_as_float(((int)n + 127) << 23);
}

// ---------------------------------------------------------------------------
// GEMM core: acc = A'[bm:bm+128, :Kp] @ B'[bn:bn+128, :Kp]^T
// 128x128 tile, BK=64, 3-stage cp.async, 8 warps (4M x 2N).
// ---------------------------------------------------------------------------
__device__ __forceinline__ void load_tile(
    const __half* __restrict__ A, const __half* __restrict__ B,
    int Kp, int bm, int bn, int tid, uint32_t tbase, int kt, int stage)
{
    uint32_t abase = tbase + (uint32_t)stage * 32768u;
    uint32_t bbase = abase + 16384u;
    #pragma unroll
    for (int r = 0; r < 4; r++) {
        int idx = tid + 256 * r;
        int row = idx >> 3;
        int c16 = idx & 7;
        uint32_t soff = SWZ128((uint32_t)(row * 128 + c16 * 16));
        cp_async16(abase + soff, A + (size_t)(bm + row) * Kp + kt * 64 + c16 * 8);
        cp_async16(bbase + soff, B + (size_t)(bn + row) * Kp + kt * 64 + c16 * 8);
    }
    CP_COMMIT();
}

__device__ __forceinline__ void gemm_core(
    const __half* __restrict__ A, const __half* __restrict__ B,
    int Kp, int bm, int bn, int tid, int wid, int lane, uint32_t tbase,
    float acc[2][8][4])
{
    const int wm = (wid & 3) * 32;
    const int wn = (wid >> 2) * 64;
    const int a_row   = wm + (lane & 15);
    const int a_chalf = lane >> 4;
    const int b_row   = wn + ((lane >> 4) << 3) + (lane & 7);
    const int b_chalf = (lane >> 3) & 1;

    const int niter = Kp / 64;
    load_tile(A, B, Kp, bm, bn, tid, tbase, 0, 0);
    load_tile(A, B, Kp, bm, bn, tid, tbase, 1, 1);

    int cs = 0, ls = 2;
    for (int it = 0; it < niter; it++) {
        CP_WAIT1();
        __syncthreads();
        if (it + 2 < niter) {
            load_tile(A, B, Kp, bm, bn, tid, tbase, it + 2, ls);
            ls = (ls == 2) ? 0 : ls + 1;
        }
        const uint32_t a_s = tbase + (uint32_t)cs * 32768u;
        const uint32_t b_s = a_s + 16384u;
        cs = (cs == 2) ? 0 : cs + 1;

        #pragma unroll
        for (int s = 0; s < 4; s++) {
            uint32_t af[2][4];
            #pragma unroll
            for (int mt = 0; mt < 2; mt++) {
                int row = a_row + mt * 16;
                int ch  = (2 * s + a_chalf) ^ (row & 7);
                ldsm_x4(af[mt], a_s + (uint32_t)(row * 128 + ch * 16));
            }
            uint32_t bf[4][4];
            #pragma unroll
            for (int nt = 0; nt < 4; nt++) {
                int row = b_row + nt * 16;
                int ch  = (2 * s + b_chalf) ^ (row & 7);
                ldsm_x4(bf[nt], b_s + (uint32_t)(row * 128 + ch * 16));
            }
            #pragma unroll
            for (int mt = 0; mt < 2; mt++)
                #pragma unroll
                for (int n8 = 0; n8 < 8; n8++)
                    mma_f16(acc[mt][n8], af[mt], &bf[n8 >> 1][(n8 & 1) * 2]);
        }
    }
}

// ---------------------------------------------------------------------------
// Merged projection kernel: q (mode-1 planes) + klat/vlat (mode-2 concat).
// 768 tiles: [0,512) q, [512,640) klat, [640,768) vlat. All Kp = K2H.
// ---------------------------------------------------------------------------
__global__ void __launch_bounds__(256, 2) proj_kernel(
    const __half* __restrict__ x2,
    const __half* __restrict__ wq2,
    const __half* __restrict__ wklat2,
    const __half* __restrict__ wvlat2,
    const float* __restrict__ bq,
    __half* __restrict__ qh, __half* __restrict__ ql,
    __half* __restrict__ klat2, __half* __restrict__ vlat2)
{
    extern __shared__ char dsm[];
    const uint32_t tbase = (smem_u32(dsm) + 1023u) & ~1023u;
    const int tid  = threadIdx.x;
    const int wid  = tid >> 5;
    const int lane = tid & 31;

    const __half* B;
    __half *o1 = nullptr, *o2c = nullptr;
    int N, mode, bm, bn;
    const int bid = blockIdx.x;
    if (bid < 512) {
        B = wq2; N = 2048; mode = 1;
        bm = (bid >> 4) * 128; bn = (bid & 15) * 128;
        o1 = qh;
    } else {
        int t = bid - 512;
        if (t < 128) { B = wklat2; o2c = klat2; }
        else         { B = wvlat2; o2c = vlat2; t -= 128; }
        N = 512; mode = 2;
        bm = (t >> 2) * 128; bn = (t & 3) * 128;
    }

    float acc[2][8][4];
    #pragma unroll
    for (int mt = 0; mt < 2; mt++)
        #pragma unroll
        for (int n8 = 0; n8 < 8; n8++)
            #pragma unroll
            for (int j = 0; j < 4; j++) acc[mt][n8][j] = 0.f;

    gemm_core(x2, B, K2H, bm, bn, tid, wid, lane, tbase, acc);

    const int wm = (wid & 3) * 32;
    const int wn = (wid >> 2) * 64;
    #pragma unroll
    for (int mt = 0; mt < 2; mt++) {
        const int r0 = bm + wm + mt * 16 + (lane >> 2);
        #pragma unroll
        for (int n8 = 0; n8 < 8; n8++) {
            const int c0 = bn + wn + n8 * 8 + (lane & 3) * 2;
            float2 v0 = make_float2(acc[mt][n8][0], acc[mt][n8][1]);
            float2 v1 = make_float2(acc[mt][n8][2], acc[mt][n8][3]);
            if (mode == 1) {
                float b0 = bq[c0], b1 = bq[c0 + 1];
                v0.x = (v0.x + b0) * QSCALE_C; v0.y = (v0.y + b1) * QSCALE_C;
                v1.x = (v1.x + b0) * QSCALE_C; v1.y = (v1.y + b1) * QSCALE_C;
                uint32_t h0 = packh(v0.x, v0.y);
                uint32_t h1 = packh(v1.x, v1.y);
                __half2 h20 = *(__half2*)&h0;
                __half2 h21 = *(__half2*)&h1;
                uint32_t l0 = packh(v0.x - __low2float(h20), v0.y - __high2float(h20));
                uint32_t l1 = packh(v1.x - __low2float(h21), v1.y - __high2float(h21));
                *(uint32_t*)(o1 + (size_t)r0 * N + c0)        = h0;
                *(uint32_t*)(o1 + (size_t)(r0 + 8) * N + c0)  = h1;
                *(uint32_t*)(ql + (size_t)r0 * N + c0)        = l0;
                *(uint32_t*)(ql + (size_t)(r0 + 8) * N + c0)  = l1;
            } else {
                uint32_t h0 = packh(v0.x, v0.y);
                uint32_t h1 = packh(v1.x, v1.y);
                __half2 h20 = *(__half2*)&h0;
                __half2 h21 = *(__half2*)&h1;
                uint32_t l0 = packh(v0.x - __low2float(h20), v0.y - __high2float(h20));
                uint32_t l1 = packh(v1.x - __low2float(h21), v1.y - __high2float(h21));
                __half* row0 = o2c + (size_t)r0 * (2 * N);
                __half* row1 = o2c + (size_t)(r0 + 8) * (2 * N);
                *(uint32_t*)(row0 + c0)     = h0;
                *(uint32_t*)(row0 + N + c0) = l0;
                *(uint32_t*)(row1 + c0)     = h1;
                *(uint32_t*)(row1 + N + c0) = l1;
            }
        }
    }
}

// ---------------------------------------------------------------------------
// Merged k+v kernel: [0,512) k, [512,1024) v. Kp = K2L, mode-3 (hi plane).
// ---------------------------------------------------------------------------
__global__ void __launch_bounds__(256, 2) kv_kernel(
    const __half* __restrict__ klat2, const __half* __restrict__ vlat2,
    const __half* __restrict__ wk2,   const __half* __restrict__ wv2,
    __half* __restrict__ kh, __half* __restrict__ vh)
{
    extern __shared__ char dsm[];
    const uint32_t tbase = (smem_u32(dsm) + 1023u) & ~1023u;
    const int tid  = threadIdx.x;
    const int wid  = tid >> 5;
    const int lane = tid & 31;

    const __half *A, *B;
    __half* O;
    int t = blockIdx.x;
    if (t < 512) { A = klat2; B = wk2; O = kh; }
    else         { A = vlat2; B = wv2; O = vh; t -= 512; }
    const int bm = (t >> 4) * 128;
    const int bn = (t & 15) * 128;
    const int N = 2048;

    float acc[2][8][4];
    #pragma unroll
    for (int mt = 0; mt < 2; mt++)
        #pragma unroll
        for (int n8 = 0; n8 < 8; n8++)
            #pragma unroll
            for (int j = 0; j < 4; j++) acc[mt][n8][j] = 0.f;

    gemm_core(A, B, K2L, bm, bn, tid, wid, lane, tbase, acc);

    const int wm = (wid & 3) * 32;
    const int wn = (wid >> 2) * 64;
    #pragma unroll
    for (int mt = 0; mt < 2; mt++) {
        const int r0 = bm + wm + mt * 16 + (lane >> 2);
        #pragma unroll
        for (int n8 = 0; n8 < 8; n8++) {
            const int c0 = bn + wn + n8 * 8 + (lane & 3) * 2;
            uint32_t h0 = packh(acc[mt][n8][0], acc[mt][n8][1]);
            uint32_t h1 = packh(acc[mt][n8][2], acc[mt][n8][3]);
            *(uint32_t*)(O + (size_t)r0 * N + c0)       = h0;
            *(uint32_t*)(O + (size_t)(r0 + 8) * N + c0) = h1;
        }
    }
}

// ---------------------------------------------------------------------------
// Output projection: out = o2 @ wo2^T + bo (fp32 out)
// ---------------------------------------------------------------------------
__global__ void __launch_bounds__(256, 2) wo_kernel(
    const __half* __restrict__ o2, const __half* __restrict__ wo2,
    const float* __restrict__ bo, float* __restrict__ C)
{
    extern __shared__ char dsm[];
    const uint32_t tbase = (smem_u32(dsm) + 1023u) & ~1023u;
    const int tid  = threadIdx.x;
    const int wid  = tid >> 5;
    const int lane = tid & 31;
    const int bm = blockIdx.y * 128;
    const int bn = blockIdx.x * 128;
    const int N = 2048;

    float acc[2][8][4];
    #pragma unroll
    for (int mt = 0; mt < 2; mt++)
        #pragma unroll
        for (int n8 = 0; n8 < 8; n8++)
            #pragma unroll
            for (int j = 0; j < 4; j++) acc[mt][n8][j] = 0.f;

    gemm_core(o2, wo2, K2H, bm, bn, tid, wid, lane, tbase, acc);

    const int wm = (wid & 3) * 32;
    const int wn = (wid >> 2) * 64;
    #pragma unroll
    for (int mt = 0; mt < 2; mt++) {
        const int r0 = bm + wm + mt * 16 + (lane >> 2);
        #pragma unroll
        for (int n8 = 0; n8 < 8; n8++) {
            const int c0 = bn + wn + n8 * 8 + (lane & 3) * 2;
            float b0 = bo[c0], b1 = bo[c0 + 1];
            float2 v0 = make_float2(acc[mt][n8][0] + b0, acc[mt][n8][1] + b1);
            float2 v1 = make_float2(acc[mt][n8][2] + b0, acc[mt][n8][3] + b1);
            *(float2*)(C + (size_t)r0 * N + c0)       = v0;
            *(float2*)(C + (size_t)(r0 + 8) * N + c0) = v1;
        }
    }
}

// ---------------------------------------------------------------------------
// Input conversions
// ---------------------------------------------------------------------------
__global__ void split2_rows_kernel(const float* __restrict__ in,
                                   __half* __restrict__ out, int R, int C)
{
    int i2 = blockIdx.x * blockDim.x + threadIdx.x;
    int total = R * (C >> 1);
    if (i2 >= total) return;
    int c2 = C >> 1;
    int r = i2 / c2, p = i2 - r * c2;
    float2 v = ((const float2*)in)[i2];
    __half2 h = __floats2half2_rn(v.x, v.y);
    __half2 l = __floats2half2_rn(v.x - __low2float(h), v.y - __high2float(h));
    __half2* ob = (__half2*)(out + (size_t)r * 2 * C);
    ob[p]      = h;
    ob[c2 + p] = l;
}

// merged weight split: fp32 [K,N] -> fp16 [N, 2K] = [hi|hi], 6 weights, one launch
__global__ void splitw_kernel(
    const float* __restrict__ wq, const float* __restrict__ wklat,
    const float* __restrict__ wvlat, const float* __restrict__ wk,
    const float* __restrict__ wv, const float* __restrict__ wo,
    __half* __restrict__ wq2, __half* __restrict__ wklat2,
    __half* __restrict__ wvlat2, __half* __restrict__ wk2,
    __half* __restrict__ wv2, __half* __restrict__ wo2)
{
    __shared__ float t[32][33];
    int l = blockIdx.x;
    const float* in; __half* out; int K, N, tt;
    if (l < 4096)      { in = wq;    out = wq2;    K = 2048; N = 2048; tt = l; }
    else if (l < 5120) { in = wklat; out = wklat2; K = 2048; N = 512;  tt = l - 4096; }
    else if (l < 6144) { in = wvlat; out = wvlat2; K = 2048; N = 512;  tt = l - 5120; }
    else if (l < 7168) { in = wk;    out = wk2;    K = 512;  N = 2048; tt = l - 6144; }
    else if (l < 8192) { in = wv;    out = wv2;    K = 512;  N = 2048; tt = l - 7168; }
    else               { in = wo;    out = wo2;    K = 2048; N = 2048; tt = l - 8192; }
    int nnb = N >> 5;
    int k0 = (tt / nnb) * 32, n0 = (tt % nnb) * 32;
    int tx = threadIdx.x, ty = threadIdx.y;
    #pragma unroll
    for (int i = 0; i < 32; i += 8)
        t[ty + i][tx] = in[(size_t)(k0 + ty + i) * N + n0 + tx];
    __syncthreads();
    #pragma unroll
    for (int i = 0; i < 32; i += 8) {
        int n = ty + i;
        __half h = __float2half_rn(t[tx][n]);
        size_t base = (size_t)(n0 + n) * 2 * K;
        out[base + k0 + tx]     = h;
        out[base + K + k0 + tx] = h;
    }
}

// ---------------------------------------------------------------------------
// Tensor-core flash attention (causal), fp16 2-term split, K/V double-buffered.
// smem: Qh,Ql + 2x(Kh,Vh) = 192KB. 256 thr = 8 warps x 16 q-rows.
// ---------------------------------------------------------------------------
#define SM_QH 0u
#define SM_QL 32768u
#define SM_KB(b) (65536u + (uint32_t)(b) * 65536u)
#define SM_VB(b) (98304u + (uint32_t)(b) * 65536u)

__global__ void __launch_bounds__(256) mla_attn_tc_kernel(
    const __half* __restrict__ Qh, const __half* __restrict__ Ql,
    const __half* __restrict__ Kh, const __half* __restrict__ Vh,
    __half* __restrict__ O2)
{
    extern __shared__ char dsm[];
    const uint32_t sb = (smem_u32(dsm) + 1023u) & ~1023u;

    const int tid  = threadIdx.x;
    const int lane = tid & 31;
    const int w    = tid >> 5;
    const int bh   = blockIdx.y;
    const int b    = bh >> 4;
    const int h    = bh & 15;
    const int qt   = gridDim.x - 1 - blockIdx.x;   // heavy tiles first

    const size_t qrow0 = (size_t)b * SS + (size_t)qt * 128;
    const size_t hcol  = (size_t)h * HDD;

    // prologue: Q planes + KV tile 0 (buffer 0), one commit group
    #pragma unroll
    for (int i = 0; i < 8; i++) {
        int idx = tid + 256 * i;
        int r   = idx >> 4;
        int d   = (idx & 15) * 8;
        uint32_t off = (uint32_t)(d >> 6) * 16384u
                     + SWZ128((uint32_t)(r * 128 + (d & 63) * 2));
        const size_t qsrc = (qrow0 + r) * HH + hcol + d;
        cp_async16(sb + SM_QH + off, Qh + qsrc);
        cp_async16(sb + SM_QL + off, Ql + qsrc);
        const size_t ksrc = ((size_t)b * SS + r) * HH + hcol + d;
        cp_async16(sb + SM_KB(0) + off, Kh + ksrc);
        cp_async16(sb + SM_VB(0) + off, Vh + ksrc);
    }
    CP_COMMIT();

    float m2[2] = {-1e30f, -1e30f};
    float l2[2] = {0.f, 0.f};
    float ov[16][4];
    #pragma unroll
    for (int j = 0; j < 16; j++)
        ov[j][0] = ov[j][1] = ov[j][2] = ov[j][3] = 0.f;

    const int a_row  = 16 * w + (lane & 15);
    const int a_ch   = lane >> 4;
    const int b_rowb = ((lane >> 4) << 3) + (lane & 7);
    const int b_ch   = (lane >> 3) & 1;
    const int v_row  = (lane & 7) + ((lane >> 3) & 1) * 8;
    const int qlocA  = 16 * w + (lane >> 2);

    for (int kt = 0; kt <= qt; kt++) {
        CP_WAIT0();          // KV(kt) (and Q on first iter) resident
        __syncthreads();     // all warps done with the buffer being refilled

        // prefetch KV(kt+1) into the other buffer; overlaps with compute below
        if (kt < qt) {
            const size_t krow1 = (size_t)b * SS + (size_t)(kt + 1) * 128;
            const uint32_t kb1 = SM_KB((kt + 1) & 1);
            const uint32_t vb1 = SM_VB((kt + 1) & 1);
            #pragma unroll
            for (int i = 0; i < 8; i++) {
                int idx = tid + 256 * i;
                int r   = idx >> 4;
                int d   = (idx & 15) * 8;
                uint32_t off = (uint32_t)(d >> 6) * 16384u
                             + SWZ128((uint32_t)(r * 128 + (d & 63) * 2));
                const size_t src = (krow1 + r) * HH + hcol + d;
                cp_async16(sb + kb1 + off, Kh + src);
                cp_async16(sb + vb1 + off, Vh + src);
            }
            CP_COMMIT();
        }

        const uint32_t kbs = sb + SM_KB(kt & 1);
        const uint32_t vbs = sb + SM_VB(kt & 1);

        // ---- scores: S = Qh·Kh^T + Ql·Kh^T ----
        float sc[16][4];
        #pragma unroll
        for (int j = 0; j < 16; j++)
            sc[j][0] = sc[j][1] = sc[j][2] = sc[j][3] = 0.f;

        #pragma unroll
        for (int kc = 0; kc < 8; kc++) {
            uint32_t ah[4], al[4];
            {
                int ch = (2 * (kc & 3) + a_ch) ^ (a_row & 7);
                uint32_t off = (uint32_t)(kc >> 2) * 16384u
                             + (uint32_t)(a_row * 128 + ch * 16);
                ldsm_x4(ah, sb + SM_QH + off);
                ldsm_x4(al, sb + SM_QL + off);
            }
            #pragma unroll
            for (int half = 0; half < 2; half++) {
                uint32_t bh4[4][4];
                #pragma unroll
                for (int nt4 = 0; nt4 < 4; nt4++) {
                    int row = (half * 4 + nt4) * 16 + b_rowb;
                    int ch = (2 * (kc & 3) + b_ch) ^ (row & 7);
                    uint32_t off = (uint32_t)(kc >> 2) * 16384u
                                 + (uint32_t)(row * 128 + ch * 16);
                    ldsm_x4(bh4[nt4], kbs + off);
                }
                #pragma unroll
                for (int nt4 = 0; nt4 < 4; nt4++) {
                    int j0 = (half * 4 + nt4) * 2;
                    mma_f16(sc[j0],     ah, &bh4[nt4][0]);
                    mma_f16(sc[j0 + 1], ah, &bh4[nt4][2]);
                    mma_f16(sc[j0],     al, &bh4[nt4][0]);
                    mma_f16(sc[j0 + 1], al, &bh4[nt4][2]);
                }
            }
        }

        // ---- causal mask (diagonal tile only) ----
        if (kt == qt) {
            #pragma unroll
            for (int j = 0; j < 16; j++) {
                int kkb = 8 * j + 2 * (lane & 3);
                #pragma unroll
                for (int c = 0; c < 2; c++) {
                    if (kkb + c > qlocA)     sc[j][c]     = -1e30f;
                    if (kkb + c > qlocA + 8) sc[j][2 + c] = -1e30f;
                }
            }
        }

        // ---- online softmax (base-2 domain) ----
        {
            float mA = -1e30f, mB = -1e30f;
            #pragma unroll
            for (int j = 0; j < 16; j++) {
                mA = fmaxf(mA, fmaxf(sc[j][0], sc[j][1]));
                mB = fmaxf(mB, fmaxf(sc[j][2], sc[j][3]));
            }
            mA = fmaxf(mA, __shfl_xor_sync(0xffffffffu, mA, 1));
            mA = fmaxf(mA, __shfl_xor_sync(0xffffffffu, mA, 2));
            mB = fmaxf(mB, __shfl_xor_sync(0xffffffffu, mB, 1));
            mB = fmaxf(mB, __shfl_xor_sync(0xffffffffu, mB, 2));
            float nmA = fmaxf(m2[0], mA), nmB = fmaxf(m2[1], mB);
            float aA = exp2p(m2[0] - nmA), aB = exp2p(m2[1] - nmB);
            float sA = 0.f, sB = 0.f;
            #pragma unroll
            for (int j = 0; j < 16; j++) {
                sc[j][0] = exp2p(sc[j][0] - nmA);
                sc[j][1] = exp2p(sc[j][1] - nmA);
                sc[j][2] = exp2p(sc[j][2] - nmB);
                sc[j][3] = exp2p(sc[j][3] - nmB);
                sA += sc[j][0] + sc[j][1];
                sB += sc[j][2] + sc[j][3];
            }
            sA += __shfl_xor_sync(0xffffffffu, sA, 1);
            sA += __shfl_xor_sync(0xffffffffu, sA, 2);
            sB += __shfl_xor_sync(0xffffffffu, sB, 1);
            sB += __shfl_xor_sync(0xffffffffu, sB, 2);
            l2[0] = l2[0] * aA + sA;
            l2[1] = l2[1] * aB + sB;
            m2[0] = nmA; m2[1] = nmB;
            #pragma unroll
            for (int j = 0; j < 16; j++) {
                ov[j][0] *= aA; ov[j][1] *= aA;
                ov[j][2] *= aB; ov[j][3] *= aB;
            }
        }

        // ---- O += Ph·Vh + Pl·Vh ----
        #pragma unroll
        for (int kc = 0; kc < 8; kc++) {
            int j0 = 2 * kc;
            uint32_t ph[4], pl[4];
            #pragma unroll
            for (int u = 0; u < 2; u++) {
                #pragma unroll
                for (int t = 0; t < 2; t++) {
                    float e = sc[j0 + u][2 * t];
                    float o = sc[j0 + u][2 * t + 1];
                    uint32_t hp = packh(e, o);
                    __half2 h2 = *(__half2*)&hp;
                    ph[2 * u + t] = hp;
                    pl[2 * u + t] = packh(e - __low2float(h2), o - __high2float(h2));
                }
            }
            #pragma unroll
            for (int dt = 0; dt < 8; dt++) {
                uint32_t vh4[4];
                int row = kc * 16 + v_row;
                int dloc = (dt * 16) & 63;
                int ch = ((dloc >> 3) + (lane >> 4)) ^ (row & 7);
                uint32_t off = (uint32_t)(dt >> 2) * 16384u
                             + (uint32_t)(row * 128 + ch * 16);
                ldsm_x4_trans(vh4, vbs + off);
                int oj = 2 * dt;
                mma_f16(ov[oj],     ph, &vh4[0]);
                mma_f16(ov[oj + 1], ph, &vh4[2]);
                mma_f16(ov[oj],     pl, &vh4[0]);
                mma_f16(ov[oj + 1], pl, &vh4[2]);
            }
        }
    }

    // ---- epilogue: normalize and write o2 = [hi|lo] ----
    {
        float i0 = 1.f / l2[0], i1 = 1.f / l2[1];
        size_t rA = qrow0 + qlocA;
        __half* row0 = O2 + rA * (size_t)K2H + hcol;
        __half* row1 = O2 + (rA + 8) * (size_t)K2H + hcol;
        #pragma unroll
        for (int j = 0; j < 16; j++) {
            int c = 8 * j + 2 * (lane & 3);
            float e0 = ov[j][0] * i0, o0 = ov[j][1] * i0;
            float e1 = ov[j][2] * i1, o1 = ov[j][3] * i1;
            uint32_t h0 = packh(e0, o0);
            uint32_t h1 = packh(e1, o1);
            __half2 h20 = *(__half2*)&h0;
            __half2 h21 = *(__half2*)&h1;
            uint32_t l0 = packh(e0 - __low2float(h20), o0 - __high2float(h20));
            uint32_t l1 = packh(e1 - __low2float(h21), o1 - __high2float(h21));
            *(uint32_t*)(row0 + c)      = h0;
            *(uint32_t*)(row0 + HH + c) = l0;
            *(uint32_t*)(row1 + c)      = h1;
            *(uint32_t*)(row1 + HH + c) = l1;
        }
    }
}

// ---------------------------------------------------------------------------
// launch
// ---------------------------------------------------------------------------
extern "C" void kernel_launch(void* const* d_in, const int* in_sizes, int n_in,
                              void* d_out, int out_size)
{
    (void)in_sizes; (void)n_in; (void)out_size;
    const float* x      = (const float*)d_in[0];
    const float* wq     = (const float*)d_in[1];
    const float* bq     = (const float*)d_in[2];
    const float* wk_lat = (const float*)d_in[3];
    const float* wv_lat = (const float*)d_in[4];
    const float* wk     = (const float*)d_in[5];
    const float* wv     = (const float*)d_in[6];
    const float* wo     = (const float*)d_in[7];
    const float* bo     = (const float*)d_in[8];
    float* out = (float*)d_out;

    __half *qh, *ql, *kh, *vh;
    cudaGetSymbolAddress((void**)&qh, g_qh);
    cudaGetSymbolAddress((void**)&ql, g_ql);
    cudaGetSymbolAddress((void**)&kh, g_kh);
    cudaGetSymbolAddress((void**)&vh, g_vh);

    __half *x2, *o2, *klat2, *vlat2, *wq2, *wo2, *wklat2, *wvlat2, *wk2, *wv2;
    cudaGetSymbolAddress((void**)&x2,     g_x2);
    cudaGetSymbolAddress((void**)&o2,     g_o2);
    cudaGetSymbolAddress((void**)&klat2,  g_klat2);
    cudaGetSymbolAddress((void**)&vlat2,  g_vlat2);
    cudaGetSymbolAddress((void**)&wq2,    g_wq2);
    cudaGetSymbolAddress((void**)&wo2,    g_wo2);
    cudaGetSymbolAddress((void**)&wklat2, g_wklat2);
    cudaGetSymbolAddress((void**)&wvlat2, g_wvlat2);
    cudaGetSymbolAddress((void**)&wk2,    g_wk2);
    cudaGetSymbolAddress((void**)&wv2,    g_wv2);

    const int smem_gemm = 3 * 32768 + 1024;
    cudaFuncSetAttribute(proj_kernel,
                         cudaFuncAttributeMaxDynamicSharedMemorySize, smem_gemm);
    cudaFuncSetAttribute(kv_kernel,
                         cudaFuncAttributeMaxDynamicSharedMemorySize, smem_gemm);
    cudaFuncSetAttribute(wo_kernel,
                         cudaFuncAttributeMaxDynamicSharedMemorySize, smem_gemm);
    const int smem_attn = 6 * 32768 + 1024;   // Q planes + 2x(K,V)
    cudaFuncSetAttribute(mla_attn_tc_kernel,
                         cudaFuncAttributeMaxDynamicSharedMemorySize, smem_attn);

    // ---- input conversions (2 launches) ----
    {
        int tot = MM * HH / 2;
        split2_rows_kernel<<<(tot + 255) / 256, 256>>>(x, x2, MM, HH);
    }
    splitw_kernel<<<12288, dim3(32, 8)>>>(
        wq, wk_lat, wv_lat, wk, wv, wo,
        wq2, wklat2, wvlat2, wk2, wv2, wo2);

    // ---- merged projections: q + klat + vlat ----
    proj_kernel<<<768, 256, smem_gemm>>>(
        x2, wq2, wklat2, wvlat2, bq, qh, ql, klat2, vlat2);

    // ---- merged k + v ----
    kv_kernel<<<1024, 256, smem_gemm>>>(klat2, vlat2, wk2, wv2, kh, vh);

    // ---- attention (double-buffered K/V) ----
    mla_attn_tc_kernel<<<dim3(SS / 128, BB * NHH), 256, smem_attn>>>(
        qh, ql, kh, vh, o2);

    // ---- output projection ----
    wo_kernel<<<dim3(HH / 128, MM / 128), 256, smem_gemm>>>(o2, wo2, bo, out);
}

// round 8
// speedup vs baseline: 5.9928x; 1.2924x over previous
#include <cuda_runtime.h>
#include <cuda_fp16.h>
#include <math.h>
#include <stdint.h>
#include <string.h>

// Problem constants
#define BB   2
#define SS   2048
#define HH   2048
#define NHH  16
#define HDD  128
#define LDD  512
#define MM   (BB*SS)     // 4096
#define K2H  (2*HH)      // 4096
#define K2L  (2*LDD)     // 1024

#define QSCALE_C (0.08838834764831845f * 1.4426950408889634f)

// ---------------------------------------------------------------------------
// Scratch (static device globals — allocation-free)
// ---------------------------------------------------------------------------
__device__ __half g_qh[MM * (size_t)HH];
__device__ __half g_kh[MM * (size_t)HH];
__device__ __half g_vh[MM * (size_t)HH];
__device__ __half g_oh[MM * (size_t)HH];
__device__ __half g_x2[MM * (size_t)K2H];
__device__ __half g_klat2[MM * (size_t)K2L];
__device__ __half g_vlat2[MM * (size_t)K2L];
__device__ __half g_wq2[HH * (size_t)K2H];
__device__ __half g_woh[HH * (size_t)HH];      // wo hi-only, K = HH
__device__ __half g_wklat2[LDD * (size_t)K2H];
__device__ __half g_wvlat2[LDD * (size_t)K2H];
__device__ __half g_wk2[HH * (size_t)K2L];
__device__ __half g_wv2[HH * (size_t)K2L];

// ---------------------------------------------------------------------------
// PTX helpers (baseline-PTX only)
// ---------------------------------------------------------------------------
__device__ __forceinline__ uint32_t smem_u32(const void* p) {
    uint32_t a;
    asm("{ .reg .u64 t; cvta.to.shared.u64 t, %1; cvt.u32.u64 %0, t; }"
        : "=r"(a) : "l"(p));
    return a;
}
__device__ __forceinline__ void cp_async16(uint32_t s, const void* g) {
    asm volatile("cp.async.cg.shared.global [%0], [%1], 16;" :: "r"(s), "l"(g));
}
#define CP_COMMIT() asm volatile("cp.async.commit_group;" ::: "memory")
#define CP_WAIT0()  asm volatile("cp.async.wait_group 0;" ::: "memory")
#define CP_WAIT1()  asm volatile("cp.async.wait_group 1;" ::: "memory")
#define SWZ128(o) ((o) ^ (((o) >> 3) & 0x70))

__device__ __forceinline__ void ldsm_x4(uint32_t* r, uint32_t addr) {
    asm volatile("ldmatrix.sync.aligned.m8n8.x4.shared.b16 {%0,%1,%2,%3}, [%4];"
        : "=r"(r[0]), "=r"(r[1]), "=r"(r[2]), "=r"(r[3]) : "r"(addr));
}
__device__ __forceinline__ void ldsm_x4_trans(uint32_t* r, uint32_t addr) {
    asm volatile("ldmatrix.sync.aligned.m8n8.x4.trans.shared.b16 {%0,%1,%2,%3}, [%4];"
        : "=r"(r[0]), "=r"(r[1]), "=r"(r[2]), "=r"(r[3]) : "r"(addr));
}
__device__ __forceinline__ void mma_f16(float* d, const uint32_t* a,
                                        const uint32_t* b) {
    asm volatile(
        "mma.sync.aligned.m16n8k16.row.col.f32.f16.f16.f32 "
        "{%0,%1,%2,%3}, {%4,%5,%6,%7}, {%8,%9}, {%0,%1,%2,%3};"
        : "+f"(d[0]), "+f"(d[1]), "+f"(d[2]), "+f"(d[3])
        : "r"(a[0]), "r"(a[1]), "r"(a[2]), "r"(a[3]), "r"(b[0]), "r"(b[1]));
}
__device__ __forceinline__ uint32_t packh(float e, float o) {
    uint32_t r;
    asm("cvt.rn.f16x2.f32 %0, %1, %2;" : "=r"(r) : "f"(o), "f"(e));
    return r;
}
__device__ __forceinline__ float exp2p(float x) {
    x = fmaxf(x, -126.f);
    float n = rintf(x);
    float f = x - n;
    float p = 0.00015403530393381609f;
    p = fmaf(p, f, 0.0013333558146428443f);
    p = fmaf(p, f, 0.009618129107628477f);
    p = fmaf(p, f, 0.05550410866482158f);
    p = fmaf(p, f, 0.2402265069591007f);
    p = fmaf(p, f, 0.6931471805599453f);
    p = fmaf(p, f, 1.0f);
    return p * __int_as_float(((int)n + 127) << 23);
}

// ---------------------------------------------------------------------------
// GEMM core: 128x128 CTA tile, 128 threads = 4 warps (2x2), warp tile 64x64.
// BK=64, 3-stage cp.async. ldsm/MMA ratio 0.25.
// ---------------------------------------------------------------------------
__device__ __forceinline__ void load_tile(
    const __half* __restrict__ A, const __half* __restrict__ B,
    int Kp, int bm, int bn, int tid, uint32_t tbase, int kt, int stage)
{
    uint32_t abase = tbase + (uint32_t)stage * 32768u;
    uint32_t bbase = abase + 16384u;
    #pragma unroll
    for (int r = 0; r < 8; r++) {
        int idx = tid + 128 * r;          // 0..1023
        int row = idx >> 3;
        int c16 = idx & 7;
        uint32_t soff = SWZ128((uint32_t)(row * 128 + c16 * 16));
        cp_async16(abase + soff, A + (size_t)(bm + row) * Kp + kt * 64 + c16 * 8);
        cp_async16(bbase + soff, B + (size_t)(bn + row) * Kp + kt * 64 + c16 * 8);
    }
    CP_COMMIT();
}

__device__ __forceinline__ void gemm_core(
    const __half* __restrict__ A, const __half* __restrict__ B,
    int Kp, int bm, int bn, int tid, int wid, int lane, uint32_t tbase,
    float acc[4][8][4])
{
    const int wm = (wid & 1) * 64;
    const int wn = (wid >> 1) * 64;
    const int a_row   = wm + (lane & 15);
    const int a_chalf = lane >> 4;
    const int b_row   = wn + ((lane >> 4) << 3) + (lane & 7);
    const int b_chalf = (lane >> 3) & 1;

    const int niter = Kp / 64;
    load_tile(A, B, Kp, bm, bn, tid, tbase, 0, 0);
    load_tile(A, B, Kp, bm, bn, tid, tbase, 1, 1);

    int cs = 0, ls = 2;
    for (int it = 0; it < niter; it++) {
        CP_WAIT1();
        __syncthreads();
        if (it + 2 < niter) {
            load_tile(A, B, Kp, bm, bn, tid, tbase, it + 2, ls);
            ls = (ls == 2) ? 0 : ls + 1;
        }
        const uint32_t a_s = tbase + (uint32_t)cs * 32768u;
        const uint32_t b_s = a_s + 16384u;
        cs = (cs == 2) ? 0 : cs + 1;

        #pragma unroll
        for (int s = 0; s < 4; s++) {
            uint32_t af[4][4];
            #pragma unroll
            for (int mt = 0; mt < 4; mt++) {
                int row = a_row + mt * 16;
                int ch  = (2 * s + a_chalf) ^ (row & 7);
                ldsm_x4(af[mt], a_s + (uint32_t)(row * 128 + ch * 16));
            }
            uint32_t bf[4][4];
            #pragma unroll
            for (int nt = 0; nt < 4; nt++) {
                int row = b_row + nt * 16;
                int ch  = (2 * s + b_chalf) ^ (row & 7);
                ldsm_x4(bf[nt], b_s + (uint32_t)(row * 128 + ch * 16));
            }
            #pragma unroll
            for (int mt = 0; mt < 4; mt++)
                #pragma unroll
                for (int n8 = 0; n8 < 8; n8++)
                    mma_f16(acc[mt][n8], af[mt], &bf[n8 >> 1][(n8 & 1) * 2]);
        }
    }
}

#define ACC_INIT(acc) do { \
    _Pragma("unroll") \
    for (int mt = 0; mt < 4; mt++) \
        _Pragma("unroll") \
        for (int n8 = 0; n8 < 8; n8++) \
            _Pragma("unroll") \
            for (int j = 0; j < 4; j++) (acc)[mt][n8][j] = 0.f; \
} while (0)

// ---------------------------------------------------------------------------
// Merged projection kernel: q (hi plane, scaled) + klat/vlat ([hi|lo] concat).
// 768 tiles: [0,512) q, [512,640) klat, [640,768) vlat. Kp = K2H.
// ---------------------------------------------------------------------------
__global__ void __launch_bounds__(128, 2) proj_kernel(
    const __half* __restrict__ x2,
    const __half* __restrict__ wq2,
    const __half* __restrict__ wklat2,
    const __half* __restrict__ wvlat2,
    const float* __restrict__ bq,
    __half* __restrict__ qh,
    __half* __restrict__ klat2, __half* __restrict__ vlat2)
{
    extern __shared__ char dsm[];
    const uint32_t tbase = (smem_u32(dsm) + 1023u) & ~1023u;
    const int tid  = threadIdx.x;
    const int wid  = tid >> 5;
    const int lane = tid & 31;

    const __half* B;
    __half* o2c = nullptr;
    int N, mode, bm, bn;
    const int bid = blockIdx.x;
    if (bid < 512) {
        B = wq2; N = 2048; mode = 1;
        bm = (bid >> 4) * 128; bn = (bid & 15) * 128;
    } else {
        int t = bid - 512;
        if (t < 128) { B = wklat2; o2c = klat2; }
        else         { B = wvlat2; o2c = vlat2; t -= 128; }
        N = 512; mode = 2;
        bm = (t >> 2) * 128; bn = (t & 3) * 128;
    }

    float acc[4][8][4];
    ACC_INIT(acc);
    gemm_core(x2, B, K2H, bm, bn, tid, wid, lane, tbase, acc);

    const int wm = (wid & 1) * 64;
    const int wn = (wid >> 1) * 64;
    #pragma unroll
    for (int mt = 0; mt < 4; mt++) {
        const int r0 = bm + wm + mt * 16 + (lane >> 2);
        #pragma unroll
        for (int n8 = 0; n8 < 8; n8++) {
            const int c0 = bn + wn + n8 * 8 + (lane & 3) * 2;
            float2 v0 = make_float2(acc[mt][n8][0], acc[mt][n8][1]);
            float2 v1 = make_float2(acc[mt][n8][2], acc[mt][n8][3]);
            if (mode == 1) {
                float b0 = bq[c0], b1 = bq[c0 + 1];
                v0.x = (v0.x + b0) * QSCALE_C; v0.y = (v0.y + b1) * QSCALE_C;
                v1.x = (v1.x + b0) * QSCALE_C; v1.y = (v1.y + b1) * QSCALE_C;
                *(uint32_t*)(qh + (size_t)r0 * N + c0)       = packh(v0.x, v0.y);
                *(uint32_t*)(qh + (size_t)(r0 + 8) * N + c0) = packh(v1.x, v1.y);
            } else {
                uint32_t h0 = packh(v0.x, v0.y);
                uint32_t h1 = packh(v1.x, v1.y);
                __half2 h20 = *(__half2*)&h0;
                __half2 h21 = *(__half2*)&h1;
                uint32_t l0 = packh(v0.x - __low2float(h20), v0.y - __high2float(h20));
                uint32_t l1 = packh(v1.x - __low2float(h21), v1.y - __high2float(h21));
                __half* row0 = o2c + (size_t)r0 * (2 * N);
                __half* row1 = o2c + (size_t)(r0 + 8) * (2 * N);
                *(uint32_t*)(row0 + c0)     = h0;
                *(uint32_t*)(row0 + N + c0) = l0;
                *(uint32_t*)(row1 + c0)     = h1;
                *(uint32_t*)(row1 + N + c0) = l1;
            }
        }
    }
}

// ---------------------------------------------------------------------------
// Merged k+v kernel: [0,512) k, [512,1024) v. Kp = K2L, hi plane out.
// ---------------------------------------------------------------------------
__global__ void __launch_bounds__(128, 2) kv_kernel(
    const __half* __restrict__ klat2, const __half* __restrict__ vlat2,
    const __half* __restrict__ wk2,   const __half* __restrict__ wv2,
    __half* __restrict__ kh, __half* __restrict__ vh)
{
    extern __shared__ char dsm[];
    const uint32_t tbase = (smem_u32(dsm) + 1023u) & ~1023u;
    const int tid  = threadIdx.x;
    const int wid  = tid >> 5;
    const int lane = tid & 31;

    const __half *A, *B;
    __half* O;
    int t = blockIdx.x;
    if (t < 512) { A = klat2; B = wk2; O = kh; }
    else         { A = vlat2; B = wv2; O = vh; t -= 512; }
    const int bm = (t >> 4) * 128;
    const int bn = (t & 15) * 128;
    const int N = 2048;

    float acc[4][8][4];
    ACC_INIT(acc);
    gemm_core(A, B, K2L, bm, bn, tid, wid, lane, tbase, acc);

    const int wm = (wid & 1) * 64;
    const int wn = (wid >> 1) * 64;
    #pragma unroll
    for (int mt = 0; mt < 4; mt++) {
        const int r0 = bm + wm + mt * 16 + (lane >> 2);
        #pragma unroll
        for (int n8 = 0; n8 < 8; n8++) {
            const int c0 = bn + wn + n8 * 8 + (lane & 3) * 2;
            *(uint32_t*)(O + (size_t)r0 * N + c0)       = packh(acc[mt][n8][0], acc[mt][n8][1]);
            *(uint32_t*)(O + (size_t)(r0 + 8) * N + c0) = packh(acc[mt][n8][2], acc[mt][n8][3]);
        }
    }
}

// ---------------------------------------------------------------------------
// Output projection: out = oh @ woh^T + bo (fp32 out), Kp = HH (single term)
// ---------------------------------------------------------------------------
__global__ void __launch_bounds__(128, 2) wo_kernel(
    const __half* __restrict__ oh, const __half* __restrict__ woh,
    const float* __restrict__ bo, float* __restrict__ C)
{
    extern __shared__ char dsm[];
    const uint32_t tbase = (smem_u32(dsm) + 1023u) & ~1023u;
    const int tid  = threadIdx.x;
    const int wid  = tid >> 5;
    const int lane = tid & 31;
    const int bm = blockIdx.y * 128;
    const int bn = blockIdx.x * 128;
    const int N = 2048;

    float acc[4][8][4];
    ACC_INIT(acc);
    gemm_core(oh, woh, HH, bm, bn, tid, wid, lane, tbase, acc);

    const int wm = (wid & 1) * 64;
    const int wn = (wid >> 1) * 64;
    #pragma unroll
    for (int mt = 0; mt < 4; mt++) {
        const int r0 = bm + wm + mt * 16 + (lane >> 2);
        #pragma unroll
        for (int n8 = 0; n8 < 8; n8++) {
            const int c0 = bn + wn + n8 * 8 + (lane & 3) * 2;
            float b0 = bo[c0], b1 = bo[c0 + 1];
            float2 v0 = make_float2(acc[mt][n8][0] + b0, acc[mt][n8][1] + b1);
            float2 v1 = make_float2(acc[mt][n8][2] + b0, acc[mt][n8][3] + b1);
            *(float2*)(C + (size_t)r0 * N + c0)       = v0;
            *(float2*)(C + (size_t)(r0 + 8) * N + c0) = v1;
        }
    }
}

// ---------------------------------------------------------------------------
// Input conversions
// ---------------------------------------------------------------------------
__global__ void split2_rows_kernel(const float* __restrict__ in,
                                   __half* __restrict__ out, int R, int C)
{
    int i2 = blockIdx.x * blockDim.x + threadIdx.x;
    int total = R * (C >> 1);
    if (i2 >= total) return;
    int c2 = C >> 1;
    int r = i2 / c2, p = i2 - r * c2;
    float2 v = ((const float2*)in)[i2];
    __half2 h = __floats2half2_rn(v.x, v.y);
    __half2 l = __floats2half2_rn(v.x - __low2float(h), v.y - __high2float(h));
    __half2* ob = (__half2*)(out + (size_t)r * 2 * C);
    ob[p]      = h;
    ob[c2 + p] = l;
}

// merged weight split. Most weights -> [N, 2K] = [hi|hi]; wo -> [N, K] hi once.
__global__ void splitw_kernel(
    const float* __restrict__ wq, const float* __restrict__ wklat,
    const float* __restrict__ wvlat, const float* __restrict__ wk,
    const float* __restrict__ wv, const float* __restrict__ wo,
    __half* __restrict__ wq2, __half* __restrict__ wklat2,
    __half* __restrict__ wvlat2, __half* __restrict__ wk2,
    __half* __restrict__ wv2, __half* __restrict__ woh)
{
    __shared__ float t[32][33];
    int l = blockIdx.x;
    const float* in; __half* out; int K, N, tt, dup = 1;
    if (l < 4096)      { in = wq;    out = wq2;    K = 2048; N = 2048; tt = l; }
    else if (l < 5120) { in = wklat; out = wklat2; K = 2048; N = 512;  tt = l - 4096; }
    else if (l < 6144) { in = wvlat; out = wvlat2; K = 2048; N = 512;  tt = l - 5120; }
    else if (l < 7168) { in = wk;    out = wk2;    K = 512;  N = 2048; tt = l - 6144; }
    else if (l < 8192) { in = wv;    out = wv2;    K = 512;  N = 2048; tt = l - 7168; }
    else               { in = wo;    out = woh;    K = 2048; N = 2048; tt = l - 8192; dup = 0; }
    int nnb = N >> 5;
    int k0 = (tt / nnb) * 32, n0 = (tt % nnb) * 32;
    int tx = threadIdx.x, ty = threadIdx.y;
    #pragma unroll
    for (int i = 0; i < 32; i += 8)
        t[ty + i][tx] = in[(size_t)(k0 + ty + i) * N + n0 + tx];
    __syncthreads();
    #pragma unroll
    for (int i = 0; i < 32; i += 8) {
        int n = ty + i;
        __half h = __float2half_rn(t[tx][n]);
        if (dup) {
            size_t base = (size_t)(n0 + n) * 2 * K;
            out[base + k0 + tx]     = h;
            out[base + K + k0 + tx] = h;
        } else {
            out[(size_t)(n0 + n) * K + k0 + tx] = h;
        }
    }
}

// ---------------------------------------------------------------------------
// Tensor-core flash attention (causal), fp16 single-term QK / PV,
// K/V double-buffered. smem: Qh + 2x(Kh,Vh) = 160KB. 256 thr = 8 warps.
// ---------------------------------------------------------------------------
#define SM_QH 0u
#define SM_KB(b) (32768u + (uint32_t)(b) * 65536u)
#define SM_VB(b) (65536u + (uint32_t)(b) * 65536u)

__global__ void __launch_bounds__(256) mla_attn_tc_kernel(
    const __half* __restrict__ Qh,
    const __half* __restrict__ Kh, const __half* __restrict__ Vh,
    __half* __restrict__ Oh)
{
    extern __shared__ char dsm[];
    const uint32_t sb = (smem_u32(dsm) + 1023u) & ~1023u;

    const int tid  = threadIdx.x;
    const int lane = tid & 31;
    const int w    = tid >> 5;
    const int bh   = blockIdx.y;
    const int b    = bh >> 4;
    const int h    = bh & 15;
    const int qt   = gridDim.x - 1 - blockIdx.x;   // heavy tiles first

    const size_t qrow0 = (size_t)b * SS + (size_t)qt * 128;
    const size_t hcol  = (size_t)h * HDD;

    // prologue: Q + KV tile 0 (buffer 0)
    #pragma unroll
    for (int i = 0; i < 8; i++) {
        int idx = tid + 256 * i;
        int r   = idx >> 4;
        int d   = (idx & 15) * 8;
        uint32_t off = (uint32_t)(d >> 6) * 16384u
                     + SWZ128((uint32_t)(r * 128 + (d & 63) * 2));
        cp_async16(sb + SM_QH + off, Qh + (qrow0 + r) * HH + hcol + d);
        const size_t ksrc = ((size_t)b * SS + r) * HH + hcol + d;
        cp_async16(sb + SM_KB(0) + off, Kh + ksrc);
        cp_async16(sb + SM_VB(0) + off, Vh + ksrc);
    }
    CP_COMMIT();

    float m2[2] = {-1e30f, -1e30f};
    float l2[2] = {0.f, 0.f};
    float ov[16][4];
    #pragma unroll
    for (int j = 0; j < 16; j++)
        ov[j][0] = ov[j][1] = ov[j][2] = ov[j][3] = 0.f;

    const int a_row  = 16 * w + (lane & 15);
    const int a_ch   = lane >> 4;
    const int b_rowb = ((lane >> 4) << 3) + (lane & 7);
    const int b_ch   = (lane >> 3) & 1;
    const int v_row  = (lane & 7) + ((lane >> 3) & 1) * 8;
    const int qlocA  = 16 * w + (lane >> 2);

    for (int kt = 0; kt <= qt; kt++) {
        CP_WAIT0();
        __syncthreads();

        if (kt < qt) {
            const size_t krow1 = (size_t)b * SS + (size_t)(kt + 1) * 128;
            const uint32_t kb1 = SM_KB((kt + 1) & 1);
            const uint32_t vb1 = SM_VB((kt + 1) & 1);
            #pragma unroll
            for (int i = 0; i < 8; i++) {
                int idx = tid + 256 * i;
                int r   = idx >> 4;
                int d   = (idx & 15) * 8;
                uint32_t off = (uint32_t)(d >> 6) * 16384u
                             + SWZ128((uint32_t)(r * 128 + (d & 63) * 2));
                const size_t src = (krow1 + r) * HH + hcol + d;
                cp_async16(sb + kb1 + off, Kh + src);
                cp_async16(sb + vb1 + off, Vh + src);
            }
            CP_COMMIT();
        }

        const uint32_t kbs = sb + SM_KB(kt & 1);
        const uint32_t vbs = sb + SM_VB(kt & 1);

        // ---- scores: S = Qh·Kh^T ----
        float sc[16][4];
        #pragma unroll
        for (int j = 0; j < 16; j++)
            sc[j][0] = sc[j][1] = sc[j][2] = sc[j][3] = 0.f;

        #pragma unroll
        for (int kc = 0; kc < 8; kc++) {
            uint32_t ah[4];
            {
                int ch = (2 * (kc & 3) + a_ch) ^ (a_row & 7);
                uint32_t off = (uint32_t)(kc >> 2) * 16384u
                             + (uint32_t)(a_row * 128 + ch * 16);
                ldsm_x4(ah, sb + SM_QH + off);
            }
            #pragma unroll
            for (int half = 0; half < 2; half++) {
                uint32_t bh4[4][4];
                #pragma unroll
                for (int nt4 = 0; nt4 < 4; nt4++) {
                    int row = (half * 4 + nt4) * 16 + b_rowb;
                    int ch = (2 * (kc & 3) + b_ch) ^ (row & 7);
                    uint32_t off = (uint32_t)(kc >> 2) * 16384u
                                 + (uint32_t)(row * 128 + ch * 16);
                    ldsm_x4(bh4[nt4], kbs + off);
                }
                #pragma unroll
                for (int nt4 = 0; nt4 < 4; nt4++) {
                    int j0 = (half * 4 + nt4) * 2;
                    mma_f16(sc[j0],     ah, &bh4[nt4][0]);
                    mma_f16(sc[j0 + 1], ah, &bh4[nt4][2]);
                }
            }
        }

        // ---- causal mask (diagonal tile only) ----
        if (kt == qt) {
            #pragma unroll
            for (int j = 0; j < 16; j++) {
                int kkb = 8 * j + 2 * (lane & 3);
                #pragma unroll
                for (int c = 0; c < 2; c++) {
                    if (kkb + c > qlocA)     sc[j][c]     = -1e30f;
                    if (kkb + c > qlocA + 8) sc[j][2 + c] = -1e30f;
                }
            }
        }

        // ---- online softmax (base-2 domain) ----
        {
            float mA = -1e30f, mB = -1e30f;
            #pragma unroll
            for (int j = 0; j < 16; j++) {
                mA = fmaxf(mA, fmaxf(sc[j][0], sc[j][1]));
                mB = fmaxf(mB, fmaxf(sc[j][2], sc[j][3]));
            }
            mA = fmaxf(mA, __shfl_xor_sync(0xffffffffu, mA, 1));
            mA = fmaxf(mA, __shfl_xor_sync(0xffffffffu, mA, 2));
            mB = fmaxf(mB, __shfl_xor_sync(0xffffffffu, mB, 1));
            mB = fmaxf(mB, __shfl_xor_sync(0xffffffffu, mB, 2));
            float nmA = fmaxf(m2[0], mA), nmB = fmaxf(m2[1], mB);
            float aA = exp2p(m2[0] - nmA), aB = exp2p(m2[1] - nmB);
            float sA = 0.f, sB = 0.f;
            #pragma unroll
            for (int j = 0; j < 16; j++) {
                sc[j][0] = exp2p(sc[j][0] - nmA);
                sc[j][1] = exp2p(sc[j][1] - nmA);
                sc[j][2] = exp2p(sc[j][2] - nmB);
                sc[j][3] = exp2p(sc[j][3] - nmB);
                sA += sc[j][0] + sc[j][1];
                sB += sc[j][2] + sc[j][3];
            }
            sA += __shfl_xor_sync(0xffffffffu, sA, 1);
            sA += __shfl_xor_sync(0xffffffffu, sA, 2);
            sB += __shfl_xor_sync(0xffffffffu, sB, 1);
            sB += __shfl_xor_sync(0xffffffffu, sB, 2);
            l2[0] = l2[0] * aA + sA;
            l2[1] = l2[1] * aB + sB;
            m2[0] = nmA; m2[1] = nmB;
            #pragma unroll
            for (int j = 0; j < 16; j++) {
                ov[j][0] *= aA; ov[j][1] *= aA;
                ov[j][2] *= aB; ov[j][3] *= aB;
            }
        }

        // ---- O += Ph·Vh ----
        #pragma unroll
        for (int kc = 0; kc < 8; kc++) {
            int j0 = 2 * kc;
            uint32_t ph[4];
            #pragma unroll
            for (int u = 0; u < 2; u++)
                #pragma unroll
                for (int t = 0; t < 2; t++)
                    ph[2 * u + t] = packh(sc[j0 + u][2 * t], sc[j0 + u][2 * t + 1]);
            #pragma unroll
            for (int dt = 0; dt < 8; dt++) {
                uint32_t vh4[4];
                int row = kc * 16 + v_row;
                int dloc = (dt * 16) & 63;
                int ch = ((dloc >> 3) + (lane >> 4)) ^ (row & 7);
                uint32_t off = (uint32_t)(dt >> 2) * 16384u
                             + (uint32_t)(row * 128 + ch * 16);
                ldsm_x4_trans(vh4, vbs + off);
                int oj = 2 * dt;
                mma_f16(ov[oj],     ph, &vh4[0]);
                mma_f16(ov[oj + 1], ph, &vh4[2]);
            }
        }
    }

    // ---- epilogue: normalize and write oh (hi only) ----
    {
        float i0 = 1.f / l2[0], i1 = 1.f / l2[1];
        size_t rA = qrow0 + qlocA;
        __half* row0 = Oh + rA * (size_t)HH + hcol;
        __half* row1 = Oh + (rA + 8) * (size_t)HH + hcol;
        #pragma unroll
        for (int j = 0; j < 16; j++) {
            int c = 8 * j + 2 * (lane & 3);
            *(uint32_t*)(row0 + c) = packh(ov[j][0] * i0, ov[j][1] * i0);
            *(uint32_t*)(row1 + c) = packh(ov[j][2] * i1, ov[j][3] * i1);
        }
    }
}

// ---------------------------------------------------------------------------
// launch
// ---------------------------------------------------------------------------
extern "C" void kernel_launch(void* const* d_in, const int* in_sizes, int n_in,
                              void* d_out, int out_size)
{
    (void)in_sizes; (void)n_in; (void)out_size;
    const float* x      = (const float*)d_in[0];
    const float* wq     = (const float*)d_in[1];
    const float* bq     = (const float*)d_in[2];
    const float* wk_lat = (const float*)d_in[3];
    const float* wv_lat = (const float*)d_in[4];
    const float* wk     = (const float*)d_in[5];
    const float* wv     = (const float*)d_in[6];
    const float* wo     = (const float*)d_in[7];
    const float* bo     = (const float*)d_in[8];
    float* out = (float*)d_out;

    __half *qh, *kh, *vh, *oh;
    cudaGetSymbolAddress((void**)&qh, g_qh);
    cudaGetSymbolAddress((void**)&kh, g_kh);
    cudaGetSymbolAddress((void**)&vh, g_vh);
    cudaGetSymbolAddress((void**)&oh, g_oh);

    __half *x2, *klat2, *vlat2, *wq2, *woh, *wklat2, *wvlat2, *wk2, *wv2;
    cudaGetSymbolAddress((void**)&x2,     g_x2);
    cudaGetSymbolAddress((void**)&klat2,  g_klat2);
    cudaGetSymbolAddress((void**)&vlat2,  g_vlat2);
    cudaGetSymbolAddress((void**)&wq2,    g_wq2);
    cudaGetSymbolAddress((void**)&woh,    g_woh);
    cudaGetSymbolAddress((void**)&wklat2, g_wklat2);
    cudaGetSymbolAddress((void**)&wvlat2, g_wvlat2);
    cudaGetSymbolAddress((void**)&wk2,    g_wk2);
    cudaGetSymbolAddress((void**)&wv2,    g_wv2);

    const int smem_gemm = 3 * 32768 + 1024;
    cudaFuncSetAttribute(proj_kernel,
                         cudaFuncAttributeMaxDynamicSharedMemorySize, smem_gemm);
    cudaFuncSetAttribute(kv_kernel,
                         cudaFuncAttributeMaxDynamicSharedMemorySize, smem_gemm);
    cudaFuncSetAttribute(wo_kernel,
                         cudaFuncAttributeMaxDynamicSharedMemorySize, smem_gemm);
    const int smem_attn = 5 * 32768 + 1024;   // Qh + 2x(K,V)
    cudaFuncSetAttribute(mla_attn_tc_kernel,
                         cudaFuncAttributeMaxDynamicSharedMemorySize, smem_attn);

    // ---- input conversions ----
    {
        int tot = MM * HH / 2;
        split2_rows_kernel<<<(tot + 255) / 256, 256>>>(x, x2, MM, HH);
    }
    splitw_kernel<<<12288, dim3(32, 8)>>>(
        wq, wk_lat, wv_lat, wk, wv, wo,
        wq2, wklat2, wvlat2, wk2, wv2, woh);

    // ---- merged projections: q + klat + vlat ----
    proj_kernel<<<768, 128, smem_gemm>>>(
        x2, wq2, wklat2, wvlat2, bq, qh, klat2, vlat2);

    // ---- merged k + v ----
    kv_kernel<<<1024, 128, smem_gemm>>>(klat2, vlat2, wk2, wv2, kh, vh);

    // ---- attention ----
    mla_attn_tc_kernel<<<dim3(SS / 128, BB * NHH), 256, smem_attn>>>(
        qh, kh, vh, oh);

    // ---- output projection (K = 2048, single term) ----
    wo_kernel<<<dim3(HH / 128, MM / 128), 128, smem_gemm>>>(oh, woh, bo, out);
}

// round 9
// speedup vs baseline: 7.4784x; 1.2479x over previous
#include <cuda_runtime.h>
#include <cuda_fp16.h>
#include <math.h>
#include <stdint.h>
#include <string.h>

// Problem constants
#define BB   2
#define SS   2048
#define HH   2048
#define NHH  16
#define HDD  128
#define LDD  512
#define MM   (BB*SS)     // 4096
#define K2L  (2*LDD)     // 1024

#define QSCALE_C (0.08838834764831845f * 1.4426950408889634f)

// ---------------------------------------------------------------------------
// Scratch (static device globals — allocation-free)
// ---------------------------------------------------------------------------
__device__ __half g_qh[MM * (size_t)HH];
__device__ __half g_kh[MM * (size_t)HH];
__device__ __half g_vh[MM * (size_t)HH];
__device__ __half g_oh[MM * (size_t)HH];
__device__ __half g_xh[MM * (size_t)HH];          // x hi plane only
__device__ __half g_klat2[MM * (size_t)K2L];      // [hi|lo] concat
__device__ __half g_vlat2[MM * (size_t)K2L];
__device__ __half g_wqh[HH * (size_t)HH];         // single-plane weights
__device__ __half g_woh[HH * (size_t)HH];
__device__ __half g_wklath[LDD * (size_t)HH];
__device__ __half g_wvlath[LDD * (size_t)HH];
__device__ __half g_wk2[HH * (size_t)K2L];        // [hi|hi] dup (pairs klat lo)
__device__ __half g_wv2[HH * (size_t)K2L];

// ---------------------------------------------------------------------------
// PTX helpers (baseline-PTX only)
// ---------------------------------------------------------------------------
__device__ __forceinline__ uint32_t smem_u32(const void* p) {
    uint32_t a;
    asm("{ .reg .u64 t; cvta.to.shared.u64 t, %1; cvt.u32.u64 %0, t; }"
        : "=r"(a) : "l"(p));
    return a;
}
__device__ __forceinline__ void cp_async16(uint32_t s, const void* g) {
    asm volatile("cp.async.cg.shared.global [%0], [%1], 16;" :: "r"(s), "l"(g));
}
#define CP_COMMIT() asm volatile("cp.async.commit_group;" ::: "memory")
#define CP_WAIT0()  asm volatile("cp.async.wait_group 0;" ::: "memory")
#define CP_WAIT1()  asm volatile("cp.async.wait_group 1;" ::: "memory")
#define SWZ128(o) ((o) ^ (((o) >> 3) & 0x70))

__device__ __forceinline__ void ldsm_x4(uint32_t* r, uint32_t addr) {
    asm volatile("ldmatrix.sync.aligned.m8n8.x4.shared.b16 {%0,%1,%2,%3}, [%4];"
        : "=r"(r[0]), "=r"(r[1]), "=r"(r[2]), "=r"(r[3]) : "r"(addr));
}
__device__ __forceinline__ void ldsm_x4_trans(uint32_t* r, uint32_t addr) {
    asm volatile("ldmatrix.sync.aligned.m8n8.x4.trans.shared.b16 {%0,%1,%2,%3}, [%4];"
        : "=r"(r[0]), "=r"(r[1]), "=r"(r[2]), "=r"(r[3]) : "r"(addr));
}
__device__ __forceinline__ void mma_f16(float* d, const uint32_t* a,
                                        const uint32_t* b) {
    asm volatile(
        "mma.sync.aligned.m16n8k16.row.col.f32.f16.f16.f32 "
        "{%0,%1,%2,%3}, {%4,%5,%6,%7}, {%8,%9}, {%0,%1,%2,%3};"
        : "+f"(d[0]), "+f"(d[1]), "+f"(d[2]), "+f"(d[3])
        : "r"(a[0]), "r"(a[1]), "r"(a[2]), "r"(a[3]), "r"(b[0]), "r"(b[1]));
}
__device__ __forceinline__ uint32_t packh(float e, float o) {
    uint32_t r;
    asm("cvt.rn.f16x2.f32 %0, %1, %2;" : "=r"(r) : "f"(o), "f"(e));
    return r;
}
__device__ __forceinline__ float exp2p(float x) {
    x = fmaxf(x, -126.f);
    float n = rintf(x);
    float f = x - n;
    float p = 0.00015403530393381609f;
    p = fmaf(p, f, 0.0013333558146428443f);
    p = fmaf(p, f, 0.009618129107628477f);
    p = fmaf(p, f, 0.05550410866482158f);
    p = fmaf(p, f, 0.2402265069591007f);
    p = fmaf(p, f, 0.6931471805599453f);
    p = fmaf(p, f, 1.0f);
    return p * __int_as_float(((int)n + 127) << 23);
}

// ---------------------------------------------------------------------------
// GEMM core: 128x128 CTA tile, 128 threads = 4 warps (2x2), warp tile 64x64.
// BK=64, 3-stage cp.async.
// ---------------------------------------------------------------------------
__device__ __forceinline__ void load_tile(
    const __half* __restrict__ A, const __half* __restrict__ B,
    int Kp, int bm, int bn, int tid, uint32_t tbase, int kt, int stage)
{
    uint32_t abase = tbase + (uint32_t)stage * 32768u;
    uint32_t bbase = abase + 16384u;
    #pragma unroll
    for (int r = 0; r < 8; r++) {
        int idx = tid + 128 * r;          // 0..1023
        int row = idx >> 3;
        int c16 = idx & 7;
        uint32_t soff = SWZ128((uint32_t)(row * 128 + c16 * 16));
        cp_async16(abase + soff, A + (size_t)(bm + row) * Kp + kt * 64 + c16 * 8);
        cp_async16(bbase + soff, B + (size_t)(bn + row) * Kp + kt * 64 + c16 * 8);
    }
    CP_COMMIT();
}

__device__ __forceinline__ void gemm_core(
    const __half* __restrict__ A, const __half* __restrict__ B,
    int Kp, int bm, int bn, int tid, int wid, int lane, uint32_t tbase,
    float acc[4][8][4])
{
    const int wm = (wid & 1) * 64;
    const int wn = (wid >> 1) * 64;
    const int a_row   = wm + (lane & 15);
    const int a_chalf = lane >> 4;
    const int b_row   = wn + ((lane >> 4) << 3) + (lane & 7);
    const int b_chalf = (lane >> 3) & 1;

    const int niter = Kp / 64;
    load_tile(A, B, Kp, bm, bn, tid, tbase, 0, 0);
    load_tile(A, B, Kp, bm, bn, tid, tbase, 1, 1);

    int cs = 0, ls = 2;
    for (int it = 0; it < niter; it++) {
        CP_WAIT1();
        __syncthreads();
        if (it + 2 < niter) {
            load_tile(A, B, Kp, bm, bn, tid, tbase, it + 2, ls);
            ls = (ls == 2) ? 0 : ls + 1;
        }
        const uint32_t a_s = tbase + (uint32_t)cs * 32768u;
        const uint32_t b_s = a_s + 16384u;
        cs = (cs == 2) ? 0 : cs + 1;

        #pragma unroll
        for (int s = 0; s < 4; s++) {
            uint32_t af[4][4];
            #pragma unroll
            for (int mt = 0; mt < 4; mt++) {
                int row = a_row + mt * 16;
                int ch  = (2 * s + a_chalf) ^ (row & 7);
                ldsm_x4(af[mt], a_s + (uint32_t)(row * 128 + ch * 16));
            }
            uint32_t bf[4][4];
            #pragma unroll
            for (int nt = 0; nt < 4; nt++) {
                int row = b_row + nt * 16;
                int ch  = (2 * s + b_chalf) ^ (row & 7);
                ldsm_x4(bf[nt], b_s + (uint32_t)(row * 128 + ch * 16));
            }
            #pragma unroll
            for (int mt = 0; mt < 4; mt++)
                #pragma unroll
                for (int n8 = 0; n8 < 8; n8++)
                    mma_f16(acc[mt][n8], af[mt], &bf[n8 >> 1][(n8 & 1) * 2]);
        }
    }
}

#define ACC_INIT(acc) do { \
    _Pragma("unroll") \
    for (int mt = 0; mt < 4; mt++) \
        _Pragma("unroll") \
        for (int n8 = 0; n8 < 8; n8++) \
            _Pragma("unroll") \
            for (int j = 0; j < 4; j++) (acc)[mt][n8][j] = 0.f; \
} while (0)

// ---------------------------------------------------------------------------
// Merged projection kernel: q (hi plane, scaled) + klat/vlat ([hi|lo] concat).
// 768 tiles: [0,512) q, [512,640) klat, [640,768) vlat. Kp = HH (single term).
// ---------------------------------------------------------------------------
__global__ void __launch_bounds__(128, 2) proj_kernel(
    const __half* __restrict__ xh,
    const __half* __restrict__ wqh,
    const __half* __restrict__ wklath,
    const __half* __restrict__ wvlath,
    const float* __restrict__ bq,
    __half* __restrict__ qh,
    __half* __restrict__ klat2, __half* __restrict__ vlat2)
{
    extern __shared__ char dsm[];
    const uint32_t tbase = (smem_u32(dsm) + 1023u) & ~1023u;
    const int tid  = threadIdx.x;
    const int wid  = tid >> 5;
    const int lane = tid & 31;

    const __half* B;
    __half* o2c = nullptr;
    int N, mode, bm, bn;
    const int bid = blockIdx.x;
    if (bid < 512) {
        B = wqh; N = 2048; mode = 1;
        bm = (bid >> 4) * 128; bn = (bid & 15) * 128;
    } else {
        int t = bid - 512;
        if (t < 128) { B = wklath; o2c = klat2; }
        else         { B = wvlath; o2c = vlat2; t -= 128; }
        N = 512; mode = 2;
        bm = (t >> 2) * 128; bn = (t & 3) * 128;
    }

    float acc[4][8][4];
    ACC_INIT(acc);
    gemm_core(xh, B, HH, bm, bn, tid, wid, lane, tbase, acc);

    const int wm = (wid & 1) * 64;
    const int wn = (wid >> 1) * 64;
    #pragma unroll
    for (int mt = 0; mt < 4; mt++) {
        const int r0 = bm + wm + mt * 16 + (lane >> 2);
        #pragma unroll
        for (int n8 = 0; n8 < 8; n8++) {
            const int c0 = bn + wn + n8 * 8 + (lane & 3) * 2;
            float2 v0 = make_float2(acc[mt][n8][0], acc[mt][n8][1]);
            float2 v1 = make_float2(acc[mt][n8][2], acc[mt][n8][3]);
            if (mode == 1) {
                float b0 = bq[c0], b1 = bq[c0 + 1];
                v0.x = (v0.x + b0) * QSCALE_C; v0.y = (v0.y + b1) * QSCALE_C;
                v1.x = (v1.x + b0) * QSCALE_C; v1.y = (v1.y + b1) * QSCALE_C;
                *(uint32_t*)(qh + (size_t)r0 * N + c0)       = packh(v0.x, v0.y);
                *(uint32_t*)(qh + (size_t)(r0 + 8) * N + c0) = packh(v1.x, v1.y);
            } else {
                uint32_t h0 = packh(v0.x, v0.y);
                uint32_t h1 = packh(v1.x, v1.y);
                __half2 h20 = *(__half2*)&h0;
                __half2 h21 = *(__half2*)&h1;
                uint32_t l0 = packh(v0.x - __low2float(h20), v0.y - __high2float(h20));
                uint32_t l1 = packh(v1.x - __low2float(h21), v1.y - __high2float(h21));
                __half* row0 = o2c + (size_t)r0 * (2 * N);
                __half* row1 = o2c + (size_t)(r0 + 8) * (2 * N);
                *(uint32_t*)(row0 + c0)     = h0;
                *(uint32_t*)(row0 + N + c0) = l0;
                *(uint32_t*)(row1 + c0)     = h1;
                *(uint32_t*)(row1 + N + c0) = l1;
            }
        }
    }
}

// ---------------------------------------------------------------------------
// Merged k+v kernel: [0,512) k, [512,1024) v. Kp = K2L (2-term), hi plane out.
// ---------------------------------------------------------------------------
__global__ void __launch_bounds__(128, 2) kv_kernel(
    const __half* __restrict__ klat2, const __half* __restrict__ vlat2,
    const __half* __restrict__ wk2,   const __half* __restrict__ wv2,
    __half* __restrict__ kh, __half* __restrict__ vh)
{
    extern __shared__ char dsm[];
    const uint32_t tbase = (smem_u32(dsm) + 1023u) & ~1023u;
    const int tid  = threadIdx.x;
    const int wid  = tid >> 5;
    const int lane = tid & 31;

    const __half *A, *B;
    __half* O;
    int t = blockIdx.x;
    if (t < 512) { A = klat2; B = wk2; O = kh; }
    else         { A = vlat2; B = wv2; O = vh; t -= 512; }
    const int bm = (t >> 4) * 128;
    const int bn = (t & 15) * 128;
    const int N = 2048;

    float acc[4][8][4];
    ACC_INIT(acc);
    gemm_core(A, B, K2L, bm, bn, tid, wid, lane, tbase, acc);

    const int wm = (wid & 1) * 64;
    const int wn = (wid >> 1) * 64;
    #pragma unroll
    for (int mt = 0; mt < 4; mt++) {
        const int r0 = bm + wm + mt * 16 + (lane >> 2);
        #pragma unroll
        for (int n8 = 0; n8 < 8; n8++) {
            const int c0 = bn + wn + n8 * 8 + (lane & 3) * 2;
            *(uint32_t*)(O + (size_t)r0 * N + c0)       = packh(acc[mt][n8][0], acc[mt][n8][1]);
            *(uint32_t*)(O + (size_t)(r0 + 8) * N + c0) = packh(acc[mt][n8][2], acc[mt][n8][3]);
        }
    }
}

// ---------------------------------------------------------------------------
// Output projection: out = oh @ woh^T + bo (fp32 out), Kp = HH (single term)
// ---------------------------------------------------------------------------
__global__ void __launch_bounds__(128, 2) wo_kernel(
    const __half* __restrict__ oh, const __half* __restrict__ woh,
    const float* __restrict__ bo, float* __restrict__ C)
{
    extern __shared__ char dsm[];
    const uint32_t tbase = (smem_u32(dsm) + 1023u) & ~1023u;
    const int tid  = threadIdx.x;
    const int wid  = tid >> 5;
    const int lane = tid & 31;
    const int bm = blockIdx.y * 128;
    const int bn = blockIdx.x * 128;
    const int N = 2048;

    float acc[4][8][4];
    ACC_INIT(acc);
    gemm_core(oh, woh, HH, bm, bn, tid, wid, lane, tbase, acc);

    const int wm = (wid & 1) * 64;
    const int wn = (wid >> 1) * 64;
    #pragma unroll
    for (int mt = 0; mt < 4; mt++) {
        const int r0 = bm + wm + mt * 16 + (lane >> 2);
        #pragma unroll
        for (int n8 = 0; n8 < 8; n8++) {
            const int c0 = bn + wn + n8 * 8 + (lane & 3) * 2;
            float b0 = bo[c0], b1 = bo[c0 + 1];
            float2 v0 = make_float2(acc[mt][n8][0] + b0, acc[mt][n8][1] + b1);
            float2 v1 = make_float2(acc[mt][n8][2] + b0, acc[mt][n8][3] + b1);
            *(float2*)(C + (size_t)r0 * N + c0)       = v0;
            *(float2*)(C + (size_t)(r0 + 8) * N + c0) = v1;
        }
    }
}

// ---------------------------------------------------------------------------
// Input conversions
// ---------------------------------------------------------------------------
__global__ void cast_rows_kernel(const float* __restrict__ in,
                                 __half* __restrict__ out, int total2)
{
    int i2 = blockIdx.x * blockDim.x + threadIdx.x;
    if (i2 >= total2) return;
    float2 v = ((const float2*)in)[i2];
    ((__half2*)out)[i2] = __floats2half2_rn(v.x, v.y);
}

// merged weight split. wq/wklat/wvlat/wo -> [N,K] single; wk/wv -> [N,2K] dup.
__global__ void splitw_kernel(
    const float* __restrict__ wq, const float* __restrict__ wklat,
    const float* __restrict__ wvlat, const float* __restrict__ wk,
    const float* __restrict__ wv, const float* __restrict__ wo,
    __half* __restrict__ wqh, __half* __restrict__ wklath,
    __half* __restrict__ wvlath, __half* __restrict__ wk2,
    __half* __restrict__ wv2, __half* __restrict__ woh)
{
    __shared__ float t[32][33];
    int l = blockIdx.x;
    const float* in; __half* out; int K, N, tt, dup = 0;
    if (l < 4096)      { in = wq;    out = wqh;    K = 2048; N = 2048; tt = l; }
    else if (l < 5120) { in = wklat; out = wklath; K = 2048; N = 512;  tt = l - 4096; }
    else if (l < 6144) { in = wvlat; out = wvlath; K = 2048; N = 512;  tt = l - 5120; }
    else if (l < 7168) { in = wk;    out = wk2;    K = 512;  N = 2048; tt = l - 6144; dup = 1; }
    else if (l < 8192) { in = wv;    out = wv2;    K = 512;  N = 2048; tt = l - 7168; dup = 1; }
    else               { in = wo;    out = woh;    K = 2048; N = 2048; tt = l - 8192; }
    int nnb = N >> 5;
    int k0 = (tt / nnb) * 32, n0 = (tt % nnb) * 32;
    int tx = threadIdx.x, ty = threadIdx.y;
    #pragma unroll
    for (int i = 0; i < 32; i += 8)
        t[ty + i][tx] = in[(size_t)(k0 + ty + i) * N + n0 + tx];
    __syncthreads();
    #pragma unroll
    for (int i = 0; i < 32; i += 8) {
        int n = ty + i;
        __half h = __float2half_rn(t[tx][n]);
        if (dup) {
            size_t base = (size_t)(n0 + n) * 2 * K;
            out[base + k0 + tx]     = h;
            out[base + K + k0 + tx] = h;
        } else {
            out[(size_t)(n0 + n) * K + k0 + tx] = h;
        }
    }
}

// ---------------------------------------------------------------------------
// Tensor-core flash attention (causal), fp16 single-term QK / PV,
// K/V double-buffered. smem: Qh + 2x(Kh,Vh) = 160KB. 256 thr = 8 warps.
// ---------------------------------------------------------------------------
#define SM_QH 0u
#define SM_KB(b) (32768u + (uint32_t)(b) * 65536u)
#define SM_VB(b) (65536u + (uint32_t)(b) * 65536u)

__global__ void __launch_bounds__(256) mla_attn_tc_kernel(
    const __half* __restrict__ Qh,
    const __half* __restrict__ Kh, const __half* __restrict__ Vh,
    __half* __restrict__ Oh)
{
    extern __shared__ char dsm[];
    const uint32_t sb = (smem_u32(dsm) + 1023u) & ~1023u;

    const int tid  = threadIdx.x;
    const int lane = tid & 31;
    const int w    = tid >> 5;
    const int bh   = blockIdx.y;
    const int b    = bh >> 4;
    const int h    = bh & 15;
    const int qt   = gridDim.x - 1 - blockIdx.x;   // heavy tiles first

    const size_t qrow0 = (size_t)b * SS + (size_t)qt * 128;
    const size_t hcol  = (size_t)h * HDD;

    // prologue: Q + KV tile 0 (buffer 0)
    #pragma unroll
    for (int i = 0; i < 8; i++) {
        int idx = tid + 256 * i;
        int r   = idx >> 4;
        int d   = (idx & 15) * 8;
        uint32_t off = (uint32_t)(d >> 6) * 16384u
                     + SWZ128((uint32_t)(r * 128 + (d & 63) * 2));
        cp_async16(sb + SM_QH + off, Qh + (qrow0 + r) * HH + hcol + d);
        const size_t ksrc = ((size_t)b * SS + r) * HH + hcol + d;
        cp_async16(sb + SM_KB(0) + off, Kh + ksrc);
        cp_async16(sb + SM_VB(0) + off, Vh + ksrc);
    }
    CP_COMMIT();

    float m2[2] = {-1e30f, -1e30f};
    float l2[2] = {0.f, 0.f};
    float ov[16][4];
    #pragma unroll
    for (int j = 0; j < 16; j++)
        ov[j][0] = ov[j][1] = ov[j][2] = ov[j][3] = 0.f;

    const int a_row  = 16 * w + (lane & 15);
    const int a_ch   = lane >> 4;
    const int b_rowb = ((lane >> 4) << 3) + (lane & 7);
    const int b_ch   = (lane >> 3) & 1;
    const int v_row  = (lane & 7) + ((lane >> 3) & 1) * 8;
    const int qlocA  = 16 * w + (lane >> 2);

    for (int kt = 0; kt <= qt; kt++) {
        CP_WAIT0();
        __syncthreads();

        if (kt < qt) {
            const size_t krow1 = (size_t)b * SS + (size_t)(kt + 1) * 128;
            const uint32_t kb1 = SM_KB((kt + 1) & 1);
            const uint32_t vb1 = SM_VB((kt + 1) & 1);
            #pragma unroll
            for (int i = 0; i < 8; i++) {
                int idx = tid + 256 * i;
                int r   = idx >> 4;
                int d   = (idx & 15) * 8;
                uint32_t off = (uint32_t)(d >> 6) * 16384u
                             + SWZ128((uint32_t)(r * 128 + (d & 63) * 2));
                const size_t src = (krow1 + r) * HH + hcol + d;
                cp_async16(sb + kb1 + off, Kh + src);
                cp_async16(sb + vb1 + off, Vh + src);
            }
            CP_COMMIT();
        }

        const uint32_t kbs = sb + SM_KB(kt & 1);
        const uint32_t vbs = sb + SM_VB(kt & 1);

        // ---- scores: S = Qh·Kh^T ----
        float sc[16][4];
        #pragma unroll
        for (int j = 0; j < 16; j++)
            sc[j][0] = sc[j][1] = sc[j][2] = sc[j][3] = 0.f;

        #pragma unroll
        for (int kc = 0; kc < 8; kc++) {
            uint32_t ah[4];
            {
                int ch = (2 * (kc & 3) + a_ch) ^ (a_row & 7);
                uint32_t off = (uint32_t)(kc >> 2) * 16384u
                             + (uint32_t)(a_row * 128 + ch * 16);
                ldsm_x4(ah, sb + SM_QH + off);
            }
            #pragma unroll
            for (int half = 0; half < 2; half++) {
                uint32_t bh4[4][4];
                #pragma unroll
                for (int nt4 = 0; nt4 < 4; nt4++) {
                    int row = (half * 4 + nt4) * 16 + b_rowb;
                    int ch = (2 * (kc & 3) + b_ch) ^ (row & 7);
                    uint32_t off = (uint32_t)(kc >> 2) * 16384u
                                 + (uint32_t)(row * 128 + ch * 16);
                    ldsm_x4(bh4[nt4], kbs + off);
                }
                #pragma unroll
                for (int nt4 = 0; nt4 < 4; nt4++) {
                    int j0 = (half * 4 + nt4) * 2;
                    mma_f16(sc[j0],     ah, &bh4[nt4][0]);
                    mma_f16(sc[j0 + 1], ah, &bh4[nt4][2]);
                }
            }
        }

        // ---- causal mask (diagonal tile only) ----
        if (kt == qt) {
            #pragma unroll
            for (int j = 0; j < 16; j++) {
                int kkb = 8 * j + 2 * (lane & 3);
                #pragma unroll
                for (int c = 0; c < 2; c++) {
                    if (kkb + c > qlocA)     sc[j][c]     = -1e30f;
                    if (kkb + c > qlocA + 8) sc[j][2 + c] = -1e30f;
                }
            }
        }

        // ---- online softmax (base-2 domain) ----
        {
            float mA = -1e30f, mB = -1e30f;
            #pragma unroll
            for (int j = 0; j < 16; j++) {
                mA = fmaxf(mA, fmaxf(sc[j][0], sc[j][1]));
                mB = fmaxf(mB, fmaxf(sc[j][2], sc[j][3]));
            }
            mA = fmaxf(mA, __shfl_xor_sync(0xffffffffu, mA, 1));
            mA = fmaxf(mA, __shfl_xor_sync(0xffffffffu, mA, 2));
            mB = fmaxf(mB, __shfl_xor_sync(0xffffffffu, mB, 1));
            mB = fmaxf(mB, __shfl_xor_sync(0xffffffffu, mB, 2));
            float nmA = fmaxf(m2[0], mA), nmB = fmaxf(m2[1], mB);
            float aA = exp2p(m2[0] - nmA), aB = exp2p(m2[1] - nmB);
            float sA = 0.f, sB = 0.f;
            #pragma unroll
            for (int j = 0; j < 16; j++) {
                sc[j][0] = exp2p(sc[j][0] - nmA);
                sc[j][1] = exp2p(sc[j][1] - nmA);
                sc[j][2] = exp2p(sc[j][2] - nmB);
                sc[j][3] = exp2p(sc[j][3] - nmB);
                sA += sc[j][0] + sc[j][1];
                sB += sc[j][2] + sc[j][3];
            }
            sA += __shfl_xor_sync(0xffffffffu, sA, 1);
            sA += __shfl_xor_sync(0xffffffffu, sA, 2);
            sB += __shfl_xor_sync(0xffffffffu, sB, 1);
            sB += __shfl_xor_sync(0xffffffffu, sB, 2);
            l2[0] = l2[0] * aA + sA;
            l2[1] = l2[1] * aB + sB;
            m2[0] = nmA; m2[1] = nmB;
            #pragma unroll
            for (int j = 0; j < 16; j++) {
                ov[j][0] *= aA; ov[j][1] *= aA;
                ov[j][2] *= aB; ov[j][3] *= aB;
            }
        }

        // ---- O += Ph·Vh ----
        #pragma unroll
        for (int kc = 0; kc < 8; kc++) {
            int j0 = 2 * kc;
            uint32_t ph[4];
            #pragma unroll
            for (int u = 0; u < 2; u++)
                #pragma unroll
                for (int t = 0; t < 2; t++)
                    ph[2 * u + t] = packh(sc[j0 + u][2 * t], sc[j0 + u][2 * t + 1]);
            #pragma unroll
            for (int dt = 0; dt < 8; dt++) {
                uint32_t vh4[4];
                int row = kc * 16 + v_row;
                int dloc = (dt * 16) & 63;
                int ch = ((dloc >> 3) + (lane >> 4)) ^ (row & 7);
                uint32_t off = (uint32_t)(dt >> 2) * 16384u
                             + (uint32_t)(row * 128 + ch * 16);
                ldsm_x4_trans(vh4, vbs + off);
                int oj = 2 * dt;
                mma_f16(ov[oj],     ph, &vh4[0]);
                mma_f16(ov[oj + 1], ph, &vh4[2]);
            }
        }
    }

    // ---- epilogue: normalize and write oh (hi only) ----
    {
        float i0 = 1.f / l2[0], i1 = 1.f / l2[1];
        size_t rA = qrow0 + qlocA;
        __half* row0 = Oh + rA * (size_t)HH + hcol;
        __half* row1 = Oh + (rA + 8) * (size_t)HH + hcol;
        #pragma unroll
        for (int j = 0; j < 16; j++) {
            int c = 8 * j + 2 * (lane & 3);
            *(uint32_t*)(row0 + c) = packh(ov[j][0] * i0, ov[j][1] * i0);
            *(uint32_t*)(row1 + c) = packh(ov[j][2] * i1, ov[j][3] * i1);
        }
    }
}

// ---------------------------------------------------------------------------
// launch
// ---------------------------------------------------------------------------
extern "C" void kernel_launch(void* const* d_in, const int* in_sizes, int n_in,
                              void* d_out, int out_size)
{
    (void)in_sizes; (void)n_in; (void)out_size;
    const float* x      = (const float*)d_in[0];
    const float* wq     = (const float*)d_in[1];
    const float* bq     = (const float*)d_in[2];
    const float* wk_lat = (const float*)d_in[3];
    const float* wv_lat = (const float*)d_in[4];
    const float* wk     = (const float*)d_in[5];
    const float* wv     = (const float*)d_in[6];
    const float* wo     = (const float*)d_in[7];
    const float* bo     = (const float*)d_in[8];
    float* out = (float*)d_out;

    __half *qh, *kh, *vh, *oh, *xh;
    cudaGetSymbolAddress((void**)&qh, g_qh);
    cudaGetSymbolAddress((void**)&kh, g_kh);
    cudaGetSymbolAddress((void**)&vh, g_vh);
    cudaGetSymbolAddress((void**)&oh, g_oh);
    cudaGetSymbolAddress((void**)&xh, g_xh);

    __half *klat2, *vlat2, *wqh, *woh, *wklath, *wvlath, *wk2, *wv2;
    cudaGetSymbolAddress((void**)&klat2,  g_klat2);
    cudaGetSymbolAddress((void**)&vlat2,  g_vlat2);
    cudaGetSymbolAddress((void**)&wqh,    g_wqh);
    cudaGetSymbolAddress((void**)&woh,    g_woh);
    cudaGetSymbolAddress((void**)&wklath, g_wklath);
    cudaGetSymbolAddress((void**)&wvlath, g_wvlath);
    cudaGetSymbolAddress((void**)&wk2,    g_wk2);
    cudaGetSymbolAddress((void**)&wv2,    g_wv2);

    const int smem_gemm = 3 * 32768 + 1024;
    cudaFuncSetAttribute(proj_kernel,
                         cudaFuncAttributeMaxDynamicSharedMemorySize, smem_gemm);
    cudaFuncSetAttribute(kv_kernel,
                         cudaFuncAttributeMaxDynamicSharedMemorySize, smem_gemm);
    cudaFuncSetAttribute(wo_kernel,
                         cudaFuncAttributeMaxDynamicSharedMemorySize, smem_gemm);
    const int smem_attn = 5 * 32768 + 1024;   // Qh + 2x(K,V)
    cudaFuncSetAttribute(mla_attn_tc_kernel,
                         cudaFuncAttributeMaxDynamicSharedMemorySize, smem_attn);

    // ---- input conversions ----
    {
        int tot = MM * HH / 2;
        cast_rows_kernel<<<(tot + 255) / 256, 256>>>(x, xh, tot);
    }
    splitw_kernel<<<12288, dim3(32, 8)>>>(
        wq, wk_lat, wv_lat, wk, wv, wo,
        wqh, wklath, wvlath, wk2, wv2, woh);

    // ---- merged projections: q + klat + vlat (K = 2048, single term) ----
    proj_kernel<<<768, 128, smem_gemm>>>(
        xh, wqh, wklath, wvlath, bq, qh, klat2, vlat2);

    // ---- merged k + v (K = 1024, 2-term hedge) ----
    kv_kernel<<<1024, 128, smem_gemm>>>(klat2, vlat2, wk2, wv2, kh, vh);

    // ---- attention ----
    mla_attn_tc_kernel<<<dim3(SS / 128, BB * NHH), 256, smem_attn>>>(
        qh, kh, vh, oh);

    // ---- output projection (K = 2048, single term) ----
    wo_kernel<<<dim3(HH / 128, MM / 128), 128, smem_gemm>>>(oh, woh, bo, out);
}